// round 10
// baseline (speedup 1.0000x reference)
#include <cuda_runtime.h>
#include <cuda_bf16.h>
#include <cuda_fp16.h>
#include <math.h>
#include <stdint.h>

// Problem constants
#define Bk   4
#define Lk   2048
#define Dk   256
#define Hk   4
#define NLk  4
#define Vk   32000
#define DHk  64
#define MR   (Bk*Lk)      // 8192 rows
#define FFD  (4*Dk)       // 1024

// weight-split offsets (elements)
#define OFF_WQ  0
#define OFF_WK  (NLk*Dk*Dk)
#define OFF_WV  (2*NLk*Dk*Dk)
#define OFF_WO  (3*NLk*Dk*Dk)
#define OFF_F1  (4*NLk*Dk*Dk)
#define OFF_F2  (4*NLk*Dk*Dk + NLk*FFD*Dk)
#define WTOT    (4*NLk*Dk*Dk + 2*NLk*FFD*Dk)

// ---------------- scratch ----------------
__device__ float g_X   [MR*Dk];
__device__ float g_Q   [MR*Dk];
__device__ float g_K   [MR*Dk];
__device__ float g_V   [MR*Dk];
__device__ __nv_bfloat16 g_XNh[MR*Dk];
__device__ __nv_bfloat16 g_XNl[MR*Dk];
__device__ __nv_bfloat16 g_AOh[MR*Dk];
__device__ __nv_bfloat16 g_AOl[MR*Dk];
__device__ __nv_bfloat16 g_F1h[MR*FFD];
__device__ __nv_bfloat16 g_F1l[MR*FFD];
__device__ __nv_bfloat16 g_Wh [WTOT];
__device__ __nv_bfloat16 g_Wl [WTOT];
__device__ __half g_XNH16[MR*Dk];
__device__ __half g_LWH  [Vk*Dk];

// ---------------- helpers ----------------
__device__ __forceinline__ void mma_bf16(float& c0, float& c1, float& c2, float& c3,
                                         uint32_t a0, uint32_t a1, uint32_t a2, uint32_t a3,
                                         uint32_t b0, uint32_t b1)
{
    asm volatile("mma.sync.aligned.m16n8k16.row.col.f32.bf16.bf16.f32 "
                 "{%0,%1,%2,%3},{%4,%5,%6,%7},{%8,%9},{%0,%1,%2,%3};"
                 : "+f"(c0), "+f"(c1), "+f"(c2), "+f"(c3)
                 : "r"(a0), "r"(a1), "r"(a2), "r"(a3), "r"(b0), "r"(b1));
}

__device__ __forceinline__ void mma_fp16(float& c0, float& c1, float& c2, float& c3,
                                         uint32_t a0, uint32_t a1, uint32_t a2, uint32_t a3,
                                         uint32_t b0, uint32_t b1)
{
    asm volatile("mma.sync.aligned.m16n8k16.row.col.f32.f16.f16.f32 "
                 "{%0,%1,%2,%3},{%4,%5,%6,%7},{%8,%9},{%0,%1,%2,%3};"
                 : "+f"(c0), "+f"(c1), "+f"(c2), "+f"(c3)
                 : "r"(a0), "r"(a1), "r"(a2), "r"(a3), "r"(b0), "r"(b1));
}

__device__ __forceinline__ void ldsm_x4(uint32_t& r0, uint32_t& r1, uint32_t& r2, uint32_t& r3,
                                        uint32_t addr)
{
    asm volatile("ldmatrix.sync.aligned.m8n8.x4.shared.b16 {%0,%1,%2,%3}, [%4];"
                 : "=r"(r0), "=r"(r1), "=r"(r2), "=r"(r3) : "r"(addr));
}

__device__ __forceinline__ void cp16(uint32_t smem, const void* gmem) {
    asm volatile("cp.async.ca.shared.global [%0], [%1], 16;\n" :: "r"(smem), "l"(gmem));
}
#define CP_COMMIT() asm volatile("cp.async.commit_group;\n" ::: "memory")
#define CP_WAIT1()  asm volatile("cp.async.wait_group 1;\n" ::: "memory")

__device__ __forceinline__ void bf16_split(float v, __nv_bfloat16& h, __nv_bfloat16& l) {
    h = __float2bfloat16_rn(v);
    l = __float2bfloat16_rn(v - __bfloat162float(h));
}

__device__ __forceinline__ uint32_t pack_h2(float a, float b) {
    __half2 h = __floats2half2_rn(a, b);
    return *reinterpret_cast<uint32_t*>(&h);
}

// ---------------- embedding ----------------
__global__ void embed_kernel(const int* __restrict__ ids, const int* __restrict__ tts,
                             const float* __restrict__ te, const float* __restrict__ ye,
                             float* __restrict__ X)
{
    int i = blockIdx.x * 256 + threadIdx.x;
    int row = i >> 8;
    int d   = i & 255;
    X[i] = te[(size_t)ids[row] * Dk + d] + ye[(size_t)tts[row] * Dk + d];
}

// ---------------- converts ----------------
__global__ void cvt_f16_kernel(const float* __restrict__ src, __half* __restrict__ dst, int n)
{
    int i = blockIdx.x * 256 + threadIdx.x;
    if (i < n) dst[i] = __float2half_rn(src[i]);
}

__global__ void split_bf16_kernel(const float* __restrict__ src,
                                  __nv_bfloat16* __restrict__ dh,
                                  __nv_bfloat16* __restrict__ dl, int n)
{
    int i = blockIdx.x * 256 + threadIdx.x;
    if (i < n) {
        __nv_bfloat16 h, l;
        bf16_split(src[i], h, l);
        dh[i] = h; dl[i] = l;
    }
}

// ---------------- RMSNorm -> bf16 hi/lo ----------------
__global__ __launch_bounds__(256) void rmsnorm_kernel(const float* __restrict__ X,
                                                      const float* __restrict__ w,
                                                      __nv_bfloat16* __restrict__ Yh,
                                                      __nv_bfloat16* __restrict__ Yl)
{
    int r = blockIdx.x;
    int t = threadIdx.x;
    float v = X[(size_t)r * Dk + t];
    float s = v * v;
    #pragma unroll
    for (int o = 16; o > 0; o >>= 1) s += __shfl_down_sync(0xffffffffu, s, o);
    __shared__ float ws[8];
    __shared__ float tot;
    int lane = t & 31, wi = t >> 5;
    if (lane == 0) ws[wi] = s;
    __syncthreads();
    if (t == 0) {
        float a = 0.f;
        #pragma unroll
        for (int i = 0; i < 8; i++) a += ws[i];
        tot = a;
    }
    __syncthreads();
    float rs = rsqrtf(tot * (1.0f / Dk) + 1.1920929e-07f);
    float y = v * rs * w[t];
    __nv_bfloat16 h, l;
    bf16_split(y, h, l);
    Yh[(size_t)r * Dk + t] = h;
    Yl[(size_t)r * Dk + t] = l;
}

// ---------------- final RMSNorm -> fp16 (LM head input) ----------------
__global__ __launch_bounds__(256) void rmsnorm_f16_kernel(const float* __restrict__ X,
                                                          const float* __restrict__ w,
                                                          __half* __restrict__ Y)
{
    int r = blockIdx.x;
    int t = threadIdx.x;
    float v = X[(size_t)r * Dk + t];
    float s = v * v;
    #pragma unroll
    for (int o = 16; o > 0; o >>= 1) s += __shfl_down_sync(0xffffffffu, s, o);
    __shared__ float ws[8];
    __shared__ float tot;
    int lane = t & 31, wi = t >> 5;
    if (lane == 0) ws[wi] = s;
    __syncthreads();
    if (t == 0) {
        float a = 0.f;
        #pragma unroll
        for (int i = 0; i < 8; i++) a += ws[i];
        tot = a;
    }
    __syncthreads();
    float rs = rsqrtf(tot * (1.0f / Dk) + 1.1920929e-07f);
    Y[(size_t)r * Dk + t] = __float2half_rn(v * rs * w[t]);
}

// ---------------- fp16 tensor-core flash attention (ldmatrix), bf16 hi/lo output -------
// 64 queries/block (4 warps x 16 rows), 64-key tiles, DH=64.
#define QPAD 36
__global__ __launch_bounds__(128) void attn_fa(const float* __restrict__ Q,
                                               const float* __restrict__ K,
                                               const float* __restrict__ V,
                                               const int*   __restrict__ mask,
                                               __nv_bfloat16* __restrict__ Oh,
                                               __nv_bfloat16* __restrict__ Ol)
{
    __shared__ uint32_t KP[64][QPAD];   // K tile (rows=key, words along d), then P (rows=q, words along key)
    __shared__ uint32_t Vs[64][QPAD];   // V^T: rows=d, words along key
    __shared__ float    mkf[64];

    int b  = blockIdx.z, h = blockIdx.y;
    int q0 = blockIdx.x * 64;
    int tid = threadIdx.x;
    int lane = tid & 31, wid = tid >> 5;
    int gr = lane >> 2, gc = lane & 3;
    int wr = wid * 16;
    int lm8 = lane & 7, ldq = (lane >> 3) & 1, ldh = lane >> 4;

    uint32_t kpbase = (uint32_t)__cvta_generic_to_shared(&KP[0][0]);
    uint32_t vsbase = (uint32_t)__cvta_generic_to_shared(&Vs[0][0]);
    // B-pattern (rows over first index, k words second): used for K rows and V rows
    uint32_t boffw = ((lm8 + 8*ldh) * QPAD + 4*ldq) * 4;
    // A-pattern for P rows (this warp's 16 rows)
    uint32_t paoff = ((wr + lm8 + 8*ldq) * QPAD + 4*ldh) * 4;

    const int* mrow = mask + (size_t)b * Lk;

    // stage Q (scaled) as fp16 pairs along d
    #pragma unroll
    for (int it = 0; it < 8; it++) {
        int pos = tid + it * 128;
        int row = pos >> 4, d4 = pos & 15;
        float4 qv = *(const float4*)(Q + ((size_t)(b*Lk + q0 + row))*Dk + h*DHk + d4*4);
        KP[row][d4*2    ] = pack_h2(qv.x*0.125f, qv.y*0.125f);
        KP[row][d4*2 + 1] = pack_h2(qv.z*0.125f, qv.w*0.125f);
    }
    __syncthreads();
    uint32_t qa[4][4];
    #pragma unroll
    for (int kw = 0; kw < 4; kw++) {
        qa[kw][0] = KP[wr+gr  ][kw*8+gc];
        qa[kw][1] = KP[wr+gr+8][kw*8+gc];
        qa[kw][2] = KP[wr+gr  ][kw*8+gc+4];
        qa[kw][3] = KP[wr+gr+8][kw*8+gc+4];
    }

    float o[8][4];
    #pragma unroll
    for (int nt = 0; nt < 8; nt++)
        #pragma unroll
        for (int j = 0; j < 4; j++) o[nt][j] = 0.f;
    float m0 = -1e30f, m1 = -1e30f, l0 = 0.f, l1 = 0.f;
    int r0 = q0 + wr + gr, r1 = r0 + 8;

    int ntile = blockIdx.x + 1;
    for (int kt = 0; kt < ntile; kt++) {
        int key0 = kt * 64;
        __syncthreads();
        #pragma unroll
        for (int it = 0; it < 8; it++) {
            int pos = tid + it * 128;
            int key = pos >> 4, d4 = pos & 15;
            size_t gbase = ((size_t)(b*Lk + key0 + key))*Dk + h*DHk + d4*4;
            float4 kv = *(const float4*)(K + gbase);
            KP[key][d4*2    ] = pack_h2(kv.x, kv.y);
            KP[key][d4*2 + 1] = pack_h2(kv.z, kv.w);
            float4 vv = *(const float4*)(V + gbase);
            __half* vh = (__half*)&Vs[0][0];
            vh[(d4*4+0)*(2*QPAD) + key] = __float2half_rn(vv.x);
            vh[(d4*4+1)*(2*QPAD) + key] = __float2half_rn(vv.y);
            vh[(d4*4+2)*(2*QPAD) + key] = __float2half_rn(vv.z);
            vh[(d4*4+3)*(2*QPAD) + key] = __float2half_rn(vv.w);
        }
        if (tid < 64) mkf[tid] = mrow[key0 + tid] ? 0.0f : -1e30f;
        __syncthreads();

        // S = Q K^T  (fp16, ldmatrix B-frags: 2 nt per ldsm_x4)
        float s[8][4];
        #pragma unroll
        for (int nt = 0; nt < 8; nt++)
            #pragma unroll
            for (int j = 0; j < 4; j++) s[nt][j] = 0.f;
        #pragma unroll
        for (int kw = 0; kw < 4; kw++) {
            #pragma unroll
            for (int p = 0; p < 4; p++) {
                uint32_t b00, b01, b10, b11;
                ldsm_x4(b00, b01, b10, b11, kpbase + boffw + (uint32_t)((p*16*QPAD + kw*8) * 4));
                mma_fp16(s[2*p  ][0], s[2*p  ][1], s[2*p  ][2], s[2*p  ][3],
                         qa[kw][0], qa[kw][1], qa[kw][2], qa[kw][3], b00, b01);
                mma_fp16(s[2*p+1][0], s[2*p+1][1], s[2*p+1][2], s[2*p+1][3],
                         qa[kw][0], qa[kw][1], qa[kw][2], qa[kw][3], b10, b11);
            }
        }

        bool last = (kt == ntile - 1);
        #pragma unroll
        for (int nt = 0; nt < 8; nt++) {
            float mk0 = mkf[nt*8+gc*2], mk1 = mkf[nt*8+gc*2+1];
            s[nt][0] += mk0; s[nt][1] += mk1;
            s[nt][2] += mk0; s[nt][3] += mk1;
            if (last) {
                int c = key0 + nt*8 + gc*2;
                if (c     > r0) s[nt][0] = -1e30f;
                if (c + 1 > r0) s[nt][1] = -1e30f;
                if (c     > r1) s[nt][2] = -1e30f;
                if (c + 1 > r1) s[nt][3] = -1e30f;
            }
        }

        float rm0 = -1e30f, rm1 = -1e30f;
        #pragma unroll
        for (int nt = 0; nt < 8; nt++) {
            rm0 = fmaxf(rm0, fmaxf(s[nt][0], s[nt][1]));
            rm1 = fmaxf(rm1, fmaxf(s[nt][2], s[nt][3]));
        }
        rm0 = fmaxf(rm0, __shfl_xor_sync(0xffffffffu, rm0, 1));
        rm0 = fmaxf(rm0, __shfl_xor_sync(0xffffffffu, rm0, 2));
        rm1 = fmaxf(rm1, __shfl_xor_sync(0xffffffffu, rm1, 1));
        rm1 = fmaxf(rm1, __shfl_xor_sync(0xffffffffu, rm1, 2));

        float mn0 = fmaxf(m0, rm0), mn1 = fmaxf(m1, rm1);
        float cor0 = __expf(m0 - mn0), cor1 = __expf(m1 - mn1);
        m0 = mn0; m1 = mn1;

        __syncthreads();   // everyone done reading K before P overwrites KP

        float ps0 = 0.f, ps1 = 0.f;
        #pragma unroll
        for (int nt = 0; nt < 8; nt++) {
            float p00 = __expf(s[nt][0] - mn0);
            float p01 = __expf(s[nt][1] - mn0);
            float p10 = __expf(s[nt][2] - mn1);
            float p11 = __expf(s[nt][3] - mn1);
            ps0 += p00 + p01;
            ps1 += p10 + p11;
            KP[wr+gr  ][nt*4+gc] = pack_h2(p00, p01);
            KP[wr+gr+8][nt*4+gc] = pack_h2(p10, p11);
        }
        ps0 += __shfl_xor_sync(0xffffffffu, ps0, 1);
        ps0 += __shfl_xor_sync(0xffffffffu, ps0, 2);
        ps1 += __shfl_xor_sync(0xffffffffu, ps1, 1);
        ps1 += __shfl_xor_sync(0xffffffffu, ps1, 2);
        l0 = l0 * cor0 + ps0;
        l1 = l1 * cor1 + ps1;
        #pragma unroll
        for (int nt = 0; nt < 8; nt++) {
            o[nt][0] *= cor0; o[nt][1] *= cor0;
            o[nt][2] *= cor1; o[nt][3] *= cor1;
        }
        __syncwarp();      // P rows read cross-lane within this warp only

        // O += P V  (fp16, ldmatrix A- and B-frags)
        #pragma unroll
        for (int kw = 0; kw < 4; kw++) {
            uint32_t pa0, pa1, pa2, pa3;
            ldsm_x4(pa0, pa1, pa2, pa3, kpbase + paoff + (uint32_t)(kw * 32));
            #pragma unroll
            for (int p = 0; p < 4; p++) {
                uint32_t v00, v01, v10, v11;
                ldsm_x4(v00, v01, v10, v11, vsbase + boffw + (uint32_t)((p*16*QPAD + kw*8) * 4));
                mma_fp16(o[2*p  ][0], o[2*p  ][1], o[2*p  ][2], o[2*p  ][3],
                         pa0, pa1, pa2, pa3, v00, v01);
                mma_fp16(o[2*p+1][0], o[2*p+1][1], o[2*p+1][2], o[2*p+1][3],
                         pa0, pa1, pa2, pa3, v10, v11);
            }
        }
    }

    float inv0 = 1.0f / l0, inv1 = 1.0f / l1;
    #pragma unroll
    for (int nt = 0; nt < 8; nt++) {
        int d = nt*8 + gc*2;
        size_t i0 = ((size_t)(b*Lk + r0))*Dk + h*DHk + d;
        size_t i1 = ((size_t)(b*Lk + r1))*Dk + h*DHk + d;
        float v00 = o[nt][0]*inv0, v01 = o[nt][1]*inv0;
        float v10 = o[nt][2]*inv1, v11 = o[nt][3]*inv1;
        __nv_bfloat16 h00, l00, h01, l01, h10, l10, h11, l11;
        bf16_split(v00, h00, l00); bf16_split(v01, h01, l01);
        bf16_split(v10, h10, l10); bf16_split(v11, h11, l11);
        __nv_bfloat162 ph0; ph0.x = h00; ph0.y = h01;
        __nv_bfloat162 ph1; ph1.x = h10; ph1.y = h11;
        __nv_bfloat162 pl0; pl0.x = l00; pl0.y = l01;
        __nv_bfloat162 pl1; pl1.x = l10; pl1.y = l11;
        *(__nv_bfloat162*)(Oh + i0) = ph0;
        *(__nv_bfloat162*)(Oh + i1) = ph1;
        *(__nv_bfloat162*)(Ol + i0) = pl0;
        *(__nv_bfloat162*)(Ol + i1) = pl1;
    }
}

// ================= bf16 3-pass split GEMM, ldmatrix frags, cp.async 2-stage =========
// EPI: 1 fp32 +R, 2 silu -> bf16 hi/lo, 3 store fp32 with RoPE on z<2 (QKV)
#define BUFW 2560
#define STGW 10240
template<int EPI>
__global__ __launch_bounds__(256, 2) void gemm_bfs(const __nv_bfloat16* __restrict__ Ah_,
                                                   const __nv_bfloat16* __restrict__ Al_,
                                                   const __nv_bfloat16* __restrict__ Bh0,
                                                   const __nv_bfloat16* __restrict__ Bl0,
                                                   const __nv_bfloat16* __restrict__ Bh1,
                                                   const __nv_bfloat16* __restrict__ Bl1,
                                                   const __nv_bfloat16* __restrict__ Bh2,
                                                   const __nv_bfloat16* __restrict__ Bl2,
                                                   const float* __restrict__ R,
                                                   float* __restrict__ C0,
                                                   float* __restrict__ C1,
                                                   float* __restrict__ C2,
                                                   __nv_bfloat16* __restrict__ Cbh,
                                                   __nv_bfloat16* __restrict__ Cbl,
                                                   int N, int K)
{
    const __nv_bfloat16* Bh = (blockIdx.z == 0) ? Bh0 : (blockIdx.z == 1 ? Bh1 : Bh2);
    const __nv_bfloat16* Bl = (blockIdx.z == 0) ? Bl0 : (blockIdx.z == 1 ? Bl1 : Bl2);
    float*               C  = (blockIdx.z == 0) ? C0  : (blockIdx.z == 1 ? C1  : C2);

    extern __shared__ uint32_t dsm[];

    int t    = threadIdx.x;
    int lane = t & 31;
    int wid  = t >> 5;
    int bm0  = blockIdx.y * 128;
    int bn0  = blockIdx.x * 128;
    int wm0  = (wid & 3) * 32;
    int wn0  = (wid >> 2) * 64;
    int gr   = lane >> 2;
    int gc   = lane & 3;
    int lm8  = lane & 7, ldq = (lane >> 3) & 1, ldh = lane >> 4;

    int lrow = t >> 1;
    int lkw  = (t & 1) * 8;

    const __nv_bfloat16* pAh = Ah_ + (size_t)(bm0 + lrow) * K + lkw * 2;
    const __nv_bfloat16* pAl = Al_ + (size_t)(bm0 + lrow) * K + lkw * 2;
    const __nv_bfloat16* pBh = Bh  + (size_t)(bn0 + lrow) * K + lkw * 2;
    const __nv_bfloat16* pBl = Bl  + (size_t)(bn0 + lrow) * K + lkw * 2;

    uint32_t sbase = (uint32_t)__cvta_generic_to_shared(dsm);
    uint32_t soff  = (lrow * 20 + lkw) * 4;
    uint32_t aoff  = ((wm0 + lm8 + 8*ldq) * 20 + 4*ldh) * 4;
    uint32_t boff  = ((wn0 + lm8 + 8*ldh) * 20 + 4*ldq) * 4;

    float c[2][8][4];
    #pragma unroll
    for (int i = 0; i < 2; i++)
        #pragma unroll
        for (int j = 0; j < 8; j++)
            #pragma unroll
            for (int q = 0; q < 4; q++) c[i][j][q] = 0.f;

    #pragma unroll
    for (int s = 0; s < 2; s++) {
        int ko = s * 32;
        uint32_t sb = sbase + s * STGW * 4 + soff;
        cp16(sb,            pAh + ko); cp16(sb + 16,            pAh + ko + 8);
        cp16(sb + BUFW*4,   pAl + ko); cp16(sb + BUFW*4 + 16,   pAl + ko + 8);
        cp16(sb + 2*BUFW*4, pBh + ko); cp16(sb + 2*BUFW*4 + 16, pBh + ko + 8);
        cp16(sb + 3*BUFW*4, pBl + ko); cp16(sb + 3*BUFW*4 + 16, pBl + ko + 8);
        CP_COMMIT();
    }

    const int niter = K / 32;
    for (int it = 0; it < niter; it++) {
        CP_WAIT1();
        __syncthreads();
        int cur = it & 1;
        uint32_t sb    = sbase + cur * (STGW * 4);
        uint32_t sAh_b = sb;
        uint32_t sAl_b = sb + BUFW * 4;
        uint32_t sBh_b = sb + 2 * BUFW * 4;
        uint32_t sBl_b = sb + 3 * BUFW * 4;

        #pragma unroll
        for (int kk = 0; kk < 16; kk += 8) {
            uint32_t afh[2][4], afl[2][4];
            #pragma unroll
            for (int mt = 0; mt < 2; mt++) {
                uint32_t ao = aoff + (uint32_t)((mt * 320 + kk) * 4);
                ldsm_x4(afh[mt][0], afh[mt][1], afh[mt][2], afh[mt][3], sAh_b + ao);
                ldsm_x4(afl[mt][0], afl[mt][1], afl[mt][2], afl[mt][3], sAl_b + ao);
            }
            #pragma unroll
            for (int p = 0; p < 4; p++) {
                uint32_t bo = boff + (uint32_t)((p * 320 + kk) * 4);
                uint32_t bh00, bh01, bh10, bh11;
                uint32_t bl00, bl01, bl10, bl11;
                ldsm_x4(bh00, bh01, bh10, bh11, sBh_b + bo);
                ldsm_x4(bl00, bl01, bl10, bl11, sBl_b + bo);
                int n0 = 2*p, n1 = 2*p + 1;
                #pragma unroll
                for (int mt = 0; mt < 2; mt++) {
                    mma_bf16(c[mt][n0][0], c[mt][n0][1], c[mt][n0][2], c[mt][n0][3],
                             afh[mt][0], afh[mt][1], afh[mt][2], afh[mt][3], bh00, bh01);
                    mma_bf16(c[mt][n0][0], c[mt][n0][1], c[mt][n0][2], c[mt][n0][3],
                             afh[mt][0], afh[mt][1], afh[mt][2], afh[mt][3], bl00, bl01);
                    mma_bf16(c[mt][n0][0], c[mt][n0][1], c[mt][n0][2], c[mt][n0][3],
                             afl[mt][0], afl[mt][1], afl[mt][2], afl[mt][3], bh00, bh01);
                    mma_bf16(c[mt][n1][0], c[mt][n1][1], c[mt][n1][2], c[mt][n1][3],
                             afh[mt][0], afh[mt][1], afh[mt][2], afh[mt][3], bh10, bh11);
                    mma_bf16(c[mt][n1][0], c[mt][n1][1], c[mt][n1][2], c[mt][n1][3],
                             afh[mt][0], afh[mt][1], afh[mt][2], afh[mt][3], bl10, bl11);
                    mma_bf16(c[mt][n1][0], c[mt][n1][1], c[mt][n1][2], c[mt][n1][3],
                             afl[mt][0], afl[mt][1], afl[mt][2], afl[mt][3], bh10, bh11);
                }
            }
        }

        __syncthreads();
        if (it + 2 < niter) {
            int ko = (it + 2) * 32;
            uint32_t sbw = sbase + cur * STGW * 4 + soff;
            cp16(sbw,            pAh + ko); cp16(sbw + 16,            pAh + ko + 8);
            cp16(sbw + BUFW*4,   pAl + ko); cp16(sbw + BUFW*4 + 16,   pAl + ko + 8);
            cp16(sbw + 2*BUFW*4, pBh + ko); cp16(sbw + 2*BUFW*4 + 16, pBh + ko + 8);
            cp16(sbw + 3*BUFW*4, pBl + ko); cp16(sbw + 3*BUFW*4 + 16, pBl + ko + 8);
        }
        CP_COMMIT();
    }

    if (EPI == 3) {
        // QKV epilogue: store fp32; apply RoPE for Q (z=0) and K (z=1).
        bool dorope = (blockIdx.z < 2);
        #pragma unroll
        for (int mt = 0; mt < 2; mt++) {
            #pragma unroll
            for (int half = 0; half < 2; half++) {
                int r = bm0 + wm0 + mt * 16 + gr + half * 8;
                int pos = r & (Lk - 1);
                #pragma unroll
                for (int nt = 0; nt < 4; nt++) {
                    int tc = nt * 8 + gc * 2;          // 0..31 within this warp's head window
                    float a0 = c[mt][nt  ][half*2+0], a1 = c[mt][nt  ][half*2+1];
                    float b0 = c[mt][nt+4][half*2+0], b1 = c[mt][nt+4][half*2+1];
                    size_t idx = (size_t)r * N + bn0 + wn0 + tc;
                    if (dorope) {
                        float inv0 = exp2f(-(float)tc       * (13.287712379549449f / 32.0f));
                        float inv1 = exp2f(-(float)(tc + 1) * (13.287712379549449f / 32.0f));
                        float sn0, cs0, sn1, cs1;
                        sincosf((float)pos * inv0, &sn0, &cs0);
                        sincosf((float)pos * inv1, &sn1, &cs1);
                        float2 lo; lo.x = a0 * cs0 - b0 * sn0; lo.y = a1 * cs1 - b1 * sn1;
                        float2 hi; hi.x = b0 * cs0 + a0 * sn0; hi.y = b1 * cs1 + a1 * sn1;
                        *(float2*)(C + idx)      = lo;
                        *(float2*)(C + idx + 32) = hi;
                    } else {
                        float2 v0; v0.x = a0; v0.y = a1;
                        float2 v1; v1.x = b0; v1.y = b1;
                        *(float2*)(C + idx)      = v0;
                        *(float2*)(C + idx + 32) = v1;
                    }
                }
            }
        }
        return;
    }

    #pragma unroll
    for (int mt = 0; mt < 2; mt++) {
        #pragma unroll
        for (int nt = 0; nt < 8; nt++) {
            int row = bm0 + wm0 + mt * 16 + gr;
            int col = bn0 + wn0 + nt * 8 + gc * 2;
            #pragma unroll
            for (int half = 0; half < 2; half++) {
                int r = row + half * 8;
                float vx = c[mt][nt][half * 2 + 0];
                float vy = c[mt][nt][half * 2 + 1];
                size_t idx = (size_t)r * N + col;
                if (EPI == 1) {
                    float2 rr = *(const float2*)(R + idx);
                    vx += rr.x; vy += rr.y;
                    float2 ov; ov.x = vx; ov.y = vy;
                    *(float2*)(C + idx) = ov;
                } else if (EPI == 2) {
                    vx = vx / (1.f + __expf(-vx));
                    vy = vy / (1.f + __expf(-vy));
                    __nv_bfloat16 hx, lx, hy, ly;
                    bf16_split(vx, hx, lx);
                    bf16_split(vy, hy, ly);
                    __nv_bfloat162 ph; ph.x = hx; ph.y = hy;
                    __nv_bfloat162 pl; pl.x = lx; pl.y = ly;
                    *(__nv_bfloat162*)(Cbh + idx) = ph;
                    *(__nv_bfloat162*)(Cbl + idx) = pl;
                }
            }
        }
    }
}

// ================= LM head GEMM: fp16 single-pass, ldmatrix frags, cp.async 2-stage ====
__global__ __launch_bounds__(256, 2) void gemm_lm_h(const __half* __restrict__ A,
                                                    const __half* __restrict__ B,
                                                    float* __restrict__ C,
                                                    int N, int K)
{
    __shared__ uint32_t sA[2][128][20];
    __shared__ uint32_t sB[2][128][20];

    int t    = threadIdx.x;
    int lane = t & 31;
    int wid  = t >> 5;
    int bm0  = blockIdx.y * 128;
    int bn0  = blockIdx.x * 128;
    int wm0  = (wid & 3) * 32;
    int wn0  = (wid >> 2) * 64;
    int gr   = lane >> 2;
    int gc   = lane & 3;
    int lm8  = lane & 7, ldq = (lane >> 3) & 1, ldh = lane >> 4;

    int lrow = t >> 1;
    int lkw  = (t & 1) * 8;

    const __half* Ap = A + (size_t)(bm0 + lrow) * K + lkw * 2;
    const __half* Bp = B + (size_t)(bn0 + lrow) * K + lkw * 2;

    float c[2][8][4];
    #pragma unroll
    for (int i = 0; i < 2; i++)
        #pragma unroll
        for (int j = 0; j < 8; j++)
            #pragma unroll
            for (int q = 0; q < 4; q++) c[i][j][q] = 0.f;

    uint32_t saA0 = (uint32_t)__cvta_generic_to_shared(&sA[0][lrow][lkw]);
    uint32_t saB0 = (uint32_t)__cvta_generic_to_shared(&sB[0][lrow][lkw]);
    uint32_t sAbase = (uint32_t)__cvta_generic_to_shared(&sA[0][0][0]);
    uint32_t sBbase = (uint32_t)__cvta_generic_to_shared(&sB[0][0][0]);
    uint32_t aoff = ((wm0 + lm8 + 8*ldq) * 20 + 4*ldh) * 4;
    uint32_t boff = ((wn0 + lm8 + 8*ldh) * 20 + 4*ldq) * 4;
    const uint32_t stageStride = 128 * 20 * 4;

    #pragma unroll
    for (int s = 0; s < 2; s++) {
        int ko = s * 32;
        cp16(saA0 + s * stageStride,      Ap + ko);
        cp16(saA0 + s * stageStride + 16, Ap + ko + 8);
        cp16(saB0 + s * stageStride,      Bp + ko);
        cp16(saB0 + s * stageStride + 16, Bp + ko + 8);
        CP_COMMIT();
    }

    const int niter = K / 32;    // 8
    for (int it = 0; it < niter; it++) {
        CP_WAIT1();
        __syncthreads();
        int cur = it & 1;
        uint32_t sAc = sAbase + cur * stageStride;
        uint32_t sBc = sBbase + cur * stageStride;

        #pragma unroll
        for (int kk = 0; kk < 16; kk += 8) {
            uint32_t af[2][4];
            #pragma unroll
            for (int mt = 0; mt < 2; mt++)
                ldsm_x4(af[mt][0], af[mt][1], af[mt][2], af[mt][3],
                        sAc + aoff + (uint32_t)((mt * 320 + kk) * 4));
            #pragma unroll
            for (int p = 0; p < 4; p++) {
                uint32_t b00, b01, b10, b11;
                ldsm_x4(b00, b01, b10, b11, sBc + boff + (uint32_t)((p * 320 + kk) * 4));
                int n0 = 2*p, n1 = 2*p + 1;
                #pragma unroll
                for (int mt = 0; mt < 2; mt++) {
                    mma_fp16(c[mt][n0][0], c[mt][n0][1], c[mt][n0][2], c[mt][n0][3],
                             af[mt][0], af[mt][1], af[mt][2], af[mt][3], b00, b01);
                    mma_fp16(c[mt][n1][0], c[mt][n1][1], c[mt][n1][2], c[mt][n1][3],
                             af[mt][0], af[mt][1], af[mt][2], af[mt][3], b10, b11);
                }
            }
        }

        __syncthreads();
        if (it + 2 < niter) {
            int ko = (it + 2) * 32;
            cp16(saA0 + cur * stageStride,      Ap + ko);
            cp16(saA0 + cur * stageStride + 16, Ap + ko + 8);
            cp16(saB0 + cur * stageStride,      Bp + ko);
            cp16(saB0 + cur * stageStride + 16, Bp + ko + 8);
        }
        CP_COMMIT();
    }

    #pragma unroll
    for (int mt = 0; mt < 2; mt++) {
        #pragma unroll
        for (int nt = 0; nt < 8; nt++) {
            int row = bm0 + wm0 + mt * 16 + gr;
            int col = bn0 + wn0 + nt * 8 + gc * 2;
            #pragma unroll
            for (int half = 0; half < 2; half++) {
                int r = row + half * 8;
                float2 ov;
                ov.x = c[mt][nt][half * 2 + 0];
                ov.y = c[mt][nt][half * 2 + 1];
                *(float2*)(C + (size_t)r * N + col) = ov;
            }
        }
    }
}

// ---------------- classifier heads ----------------
__global__ void heads_kernel(const float* __restrict__ X,
                             const float* __restrict__ fnw,
                             const float* __restrict__ rw, const float* __restrict__ rb,
                             const float* __restrict__ mw, const float* __restrict__ mb,
                             float* __restrict__ out)
{
    int w = threadIdx.x >> 5, lane = threadIdx.x & 31;
    if (w >= Bk) return;
    const float* x = X + (size_t)w * Lk * Dk;
    float ss = 0.f;
    for (int d = lane; d < Dk; d += 32) { float v = x[d]; ss += v * v; }
    #pragma unroll
    for (int o = 16; o > 0; o >>= 1) ss += __shfl_xor_sync(0xffffffffu, ss, o);
    float rs = rsqrtf(ss * (1.0f / Dk) + 1.1920929e-07f);
    float sr = 0.f, sm = 0.f;
    for (int d = lane; d < Dk; d += 32) {
        float xn = x[d] * rs * fnw[d];
        sr += xn * rw[d];
        sm += xn * mw[d];
    }
    #pragma unroll
    for (int o = 16; o > 0; o >>= 1) {
        sr += __shfl_down_sync(0xffffffffu, sr, o);
        sm += __shfl_down_sync(0xffffffffu, sm, o);
    }
    if (lane == 0) {
        out[w]      = sr + rb[0];
        out[Bk + w] = sm + mb[0];
    }
}

// ---------------- launch ----------------
extern "C" void kernel_launch(void* const* d_in, const int* in_sizes, int n_in,
                              void* d_out, int out_size)
{
    const int*   ids      = (const int*)d_in[0];
    const int*   tts      = (const int*)d_in[1];
    const int*   mask     = (const int*)d_in[2];
    const float* tok_emb  = (const float*)d_in[3];
    const float* type_emb = (const float*)d_in[4];
    const float* norm1    = (const float*)d_in[5];
    const float* wq       = (const float*)d_in[6];
    const float* wk       = (const float*)d_in[7];
    const float* wv       = (const float*)d_in[8];
    const float* wo       = (const float*)d_in[9];
    const float* norm2    = (const float*)d_in[10];
    const float* fw1      = (const float*)d_in[11];
    const float* fw2      = (const float*)d_in[12];
    const float* fnorm    = (const float*)d_in[13];
    const float* lmw      = (const float*)d_in[14];
    const float* rw       = (const float*)d_in[15];
    const float* rbias    = (const float*)d_in[16];
    const float* mw       = (const float*)d_in[17];
    const float* mbias    = (const float*)d_in[18];
    float* out = (float*)d_out;

    float *X, *Q, *K, *V;
    __nv_bfloat16 *XNh, *XNl, *AOh, *AOl, *F1h, *F1l, *Wh, *Wl;
    __half *XNH16, *LWH;
    cudaGetSymbolAddress((void**)&X,     g_X);
    cudaGetSymbolAddress((void**)&Q,     g_Q);
    cudaGetSymbolAddress((void**)&K,     g_K);
    cudaGetSymbolAddress((void**)&V,     g_V);
    cudaGetSymbolAddress((void**)&XNh,   g_XNh);
    cudaGetSymbolAddress((void**)&XNl,   g_XNl);
    cudaGetSymbolAddress((void**)&AOh,   g_AOh);
    cudaGetSymbolAddress((void**)&AOl,   g_AOl);
    cudaGetSymbolAddress((void**)&F1h,   g_F1h);
    cudaGetSymbolAddress((void**)&F1l,   g_F1l);
    cudaGetSymbolAddress((void**)&Wh,    g_Wh);
    cudaGetSymbolAddress((void**)&Wl,    g_Wl);
    cudaGetSymbolAddress((void**)&XNH16, g_XNH16);
    cudaGetSymbolAddress((void**)&LWH,   g_LWH);

    const int dynSmem = STGW * 2 * 4;   // 81920 bytes
    cudaFuncSetAttribute(gemm_bfs<1>, cudaFuncAttributeMaxDynamicSharedMemorySize, dynSmem);
    cudaFuncSetAttribute(gemm_bfs<2>, cudaFuncAttributeMaxDynamicSharedMemorySize, dynSmem);
    cudaFuncSetAttribute(gemm_bfs<3>, cudaFuncAttributeMaxDynamicSharedMemorySize, dynSmem);

    embed_kernel<<<(MR * Dk) / 256, 256>>>(ids, tts, tok_emb, type_emb, X);
    cvt_f16_kernel<<<(Vk * Dk) / 256, 256>>>(lmw, LWH, Vk * Dk);

    split_bf16_kernel<<<(NLk*Dk*Dk) / 256, 256>>>(wq,  Wh + OFF_WQ, Wl + OFF_WQ, NLk*Dk*Dk);
    split_bf16_kernel<<<(NLk*Dk*Dk) / 256, 256>>>(wk,  Wh + OFF_WK, Wl + OFF_WK, NLk*Dk*Dk);
    split_bf16_kernel<<<(NLk*Dk*Dk) / 256, 256>>>(wv,  Wh + OFF_WV, Wl + OFF_WV, NLk*Dk*Dk);
    split_bf16_kernel<<<(NLk*Dk*Dk) / 256, 256>>>(wo,  Wh + OFF_WO, Wl + OFF_WO, NLk*Dk*Dk);
    split_bf16_kernel<<<(NLk*FFD*Dk) / 256, 256>>>(fw1, Wh + OFF_F1, Wl + OFF_F1, NLk*FFD*Dk);
    split_bf16_kernel<<<(NLk*FFD*Dk) / 256, 256>>>(fw2, Wh + OFF_F2, Wl + OFF_F2, NLk*FFD*Dk);

    dim3 gqkv(Dk  / 128, MR / 128, 3);
    dim3 gs  (Dk  / 128, MR / 128, 1);
    dim3 gf1 (FFD / 128, MR / 128, 1);
    dim3 glm (Vk  / 128, MR / 128);
    dim3 ga  (Lk / 64, Hk, Bk);

    for (int i = 0; i < NLk; i++) {
        size_t od = (size_t)i * Dk * Dk;
        size_t of = (size_t)i * FFD * Dk;
        const __nv_bfloat16 *qh = Wh + OFF_WQ + od, *ql = Wl + OFF_WQ + od;
        const __nv_bfloat16 *kh = Wh + OFF_WK + od, *kl = Wl + OFF_WK + od;
        const __nv_bfloat16 *vh = Wh + OFF_WV + od, *vl = Wl + OFF_WV + od;
        const __nv_bfloat16 *oh = Wh + OFF_WO + od, *ol = Wl + OFF_WO + od;
        const __nv_bfloat16 *f1h = Wh + OFF_F1 + of, *f1l = Wl + OFF_F1 + of;
        const __nv_bfloat16 *f2h = Wh + OFF_F2 + of, *f2l = Wl + OFF_F2 + of;

        rmsnorm_kernel<<<MR, 256>>>(X, norm1 + (size_t)i * Dk, XNh, XNl);
        gemm_bfs<3><<<gqkv, 256, dynSmem>>>(XNh, XNl, qh, ql, kh, kl, vh, vl,
                                            nullptr, Q, K, V, nullptr, nullptr, Dk, Dk);
        attn_fa<<<ga, 128>>>(Q, K, V, mask, AOh, AOl);
        gemm_bfs<1><<<gs, 256, dynSmem>>>(AOh, AOl, oh, ol, oh, ol, oh, ol,
                                          X, X, X, X, nullptr, nullptr, Dk, Dk);
        rmsnorm_kernel<<<MR, 256>>>(X, norm2 + (size_t)i * Dk, XNh, XNl);
        gemm_bfs<2><<<gf1, 256, dynSmem>>>(XNh, XNl, f1h, f1l, f1h, f1l, f1h, f1l,
                                           nullptr, nullptr, nullptr, nullptr,
                                           F1h, F1l, FFD, Dk);
        gemm_bfs<1><<<gs, 256, dynSmem>>>(F1h, F1l, f2h, f2l, f2h, f2l, f2h, f2l,
                                          X, X, X, X, nullptr, nullptr, Dk, FFD);
    }

    rmsnorm_f16_kernel<<<MR, 256>>>(X, fnorm, XNH16);
    gemm_lm_h<<<glm, 256>>>(XNH16, LWH, out, Vk, Dk);
    heads_kernel<<<1, 128>>>(X, fnorm, rw, rbias, mw, mbias, out + (size_t)Bk * Lk * Vk);
}

// round 11
// speedup vs baseline: 1.3766x; 1.3766x over previous
#include <cuda_runtime.h>
#include <cuda_bf16.h>
#include <cuda_fp16.h>
#include <math.h>
#include <stdint.h>

// Problem constants
#define Bk   4
#define Lk   2048
#define Dk   256
#define Hk   4
#define NLk  4
#define Vk   32000
#define DHk  64
#define MR   (Bk*Lk)      // 8192 rows
#define FFD  (4*Dk)       // 1024

// weight-split offsets (elements)
#define WDSZ (NLk*Dk*Dk)          // 262144
#define WFSZ (NLk*FFD*Dk)         // 1048576
#define OFF_WQ  0
#define OFF_WK  (WDSZ)
#define OFF_WV  (2*WDSZ)
#define OFF_WO  (3*WDSZ)
#define OFF_F1  (4*WDSZ)
#define OFF_F2  (4*WDSZ + WFSZ)
#define WTOT    (4*WDSZ + 2*WFSZ)

// ---------------- scratch ----------------
__device__ float g_X   [MR*Dk];
__device__ float g_Q   [MR*Dk];
__device__ float g_K   [MR*Dk];
__device__ float g_V   [MR*Dk];
__device__ __nv_bfloat16 g_XNh[MR*Dk];
__device__ __nv_bfloat16 g_XNl[MR*Dk];
__device__ __nv_bfloat16 g_AOh[MR*Dk];
__device__ __nv_bfloat16 g_AOl[MR*Dk];
__device__ __nv_bfloat16 g_F1h[MR*FFD];
__device__ __nv_bfloat16 g_F1l[MR*FFD];
__device__ __nv_bfloat16 g_Wh [WTOT];
__device__ __nv_bfloat16 g_Wl [WTOT];
__device__ __half g_XNH16[MR*Dk];
__device__ __half g_LWH  [Vk*Dk];
__device__ float2 g_ROPE [Lk*32];

// ---------------- helpers ----------------
__device__ __forceinline__ void mma_bf16(float& c0, float& c1, float& c2, float& c3,
                                         uint32_t a0, uint32_t a1, uint32_t a2, uint32_t a3,
                                         uint32_t b0, uint32_t b1)
{
    asm volatile("mma.sync.aligned.m16n8k16.row.col.f32.bf16.bf16.f32 "
                 "{%0,%1,%2,%3},{%4,%5,%6,%7},{%8,%9},{%0,%1,%2,%3};"
                 : "+f"(c0), "+f"(c1), "+f"(c2), "+f"(c3)
                 : "r"(a0), "r"(a1), "r"(a2), "r"(a3), "r"(b0), "r"(b1));
}

__device__ __forceinline__ void mma_fp16(float& c0, float& c1, float& c2, float& c3,
                                         uint32_t a0, uint32_t a1, uint32_t a2, uint32_t a3,
                                         uint32_t b0, uint32_t b1)
{
    asm volatile("mma.sync.aligned.m16n8k16.row.col.f32.f16.f16.f32 "
                 "{%0,%1,%2,%3},{%4,%5,%6,%7},{%8,%9},{%0,%1,%2,%3};"
                 : "+f"(c0), "+f"(c1), "+f"(c2), "+f"(c3)
                 : "r"(a0), "r"(a1), "r"(a2), "r"(a3), "r"(b0), "r"(b1));
}

__device__ __forceinline__ void cp16(uint32_t smem, const void* gmem) {
    asm volatile("cp.async.ca.shared.global [%0], [%1], 16;\n" :: "r"(smem), "l"(gmem));
}
#define CP_COMMIT() asm volatile("cp.async.commit_group;\n" ::: "memory")
#define CP_WAIT1()  asm volatile("cp.async.wait_group 1;\n" ::: "memory")

__device__ __forceinline__ void bf16_split(float v, __nv_bfloat16& h, __nv_bfloat16& l) {
    h = __float2bfloat16_rn(v);
    l = __float2bfloat16_rn(v - __bfloat162float(h));
}

__device__ __forceinline__ uint32_t pack_h2(float a, float b) {
    __half2 h = __floats2half2_rn(a, b);
    return *reinterpret_cast<uint32_t*>(&h);
}

// ---------------- embedding ----------------
__global__ void embed_kernel(const int* __restrict__ ids, const int* __restrict__ tts,
                             const float* __restrict__ te, const float* __restrict__ ye,
                             float* __restrict__ X)
{
    int i = blockIdx.x * 256 + threadIdx.x;
    int row = i >> 8;
    int d   = i & 255;
    X[i] = te[(size_t)ids[row] * Dk + d] + ye[(size_t)tts[row] * Dk + d];
}

// ---------------- merged prep: weight splits + LM fp16 convert ----------------
__global__ void prep_kernel(const float* __restrict__ wq, const float* __restrict__ wk,
                            const float* __restrict__ wv, const float* __restrict__ wo,
                            const float* __restrict__ fw1, const float* __restrict__ fw2,
                            const float* __restrict__ lmw,
                            __nv_bfloat16* __restrict__ Wh,
                            __nv_bfloat16* __restrict__ Wl,
                            __half* __restrict__ LWH)
{
    int i = blockIdx.x * 256 + threadIdx.x;
    if (i < WTOT) {
        float x;
        if (i < 4*WDSZ) {
            int seg = i / WDSZ;
            int j = i - seg * WDSZ;
            const float* src = (seg == 0) ? wq : (seg == 1) ? wk : (seg == 2) ? wv : wo;
            x = src[j];
        } else if (i < 4*WDSZ + WFSZ) {
            x = fw1[i - 4*WDSZ];
        } else {
            x = fw2[i - 4*WDSZ - WFSZ];
        }
        __nv_bfloat16 h, l;
        bf16_split(x, h, l);
        Wh[i] = h; Wl[i] = l;
    } else {
        int j = i - WTOT;           // < Vk*Dk by grid sizing
        LWH[j] = __float2half_rn(lmw[j]);
    }
}

// ---------------- RoPE table ----------------
__global__ void rope_tab_kernel()
{
    int i = blockIdx.x * 256 + threadIdx.x;    // Lk*32
    int pos = i >> 5, t = i & 31;
    float inv = exp2f(-(float)t * (13.287712379549449f / 32.0f));
    float sn, cs;
    sincosf((float)pos * inv, &sn, &cs);
    float2 v; v.x = cs; v.y = sn;
    g_ROPE[i] = v;
}

// ---------------- RMSNorm: warp-per-row -> bf16 hi/lo ----------------
__global__ __launch_bounds__(256) void rmsnorm_kernel(const float* __restrict__ X,
                                                      const float* __restrict__ w,
                                                      __nv_bfloat16* __restrict__ Yh,
                                                      __nv_bfloat16* __restrict__ Yl)
{
    int warp = threadIdx.x >> 5, lane = threadIdx.x & 31;
    int r = blockIdx.x * 8 + warp;
    const float* xr = X + (size_t)r * Dk;
    float4 v0 = *(const float4*)(xr + lane * 4);
    float4 v1 = *(const float4*)(xr + 128 + lane * 4);
    float s = v0.x*v0.x + v0.y*v0.y + v0.z*v0.z + v0.w*v0.w
            + v1.x*v1.x + v1.y*v1.y + v1.z*v1.z + v1.w*v1.w;
    #pragma unroll
    for (int o = 16; o > 0; o >>= 1) s += __shfl_xor_sync(0xffffffffu, s, o);
    float rs = rsqrtf(s * (1.0f / Dk) + 1.1920929e-07f);
    float4 w0 = *(const float4*)(w + lane * 4);
    float4 w1 = *(const float4*)(w + 128 + lane * 4);
    float y[8] = { v0.x*rs*w0.x, v0.y*rs*w0.y, v0.z*rs*w0.z, v0.w*rs*w0.w,
                   v1.x*rs*w1.x, v1.y*rs*w1.y, v1.z*rs*w1.z, v1.w*rs*w1.w };
    #pragma unroll
    for (int seg = 0; seg < 2; seg++) {
        #pragma unroll
        for (int p = 0; p < 2; p++) {
            __nv_bfloat16 h0, l0, h1, l1;
            bf16_split(y[seg*4 + p*2    ], h0, l0);
            bf16_split(y[seg*4 + p*2 + 1], h1, l1);
            __nv_bfloat162 ph; ph.x = h0; ph.y = h1;
            __nv_bfloat162 pl; pl.x = l0; pl.y = l1;
            size_t idx = (size_t)r * Dk + seg * 128 + lane * 4 + p * 2;
            *(__nv_bfloat162*)(Yh + idx) = ph;
            *(__nv_bfloat162*)(Yl + idx) = pl;
        }
    }
}

// ---------------- final RMSNorm: warp-per-row -> fp16 ----------------
__global__ __launch_bounds__(256) void rmsnorm_f16_kernel(const float* __restrict__ X,
                                                          const float* __restrict__ w,
                                                          __half* __restrict__ Y)
{
    int warp = threadIdx.x >> 5, lane = threadIdx.x & 31;
    int r = blockIdx.x * 8 + warp;
    const float* xr = X + (size_t)r * Dk;
    float4 v0 = *(const float4*)(xr + lane * 4);
    float4 v1 = *(const float4*)(xr + 128 + lane * 4);
    float s = v0.x*v0.x + v0.y*v0.y + v0.z*v0.z + v0.w*v0.w
            + v1.x*v1.x + v1.y*v1.y + v1.z*v1.z + v1.w*v1.w;
    #pragma unroll
    for (int o = 16; o > 0; o >>= 1) s += __shfl_xor_sync(0xffffffffu, s, o);
    float rs = rsqrtf(s * (1.0f / Dk) + 1.1920929e-07f);
    float4 w0 = *(const float4*)(w + lane * 4);
    float4 w1 = *(const float4*)(w + 128 + lane * 4);
    size_t base = (size_t)r * Dk + lane * 4;
    __half2 a0 = __floats2half2_rn(v0.x*rs*w0.x, v0.y*rs*w0.y);
    __half2 a1 = __floats2half2_rn(v0.z*rs*w0.z, v0.w*rs*w0.w);
    __half2 b0 = __floats2half2_rn(v1.x*rs*w1.x, v1.y*rs*w1.y);
    __half2 b1 = __floats2half2_rn(v1.z*rs*w1.z, v1.w*rs*w1.w);
    *(__half2*)(Y + base)           = a0;
    *(__half2*)(Y + base + 2)       = a1;
    *(__half2*)(Y + base + 128)     = b0;
    *(__half2*)(Y + base + 128 + 2) = b1;
}

// ---------------- RoPE (table-driven; Q and K via blockIdx.y) ----------------
__global__ void rope2_kernel(float* __restrict__ Q, float* __restrict__ K)
{
    float* P = blockIdx.y ? K : Q;
    int i   = blockIdx.x * 256 + threadIdx.x;
    int t   = i & 31;
    int h   = (i >> 5) & 3;
    int row = i >> 7;
    int pos = row & (Lk - 1);
    float2 cs = g_ROPE[(pos << 5) | t];
    size_t base = (size_t)row * Dk + h * DHk;
    float a = P[base + t];
    float b = P[base + t + 32];
    P[base + t]      = a * cs.x - b * cs.y;
    P[base + t + 32] = b * cs.x + a * cs.y;
}

// ---------------- fp16 tensor-core flash attention, bf16 hi/lo output ----------------
// 64 queries/block (4 warps x 16 rows), 64-key tiles, DH=64.
#define QPAD 36
__global__ __launch_bounds__(128) void attn_fa(const float* __restrict__ Q,
                                               const float* __restrict__ K,
                                               const float* __restrict__ V,
                                               const int*   __restrict__ mask,
                                               __nv_bfloat16* __restrict__ Oh,
                                               __nv_bfloat16* __restrict__ Ol)
{
    __shared__ uint32_t KP[64][QPAD];   // K tile (rows=key, words along d), then P (rows=q, words along key)
    __shared__ uint32_t Vs[64][QPAD];   // V^T: rows=d, words along key
    __shared__ float    mkf[64];

    int b  = blockIdx.z, h = blockIdx.y;
    int q0 = blockIdx.x * 64;
    int tid = threadIdx.x;
    int lane = tid & 31, wid = tid >> 5;
    int gr = lane >> 2, gc = lane & 3;
    int wr = wid * 16;

    const int* mrow = mask + (size_t)b * Lk;

    // stage Q (scaled) as fp16 pairs along d
    #pragma unroll
    for (int it = 0; it < 8; it++) {
        int pos = tid + it * 128;
        int row = pos >> 4, d4 = pos & 15;
        float4 qv = *(const float4*)(Q + ((size_t)(b*Lk + q0 + row))*Dk + h*DHk + d4*4);
        KP[row][d4*2    ] = pack_h2(qv.x*0.125f, qv.y*0.125f);
        KP[row][d4*2 + 1] = pack_h2(qv.z*0.125f, qv.w*0.125f);
    }
    __syncthreads();
    uint32_t qa[4][4];
    #pragma unroll
    for (int kw = 0; kw < 4; kw++) {
        qa[kw][0] = KP[wr+gr  ][kw*8+gc];
        qa[kw][1] = KP[wr+gr+8][kw*8+gc];
        qa[kw][2] = KP[wr+gr  ][kw*8+gc+4];
        qa[kw][3] = KP[wr+gr+8][kw*8+gc+4];
    }

    float o[8][4];
    #pragma unroll
    for (int nt = 0; nt < 8; nt++)
        #pragma unroll
        for (int j = 0; j < 4; j++) o[nt][j] = 0.f;
    float m0 = -1e30f, m1 = -1e30f, l0 = 0.f, l1 = 0.f;
    int r0 = q0 + wr + gr, r1 = r0 + 8;

    int ntile = blockIdx.x + 1;
    for (int kt = 0; kt < ntile; kt++) {
        int key0 = kt * 64;
        __syncthreads();
        #pragma unroll
        for (int it = 0; it < 8; it++) {
            int pos = tid + it * 128;
            int key = pos >> 4, d4 = pos & 15;
            size_t gbase = ((size_t)(b*Lk + key0 + key))*Dk + h*DHk + d4*4;
            float4 kv = *(const float4*)(K + gbase);
            KP[key][d4*2    ] = pack_h2(kv.x, kv.y);
            KP[key][d4*2 + 1] = pack_h2(kv.z, kv.w);
            float4 vv = *(const float4*)(V + gbase);
            __half* vh = (__half*)&Vs[0][0];
            vh[(d4*4+0)*(2*QPAD) + key] = __float2half_rn(vv.x);
            vh[(d4*4+1)*(2*QPAD) + key] = __float2half_rn(vv.y);
            vh[(d4*4+2)*(2*QPAD) + key] = __float2half_rn(vv.z);
            vh[(d4*4+3)*(2*QPAD) + key] = __float2half_rn(vv.w);
        }
        if (tid < 64) mkf[tid] = mrow[key0 + tid] ? 0.0f : -1e30f;
        __syncthreads();

        // S = Q K^T  (fp16, k16 per mma)
        float s[8][4];
        #pragma unroll
        for (int nt = 0; nt < 8; nt++)
            #pragma unroll
            for (int j = 0; j < 4; j++) s[nt][j] = 0.f;
        #pragma unroll
        for (int kw = 0; kw < 4; kw++) {
            #pragma unroll
            for (int nt = 0; nt < 8; nt++) {
                uint32_t b0 = KP[nt*8+gr][kw*8+gc];
                uint32_t b1 = KP[nt*8+gr][kw*8+gc+4];
                mma_fp16(s[nt][0], s[nt][1], s[nt][2], s[nt][3],
                         qa[kw][0], qa[kw][1], qa[kw][2], qa[kw][3], b0, b1);
            }
        }

        bool last = (kt == ntile - 1);
        #pragma unroll
        for (int nt = 0; nt < 8; nt++) {
            float mk0 = mkf[nt*8+gc*2], mk1 = mkf[nt*8+gc*2+1];
            s[nt][0] += mk0; s[nt][1] += mk1;
            s[nt][2] += mk0; s[nt][3] += mk1;
            if (last) {
                int c = key0 + nt*8 + gc*2;
                if (c     > r0) s[nt][0] = -1e30f;
                if (c + 1 > r0) s[nt][1] = -1e30f;
                if (c     > r1) s[nt][2] = -1e30f;
                if (c + 1 > r1) s[nt][3] = -1e30f;
            }
        }

        float rm0 = -1e30f, rm1 = -1e30f;
        #pragma unroll
        for (int nt = 0; nt < 8; nt++) {
            rm0 = fmaxf(rm0, fmaxf(s[nt][0], s[nt][1]));
            rm1 = fmaxf(rm1, fmaxf(s[nt][2], s[nt][3]));
        }
        rm0 = fmaxf(rm0, __shfl_xor_sync(0xffffffffu, rm0, 1));
        rm0 = fmaxf(rm0, __shfl_xor_sync(0xffffffffu, rm0, 2));
        rm1 = fmaxf(rm1, __shfl_xor_sync(0xffffffffu, rm1, 1));
        rm1 = fmaxf(rm1, __shfl_xor_sync(0xffffffffu, rm1, 2));

        float mn0 = fmaxf(m0, rm0), mn1 = fmaxf(m1, rm1);
        float cor0 = __expf(m0 - mn0), cor1 = __expf(m1 - mn1);
        m0 = mn0; m1 = mn1;

        __syncthreads();   // everyone done reading K before P overwrites KP

        float ps0 = 0.f, ps1 = 0.f;
        #pragma unroll
        for (int nt = 0; nt < 8; nt++) {
            float p00 = __expf(s[nt][0] - mn0);
            float p01 = __expf(s[nt][1] - mn0);
            float p10 = __expf(s[nt][2] - mn1);
            float p11 = __expf(s[nt][3] - mn1);
            ps0 += p00 + p01;
            ps1 += p10 + p11;
            KP[wr+gr  ][nt*4+gc] = pack_h2(p00, p01);
            KP[wr+gr+8][nt*4+gc] = pack_h2(p10, p11);
        }
        ps0 += __shfl_xor_sync(0xffffffffu, ps0, 1);
        ps0 += __shfl_xor_sync(0xffffffffu, ps0, 2);
        ps1 += __shfl_xor_sync(0xffffffffu, ps1, 1);
        ps1 += __shfl_xor_sync(0xffffffffu, ps1, 2);
        l0 = l0 * cor0 + ps0;
        l1 = l1 * cor1 + ps1;
        #pragma unroll
        for (int nt = 0; nt < 8; nt++) {
            o[nt][0] *= cor0; o[nt][1] *= cor0;
            o[nt][2] *= cor1; o[nt][3] *= cor1;
        }
        __syncwarp();      // P rows read cross-lane within this warp only

        // O += P V  (fp16)
        #pragma unroll
        for (int kw = 0; kw < 4; kw++) {
            uint32_t pa0 = KP[wr+gr  ][kw*8+gc];
            uint32_t pa1 = KP[wr+gr+8][kw*8+gc];
            uint32_t pa2 = KP[wr+gr  ][kw*8+gc+4];
            uint32_t pa3 = KP[wr+gr+8][kw*8+gc+4];
            #pragma unroll
            for (int nt = 0; nt < 8; nt++) {
                uint32_t vb0 = Vs[nt*8+gr][kw*8+gc];
                uint32_t vb1 = Vs[nt*8+gr][kw*8+gc+4];
                mma_fp16(o[nt][0], o[nt][1], o[nt][2], o[nt][3],
                         pa0, pa1, pa2, pa3, vb0, vb1);
            }
        }
    }

    float inv0 = 1.0f / l0, inv1 = 1.0f / l1;
    #pragma unroll
    for (int nt = 0; nt < 8; nt++) {
        int d = nt*8 + gc*2;
        size_t i0 = ((size_t)(b*Lk + r0))*Dk + h*DHk + d;
        size_t i1 = ((size_t)(b*Lk + r1))*Dk + h*DHk + d;
        float v00 = o[nt][0]*inv0, v01 = o[nt][1]*inv0;
        float v10 = o[nt][2]*inv1, v11 = o[nt][3]*inv1;
        __nv_bfloat16 h00, l00, h01, l01, h10, l10, h11, l11;
        bf16_split(v00, h00, l00); bf16_split(v01, h01, l01);
        bf16_split(v10, h10, l10); bf16_split(v11, h11, l11);
        __nv_bfloat162 ph0; ph0.x = h00; ph0.y = h01;
        __nv_bfloat162 ph1; ph1.x = h10; ph1.y = h11;
        __nv_bfloat162 pl0; pl0.x = l00; pl0.y = l01;
        __nv_bfloat162 pl1; pl1.x = l10; pl1.y = l11;
        *(__nv_bfloat162*)(Oh + i0) = ph0;
        *(__nv_bfloat162*)(Oh + i1) = ph1;
        *(__nv_bfloat162*)(Ol + i0) = pl0;
        *(__nv_bfloat162*)(Ol + i1) = pl1;
    }
}

// ================= bf16 3-pass split GEMM, cp.async 2-stage, K=32 per stage =========
#define BUFW 2560
#define STGW 10240
template<int EPI>
__global__ __launch_bounds__(256, 2) void gemm_bfs(const __nv_bfloat16* __restrict__ Ah_,
                                                   const __nv_bfloat16* __restrict__ Al_,
                                                   const __nv_bfloat16* __restrict__ Bh0,
                                                   const __nv_bfloat16* __restrict__ Bl0,
                                                   const __nv_bfloat16* __restrict__ Bh1,
                                                   const __nv_bfloat16* __restrict__ Bl1,
                                                   const __nv_bfloat16* __restrict__ Bh2,
                                                   const __nv_bfloat16* __restrict__ Bl2,
                                                   const float* __restrict__ R,
                                                   float* __restrict__ C0,
                                                   float* __restrict__ C1,
                                                   float* __restrict__ C2,
                                                   __nv_bfloat16* __restrict__ Cbh,
                                                   __nv_bfloat16* __restrict__ Cbl,
                                                   int N, int K)
{
    const __nv_bfloat16* Bh = (blockIdx.z == 0) ? Bh0 : (blockIdx.z == 1 ? Bh1 : Bh2);
    const __nv_bfloat16* Bl = (blockIdx.z == 0) ? Bl0 : (blockIdx.z == 1 ? Bl1 : Bl2);
    float*               C  = (blockIdx.z == 0) ? C0  : (blockIdx.z == 1 ? C1  : C2);

    extern __shared__ uint32_t dsm[];

    int t    = threadIdx.x;
    int lane = t & 31;
    int wid  = t >> 5;
    int bm0  = blockIdx.y * 128;
    int bn0  = blockIdx.x * 128;
    int wm0  = (wid & 3) * 32;
    int wn0  = (wid >> 2) * 64;
    int gr   = lane >> 2;
    int gc   = lane & 3;

    int lrow = t >> 1;
    int lkw  = (t & 1) * 8;

    const __nv_bfloat16* pAh = Ah_ + (size_t)(bm0 + lrow) * K + lkw * 2;
    const __nv_bfloat16* pAl = Al_ + (size_t)(bm0 + lrow) * K + lkw * 2;
    const __nv_bfloat16* pBh = Bh  + (size_t)(bn0 + lrow) * K + lkw * 2;
    const __nv_bfloat16* pBl = Bl  + (size_t)(bn0 + lrow) * K + lkw * 2;

    uint32_t sbase = (uint32_t)__cvta_generic_to_shared(dsm);
    uint32_t soff  = (lrow * 20 + lkw) * 4;

    float c[2][8][4];
    #pragma unroll
    for (int i = 0; i < 2; i++)
        #pragma unroll
        for (int j = 0; j < 8; j++)
            #pragma unroll
            for (int q = 0; q < 4; q++) c[i][j][q] = 0.f;

    #pragma unroll
    for (int s = 0; s < 2; s++) {
        int ko = s * 32;
        uint32_t sb = sbase + s * STGW * 4 + soff;
        cp16(sb,            pAh + ko); cp16(sb + 16,            pAh + ko + 8);
        cp16(sb + BUFW*4,   pAl + ko); cp16(sb + BUFW*4 + 16,   pAl + ko + 8);
        cp16(sb + 2*BUFW*4, pBh + ko); cp16(sb + 2*BUFW*4 + 16, pBh + ko + 8);
        cp16(sb + 3*BUFW*4, pBl + ko); cp16(sb + 3*BUFW*4 + 16, pBl + ko + 8);
        CP_COMMIT();
    }

    const int niter = K / 32;
    for (int it = 0; it < niter; it++) {
        CP_WAIT1();
        __syncthreads();
        int cur = it & 1;
        const uint32_t* sAh = dsm + cur * STGW;
        const uint32_t* sAl = sAh + BUFW;
        const uint32_t* sBh = sAh + 2 * BUFW;
        const uint32_t* sBl = sAh + 3 * BUFW;

        #pragma unroll
        for (int kk = 0; kk < 16; kk += 8) {
            uint32_t afh[2][4], afl[2][4];
            #pragma unroll
            for (int mt = 0; mt < 2; mt++) {
                int rr = (wm0 + mt * 16 + gr) * 20 + kk + gc;
                afh[mt][0] = sAh[rr];
                afh[mt][1] = sAh[rr + 8 * 20];
                afh[mt][2] = sAh[rr + 4];
                afh[mt][3] = sAh[rr + 8 * 20 + 4];
                afl[mt][0] = sAl[rr];
                afl[mt][1] = sAl[rr + 8 * 20];
                afl[mt][2] = sAl[rr + 4];
                afl[mt][3] = sAl[rr + 8 * 20 + 4];
            }
            #pragma unroll
            for (int nt = 0; nt < 8; nt++) {
                int nn = (wn0 + nt * 8 + gr) * 20 + kk + gc;
                uint32_t bh0 = sBh[nn], bh1 = sBh[nn + 4];
                uint32_t bl0 = sBl[nn], bl1 = sBl[nn + 4];
                #pragma unroll
                for (int mt = 0; mt < 2; mt++) {
                    mma_bf16(c[mt][nt][0], c[mt][nt][1], c[mt][nt][2], c[mt][nt][3],
                             afh[mt][0], afh[mt][1], afh[mt][2], afh[mt][3], bh0, bh1);
                    mma_bf16(c[mt][nt][0], c[mt][nt][1], c[mt][nt][2], c[mt][nt][3],
                             afh[mt][0], afh[mt][1], afh[mt][2], afh[mt][3], bl0, bl1);
                    mma_bf16(c[mt][nt][0], c[mt][nt][1], c[mt][nt][2], c[mt][nt][3],
                             afl[mt][0], afl[mt][1], afl[mt][2], afl[mt][3], bh0, bh1);
                }
            }
        }

        __syncthreads();
        if (it + 2 < niter) {
            int ko = (it + 2) * 32;
            uint32_t sb = sbase + cur * STGW * 4 + soff;
            cp16(sb,            pAh + ko); cp16(sb + 16,            pAh + ko + 8);
            cp16(sb + BUFW*4,   pAl + ko); cp16(sb + BUFW*4 + 16,   pAl + ko + 8);
            cp16(sb + 2*BUFW*4, pBh + ko); cp16(sb + 2*BUFW*4 + 16, pBh + ko + 8);
            cp16(sb + 3*BUFW*4, pBl + ko); cp16(sb + 3*BUFW*4 + 16, pBl + ko + 8);
        }
        CP_COMMIT();
    }

    #pragma unroll
    for (int mt = 0; mt < 2; mt++) {
        #pragma unroll
        for (int nt = 0; nt < 8; nt++) {
            int row = bm0 + wm0 + mt * 16 + gr;
            int col = bn0 + wn0 + nt * 8 + gc * 2;
            #pragma unroll
            for (int half = 0; half < 2; half++) {
                int r = row + half * 8;
                float vx = c[mt][nt][half * 2 + 0];
                float vy = c[mt][nt][half * 2 + 1];
                size_t idx = (size_t)r * N + col;
                if (EPI == 1) {
                    float2 rr = *(const float2*)(R + idx);
                    vx += rr.x; vy += rr.y;
                    float2 ov; ov.x = vx; ov.y = vy;
                    *(float2*)(C + idx) = ov;
                } else if (EPI == 2) {
                    vx = vx / (1.f + __expf(-vx));
                    vy = vy / (1.f + __expf(-vy));
                    __nv_bfloat16 hx, lx, hy, ly;
                    bf16_split(vx, hx, lx);
                    bf16_split(vy, hy, ly);
                    __nv_bfloat162 ph; ph.x = hx; ph.y = hy;
                    __nv_bfloat162 pl; pl.x = lx; pl.y = ly;
                    *(__nv_bfloat162*)(Cbh + idx) = ph;
                    *(__nv_bfloat162*)(Cbl + idx) = pl;
                } else {
                    float2 ov; ov.x = vx; ov.y = vy;
                    *(float2*)(C + idx) = ov;
                }
            }
        }
    }
}

// ================= LM head GEMM: fp16 single-pass, cp.async 2-stage =================
__global__ __launch_bounds__(256, 2) void gemm_lm_h(const __half* __restrict__ A,
                                                    const __half* __restrict__ B,
                                                    float* __restrict__ C,
                                                    int N, int K)
{
    __shared__ uint32_t sA[2][128][20];
    __shared__ uint32_t sB[2][128][20];

    int t    = threadIdx.x;
    int lane = t & 31;
    int wid  = t >> 5;
    int bm0  = blockIdx.y * 128;
    int bn0  = blockIdx.x * 128;
    int wm0  = (wid & 3) * 32;
    int wn0  = (wid >> 2) * 64;
    int gr   = lane >> 2;
    int gc   = lane & 3;

    int lrow = t >> 1;
    int lkw  = (t & 1) * 8;

    const __half* Ap = A + (size_t)(bm0 + lrow) * K + lkw * 2;
    const __half* Bp = B + (size_t)(bn0 + lrow) * K + lkw * 2;

    float c[2][8][4];
    #pragma unroll
    for (int i = 0; i < 2; i++)
        #pragma unroll
        for (int j = 0; j < 8; j++)
            #pragma unroll
            for (int q = 0; q < 4; q++) c[i][j][q] = 0.f;

    uint32_t saA0 = (uint32_t)__cvta_generic_to_shared(&sA[0][lrow][lkw]);
    uint32_t saB0 = (uint32_t)__cvta_generic_to_shared(&sB[0][lrow][lkw]);
    const uint32_t stageStride = 128 * 20 * 4;

    #pragma unroll
    for (int s = 0; s < 2; s++) {
        int ko = s * 32;
        cp16(saA0 + s * stageStride,      Ap + ko);
        cp16(saA0 + s * stageStride + 16, Ap + ko + 8);
        cp16(saB0 + s * stageStride,      Bp + ko);
        cp16(saB0 + s * stageStride + 16, Bp + ko + 8);
        CP_COMMIT();
    }

    const int niter = K / 32;    // 8
    for (int it = 0; it < niter; it++) {
        CP_WAIT1();
        __syncthreads();
        int cur = it & 1;

        #pragma unroll
        for (int kk = 0; kk < 16; kk += 8) {
            uint32_t af[2][4], bf[8][2];
            #pragma unroll
            for (int mt = 0; mt < 2; mt++) {
                int rr = wm0 + mt * 16 + gr;
                af[mt][0] = sA[cur][rr][kk + gc];
                af[mt][1] = sA[cur][rr + 8][kk + gc];
                af[mt][2] = sA[cur][rr][kk + 4 + gc];
                af[mt][3] = sA[cur][rr + 8][kk + 4 + gc];
            }
            #pragma unroll
            for (int nt = 0; nt < 8; nt++) {
                int n0 = wn0 + nt * 8 + gr;
                bf[nt][0] = sB[cur][n0][kk + gc];
                bf[nt][1] = sB[cur][n0][kk + 4 + gc];
            }
            #pragma unroll
            for (int mt = 0; mt < 2; mt++)
                #pragma unroll
                for (int nt = 0; nt < 8; nt++)
                    mma_fp16(c[mt][nt][0], c[mt][nt][1], c[mt][nt][2], c[mt][nt][3],
                             af[mt][0], af[mt][1], af[mt][2], af[mt][3],
                             bf[nt][0], bf[nt][1]);
        }

        __syncthreads();
        if (it + 2 < niter) {
            int ko = (it + 2) * 32;
            cp16(saA0 + cur * stageStride,      Ap + ko);
            cp16(saA0 + cur * stageStride + 16, Ap + ko + 8);
            cp16(saB0 + cur * stageStride,      Bp + ko);
            cp16(saB0 + cur * stageStride + 16, Bp + ko + 8);
        }
        CP_COMMIT();
    }

    #pragma unroll
    for (int mt = 0; mt < 2; mt++) {
        #pragma unroll
        for (int nt = 0; nt < 8; nt++) {
            int row = bm0 + wm0 + mt * 16 + gr;
            int col = bn0 + wn0 + nt * 8 + gc * 2;
            #pragma unroll
            for (int half = 0; half < 2; half++) {
                int r = row + half * 8;
                float2 ov;
                ov.x = c[mt][nt][half * 2 + 0];
                ov.y = c[mt][nt][half * 2 + 1];
                *(float2*)(C + (size_t)r * N + col) = ov;
            }
        }
    }
}

// ---------------- classifier heads ----------------
__global__ void heads_kernel(const float* __restrict__ X,
                             const float* __restrict__ fnw,
                             const float* __restrict__ rw, const float* __restrict__ rb,
                             const float* __restrict__ mw, const float* __restrict__ mb,
                             float* __restrict__ out)
{
    int w = threadIdx.x >> 5, lane = threadIdx.x & 31;
    if (w >= Bk) return;
    const float* x = X + (size_t)w * Lk * Dk;
    float ss = 0.f;
    for (int d = lane; d < Dk; d += 32) { float v = x[d]; ss += v * v; }
    #pragma unroll
    for (int o = 16; o > 0; o >>= 1) ss += __shfl_xor_sync(0xffffffffu, ss, o);
    float rs = rsqrtf(ss * (1.0f / Dk) + 1.1920929e-07f);
    float sr = 0.f, sm = 0.f;
    for (int d = lane; d < Dk; d += 32) {
        float xn = x[d] * rs * fnw[d];
        sr += xn * rw[d];
        sm += xn * mw[d];
    }
    #pragma unroll
    for (int o = 16; o > 0; o >>= 1) {
        sr += __shfl_down_sync(0xffffffffu, sr, o);
        sm += __shfl_down_sync(0xffffffffu, sm, o);
    }
    if (lane == 0) {
        out[w]      = sr + rb[0];
        out[Bk + w] = sm + mb[0];
    }
}

// ---------------- launch ----------------
extern "C" void kernel_launch(void* const* d_in, const int* in_sizes, int n_in,
                              void* d_out, int out_size)
{
    const int*   ids      = (const int*)d_in[0];
    const int*   tts      = (const int*)d_in[1];
    const int*   mask     = (const int*)d_in[2];
    const float* tok_emb  = (const float*)d_in[3];
    const float* type_emb = (const float*)d_in[4];
    const float* norm1    = (const float*)d_in[5];
    const float* wq       = (const float*)d_in[6];
    const float* wk       = (const float*)d_in[7];
    const float* wv       = (const float*)d_in[8];
    const float* wo       = (const float*)d_in[9];
    const float* norm2    = (const float*)d_in[10];
    const float* fw1      = (const float*)d_in[11];
    const float* fw2      = (const float*)d_in[12];
    const float* fnorm    = (const float*)d_in[13];
    const float* lmw      = (const float*)d_in[14];
    const float* rw       = (const float*)d_in[15];
    const float* rbias    = (const float*)d_in[16];
    const float* mw       = (const float*)d_in[17];
    const float* mbias    = (const float*)d_in[18];
    float* out = (float*)d_out;

    float *X, *Q, *K, *V;
    __nv_bfloat16 *XNh, *XNl, *AOh, *AOl, *F1h, *F1l, *Wh, *Wl;
    __half *XNH16, *LWH;
    cudaGetSymbolAddress((void**)&X,     g_X);
    cudaGetSymbolAddress((void**)&Q,     g_Q);
    cudaGetSymbolAddress((void**)&K,     g_K);
    cudaGetSymbolAddress((void**)&V,     g_V);
    cudaGetSymbolAddress((void**)&XNh,   g_XNh);
    cudaGetSymbolAddress((void**)&XNl,   g_XNl);
    cudaGetSymbolAddress((void**)&AOh,   g_AOh);
    cudaGetSymbolAddress((void**)&AOl,   g_AOl);
    cudaGetSymbolAddress((void**)&F1h,   g_F1h);
    cudaGetSymbolAddress((void**)&F1l,   g_F1l);
    cudaGetSymbolAddress((void**)&Wh,    g_Wh);
    cudaGetSymbolAddress((void**)&Wl,    g_Wl);
    cudaGetSymbolAddress((void**)&XNH16, g_XNH16);
    cudaGetSymbolAddress((void**)&LWH,   g_LWH);

    const int dynSmem = STGW * 2 * 4;   // 81920 bytes
    cudaFuncSetAttribute(gemm_bfs<0>, cudaFuncAttributeMaxDynamicSharedMemorySize, dynSmem);
    cudaFuncSetAttribute(gemm_bfs<1>, cudaFuncAttributeMaxDynamicSharedMemorySize, dynSmem);
    cudaFuncSetAttribute(gemm_bfs<2>, cudaFuncAttributeMaxDynamicSharedMemorySize, dynSmem);

    embed_kernel<<<(MR * Dk) / 256, 256>>>(ids, tts, tok_emb, type_emb, X);
    prep_kernel<<<(WTOT + Vk * Dk) / 256, 256>>>(wq, wk, wv, wo, fw1, fw2, lmw, Wh, Wl, LWH);
    rope_tab_kernel<<<(Lk * 32) / 256, 256>>>();

    dim3 gqkv(Dk  / 128, MR / 128, 3);
    dim3 gs  (Dk  / 128, MR / 128, 1);
    dim3 gf1 (FFD / 128, MR / 128, 1);
    dim3 glm (Vk  / 128, MR / 128);
    dim3 ga  (Lk / 64, Hk, Bk);
    dim3 grp ((MR * Hk * 32) / 256, 2);

    for (int i = 0; i < NLk; i++) {
        size_t od = (size_t)i * Dk * Dk;
        size_t of = (size_t)i * FFD * Dk;
        const __nv_bfloat16 *qh = Wh + OFF_WQ + od, *ql = Wl + OFF_WQ + od;
        const __nv_bfloat16 *kh = Wh + OFF_WK + od, *kl = Wl + OFF_WK + od;
        const __nv_bfloat16 *vh = Wh + OFF_WV + od, *vl = Wl + OFF_WV + od;
        const __nv_bfloat16 *oh = Wh + OFF_WO + od, *ol = Wl + OFF_WO + od;
        const __nv_bfloat16 *f1h = Wh + OFF_F1 + of, *f1l = Wl + OFF_F1 + of;
        const __nv_bfloat16 *f2h = Wh + OFF_F2 + of, *f2l = Wl + OFF_F2 + of;

        rmsnorm_kernel<<<MR / 8, 256>>>(X, norm1 + (size_t)i * Dk, XNh, XNl);
        gemm_bfs<0><<<gqkv, 256, dynSmem>>>(XNh, XNl, qh, ql, kh, kl, vh, vl,
                                            nullptr, Q, K, V, nullptr, nullptr, Dk, Dk);
        rope2_kernel<<<grp, 256>>>(Q, K);
        attn_fa<<<ga, 128>>>(Q, K, V, mask, AOh, AOl);
        gemm_bfs<1><<<gs, 256, dynSmem>>>(AOh, AOl, oh, ol, oh, ol, oh, ol,
                                          X, X, X, X, nullptr, nullptr, Dk, Dk);
        rmsnorm_kernel<<<MR / 8, 256>>>(X, norm2 + (size_t)i * Dk, XNh, XNl);
        gemm_bfs<2><<<gf1, 256, dynSmem>>>(XNh, XNl, f1h, f1l, f1h, f1l, f1h, f1l,
                                           nullptr, nullptr, nullptr, nullptr,
                                           F1h, F1l, FFD, Dk);
        gemm_bfs<1><<<gs, 256, dynSmem>>>(F1h, F1l, f2h, f2l, f2h, f2l, f2h, f2l,
                                          X, X, X, X, nullptr, nullptr, Dk, FFD);
    }

    rmsnorm_f16_kernel<<<MR / 8, 256>>>(X, fnorm, XNH16);
    gemm_lm_h<<<glm, 256>>>(XNH16, LWH, out, Vk, Dk);
    heads_kernel<<<1, 128>>>(X, fnorm, rw, rbias, mw, mbias, out + (size_t)Bk * Lk * Vk);
}

// round 12
// speedup vs baseline: 1.4285x; 1.0377x over previous
#include <cuda_runtime.h>
#include <cuda_bf16.h>
#include <cuda_fp16.h>
#include <math.h>
#include <stdint.h>

// Problem constants
#define Bk   4
#define Lk   2048
#define Dk   256
#define Hk   4
#define NLk  4
#define Vk   32000
#define DHk  64
#define MR   (Bk*Lk)      // 8192 rows
#define FFD  (4*Dk)       // 1024

// weight-split offsets (elements)
#define WDSZ (NLk*Dk*Dk)          // 262144
#define WFSZ (NLk*FFD*Dk)         // 1048576
#define OFF_WQ  0
#define OFF_WK  (WDSZ)
#define OFF_WV  (2*WDSZ)
#define OFF_WO  (3*WDSZ)
#define OFF_F1  (4*WDSZ)
#define OFF_F2  (4*WDSZ + WFSZ)
#define WTOT    (4*WDSZ + 2*WFSZ)

// ---------------- scratch ----------------
__device__ float g_X   [MR*Dk];
__device__ float g_Q   [MR*Dk];
__device__ float g_K   [MR*Dk];
__device__ float g_V   [MR*Dk];
__device__ __nv_bfloat16 g_XNh[MR*Dk];
__device__ __nv_bfloat16 g_XNl[MR*Dk];
__device__ __nv_bfloat16 g_AOh[MR*Dk];
__device__ __nv_bfloat16 g_AOl[MR*Dk];
__device__ __nv_bfloat16 g_F1h[MR*FFD];
__device__ __nv_bfloat16 g_F1l[MR*FFD];
__device__ __nv_bfloat16 g_Wh [WTOT];
__device__ __nv_bfloat16 g_Wl [WTOT];
__device__ __half g_XNH16[MR*Dk];
__device__ __half g_LWH  [Vk*Dk];
__device__ float2 g_ROPE [Lk*32];

// ---------------- helpers ----------------
__device__ __forceinline__ void mma_bf16(float& c0, float& c1, float& c2, float& c3,
                                         uint32_t a0, uint32_t a1, uint32_t a2, uint32_t a3,
                                         uint32_t b0, uint32_t b1)
{
    asm volatile("mma.sync.aligned.m16n8k16.row.col.f32.bf16.bf16.f32 "
                 "{%0,%1,%2,%3},{%4,%5,%6,%7},{%8,%9},{%0,%1,%2,%3};"
                 : "+f"(c0), "+f"(c1), "+f"(c2), "+f"(c3)
                 : "r"(a0), "r"(a1), "r"(a2), "r"(a3), "r"(b0), "r"(b1));
}

__device__ __forceinline__ void mma_fp16(float& c0, float& c1, float& c2, float& c3,
                                         uint32_t a0, uint32_t a1, uint32_t a2, uint32_t a3,
                                         uint32_t b0, uint32_t b1)
{
    asm volatile("mma.sync.aligned.m16n8k16.row.col.f32.f16.f16.f32 "
                 "{%0,%1,%2,%3},{%4,%5,%6,%7},{%8,%9},{%0,%1,%2,%3};"
                 : "+f"(c0), "+f"(c1), "+f"(c2), "+f"(c3)
                 : "r"(a0), "r"(a1), "r"(a2), "r"(a3), "r"(b0), "r"(b1));
}

__device__ __forceinline__ void ldsm_x4(uint32_t& r0, uint32_t& r1, uint32_t& r2, uint32_t& r3,
                                        uint32_t addr)
{
    asm volatile("ldmatrix.sync.aligned.m8n8.x4.shared.b16 {%0,%1,%2,%3}, [%4];"
                 : "=r"(r0), "=r"(r1), "=r"(r2), "=r"(r3) : "r"(addr));
}

__device__ __forceinline__ void cp16(uint32_t smem, const void* gmem) {
    asm volatile("cp.async.ca.shared.global [%0], [%1], 16;\n" :: "r"(smem), "l"(gmem));
}
#define CP_COMMIT() asm volatile("cp.async.commit_group;\n" ::: "memory")
#define CP_WAIT1()  asm volatile("cp.async.wait_group 1;\n" ::: "memory")

__device__ __forceinline__ void bf16_split(float v, __nv_bfloat16& h, __nv_bfloat16& l) {
    h = __float2bfloat16_rn(v);
    l = __float2bfloat16_rn(v - __bfloat162float(h));
}

__device__ __forceinline__ uint32_t pack_h2(float a, float b) {
    __half2 h = __floats2half2_rn(a, b);
    return *reinterpret_cast<uint32_t*>(&h);
}

// ---------------- embedding ----------------
__global__ void embed_kernel(const int* __restrict__ ids, const int* __restrict__ tts,
                             const float* __restrict__ te, const float* __restrict__ ye,
                             float* __restrict__ X)
{
    int i = blockIdx.x * 256 + threadIdx.x;
    int row = i >> 8;
    int d   = i & 255;
    X[i] = te[(size_t)ids[row] * Dk + d] + ye[(size_t)tts[row] * Dk + d];
}

// ---------------- merged prep: weight splits + LM fp16 convert ----------------
__global__ void prep_kernel(const float* __restrict__ wq, const float* __restrict__ wk,
                            const float* __restrict__ wv, const float* __restrict__ wo,
                            const float* __restrict__ fw1, const float* __restrict__ fw2,
                            const float* __restrict__ lmw,
                            __nv_bfloat16* __restrict__ Wh,
                            __nv_bfloat16* __restrict__ Wl,
                            __half* __restrict__ LWH)
{
    int i = blockIdx.x * 256 + threadIdx.x;
    if (i < WTOT) {
        float x;
        if (i < 4*WDSZ) {
            int seg = i / WDSZ;
            int j = i - seg * WDSZ;
            const float* src = (seg == 0) ? wq : (seg == 1) ? wk : (seg == 2) ? wv : wo;
            x = src[j];
        } else if (i < 4*WDSZ + WFSZ) {
            x = fw1[i - 4*WDSZ];
        } else {
            x = fw2[i - 4*WDSZ - WFSZ];
        }
        __nv_bfloat16 h, l;
        bf16_split(x, h, l);
        Wh[i] = h; Wl[i] = l;
    } else {
        int j = i - WTOT;           // < Vk*Dk by grid sizing
        LWH[j] = __float2half_rn(lmw[j]);
    }
}

// ---------------- RoPE table ----------------
__global__ void rope_tab_kernel()
{
    int i = blockIdx.x * 256 + threadIdx.x;    // Lk*32
    int pos = i >> 5, t = i & 31;
    float inv = exp2f(-(float)t * (13.287712379549449f / 32.0f));
    float sn, cs;
    sincosf((float)pos * inv, &sn, &cs);
    float2 v; v.x = cs; v.y = sn;
    g_ROPE[i] = v;
}

// ---------------- RMSNorm: warp-per-row -> bf16 hi/lo ----------------
__global__ __launch_bounds__(256) void rmsnorm_kernel(const float* __restrict__ X,
                                                      const float* __restrict__ w,
                                                      __nv_bfloat16* __restrict__ Yh,
                                                      __nv_bfloat16* __restrict__ Yl)
{
    int warp = threadIdx.x >> 5, lane = threadIdx.x & 31;
    int r = blockIdx.x * 8 + warp;
    const float* xr = X + (size_t)r * Dk;
    float4 v0 = *(const float4*)(xr + lane * 4);
    float4 v1 = *(const float4*)(xr + 128 + lane * 4);
    float s = v0.x*v0.x + v0.y*v0.y + v0.z*v0.z + v0.w*v0.w
            + v1.x*v1.x + v1.y*v1.y + v1.z*v1.z + v1.w*v1.w;
    #pragma unroll
    for (int o = 16; o > 0; o >>= 1) s += __shfl_xor_sync(0xffffffffu, s, o);
    float rs = rsqrtf(s * (1.0f / Dk) + 1.1920929e-07f);
    float4 w0 = *(const float4*)(w + lane * 4);
    float4 w1 = *(const float4*)(w + 128 + lane * 4);
    float y[8] = { v0.x*rs*w0.x, v0.y*rs*w0.y, v0.z*rs*w0.z, v0.w*rs*w0.w,
                   v1.x*rs*w1.x, v1.y*rs*w1.y, v1.z*rs*w1.z, v1.w*rs*w1.w };
    #pragma unroll
    for (int seg = 0; seg < 2; seg++) {
        #pragma unroll
        for (int p = 0; p < 2; p++) {
            __nv_bfloat16 h0, l0, h1, l1;
            bf16_split(y[seg*4 + p*2    ], h0, l0);
            bf16_split(y[seg*4 + p*2 + 1], h1, l1);
            __nv_bfloat162 ph; ph.x = h0; ph.y = h1;
            __nv_bfloat162 pl; pl.x = l0; pl.y = l1;
            size_t idx = (size_t)r * Dk + seg * 128 + lane * 4 + p * 2;
            *(__nv_bfloat162*)(Yh + idx) = ph;
            *(__nv_bfloat162*)(Yl + idx) = pl;
        }
    }
}

// ---------------- final RMSNorm: warp-per-row -> fp16 ----------------
__global__ __launch_bounds__(256) void rmsnorm_f16_kernel(const float* __restrict__ X,
                                                          const float* __restrict__ w,
                                                          __half* __restrict__ Y)
{
    int warp = threadIdx.x >> 5, lane = threadIdx.x & 31;
    int r = blockIdx.x * 8 + warp;
    const float* xr = X + (size_t)r * Dk;
    float4 v0 = *(const float4*)(xr + lane * 4);
    float4 v1 = *(const float4*)(xr + 128 + lane * 4);
    float s = v0.x*v0.x + v0.y*v0.y + v0.z*v0.z + v0.w*v0.w
            + v1.x*v1.x + v1.y*v1.y + v1.z*v1.z + v1.w*v1.w;
    #pragma unroll
    for (int o = 16; o > 0; o >>= 1) s += __shfl_xor_sync(0xffffffffu, s, o);
    float rs = rsqrtf(s * (1.0f / Dk) + 1.1920929e-07f);
    float4 w0 = *(const float4*)(w + lane * 4);
    float4 w1 = *(const float4*)(w + 128 + lane * 4);
    size_t base = (size_t)r * Dk + lane * 4;
    __half2 a0 = __floats2half2_rn(v0.x*rs*w0.x, v0.y*rs*w0.y);
    __half2 a1 = __floats2half2_rn(v0.z*rs*w0.z, v0.w*rs*w0.w);
    __half2 b0 = __floats2half2_rn(v1.x*rs*w1.x, v1.y*rs*w1.y);
    __half2 b1 = __floats2half2_rn(v1.z*rs*w1.z, v1.w*rs*w1.w);
    *(__half2*)(Y + base)           = a0;
    *(__half2*)(Y + base + 2)       = a1;
    *(__half2*)(Y + base + 128)     = b0;
    *(__half2*)(Y + base + 128 + 2) = b1;
}

// ---------------- RoPE (table-driven; Q and K via blockIdx.y) ----------------
__global__ void rope2_kernel(float* __restrict__ Q, float* __restrict__ K)
{
    float* P = blockIdx.y ? K : Q;
    int i   = blockIdx.x * 256 + threadIdx.x;
    int t   = i & 31;
    int h   = (i >> 5) & 3;
    int row = i >> 7;
    int pos = row & (Lk - 1);
    float2 cs = g_ROPE[(pos << 5) | t];
    size_t base = (size_t)row * Dk + h * DHk;
    float a = P[base + t];
    float b = P[base + t + 32];
    P[base + t]      = a * cs.x - b * cs.y;
    P[base + t + 32] = b * cs.x + a * cs.y;
}

// ---------------- fp16 tensor-core flash attention, bf16 hi/lo output ----------------
// 64 queries/block (4 warps x 16 rows), 64-key tiles, DH=64.
#define QPAD 36
__global__ __launch_bounds__(128) void attn_fa(const float* __restrict__ Q,
                                               const float* __restrict__ K,
                                               const float* __restrict__ V,
                                               const int*   __restrict__ mask,
                                               __nv_bfloat16* __restrict__ Oh,
                                               __nv_bfloat16* __restrict__ Ol)
{
    __shared__ uint32_t KP[64][QPAD];   // K tile (rows=key, words along d), then P (rows=q, words along key)
    __shared__ uint32_t Vs[64][QPAD];   // V^T: rows=d, words along key
    __shared__ float    mkf[64];

    int b  = blockIdx.z, h = blockIdx.y;
    int q0 = blockIdx.x * 64;
    int tid = threadIdx.x;
    int lane = tid & 31, wid = tid >> 5;
    int gr = lane >> 2, gc = lane & 3;
    int wr = wid * 16;

    const int* mrow = mask + (size_t)b * Lk;

    // stage Q (scaled) as fp16 pairs along d
    #pragma unroll
    for (int it = 0; it < 8; it++) {
        int pos = tid + it * 128;
        int row = pos >> 4, d4 = pos & 15;
        float4 qv = *(const float4*)(Q + ((size_t)(b*Lk + q0 + row))*Dk + h*DHk + d4*4);
        KP[row][d4*2    ] = pack_h2(qv.x*0.125f, qv.y*0.125f);
        KP[row][d4*2 + 1] = pack_h2(qv.z*0.125f, qv.w*0.125f);
    }
    __syncthreads();
    uint32_t qa[4][4];
    #pragma unroll
    for (int kw = 0; kw < 4; kw++) {
        qa[kw][0] = KP[wr+gr  ][kw*8+gc];
        qa[kw][1] = KP[wr+gr+8][kw*8+gc];
        qa[kw][2] = KP[wr+gr  ][kw*8+gc+4];
        qa[kw][3] = KP[wr+gr+8][kw*8+gc+4];
    }

    float o[8][4];
    #pragma unroll
    for (int nt = 0; nt < 8; nt++)
        #pragma unroll
        for (int j = 0; j < 4; j++) o[nt][j] = 0.f;
    float m0 = -1e30f, m1 = -1e30f, l0 = 0.f, l1 = 0.f;
    int r0 = q0 + wr + gr, r1 = r0 + 8;

    int ntile = blockIdx.x + 1;
    for (int kt = 0; kt < ntile; kt++) {
        int key0 = kt * 64;
        __syncthreads();
        #pragma unroll
        for (int it = 0; it < 8; it++) {
            int pos = tid + it * 128;
            int key = pos >> 4, d4 = pos & 15;
            size_t gbase = ((size_t)(b*Lk + key0 + key))*Dk + h*DHk + d4*4;
            float4 kv = *(const float4*)(K + gbase);
            KP[key][d4*2    ] = pack_h2(kv.x, kv.y);
            KP[key][d4*2 + 1] = pack_h2(kv.z, kv.w);
            float4 vv = *(const float4*)(V + gbase);
            __half* vh = (__half*)&Vs[0][0];
            vh[(d4*4+0)*(2*QPAD) + key] = __float2half_rn(vv.x);
            vh[(d4*4+1)*(2*QPAD) + key] = __float2half_rn(vv.y);
            vh[(d4*4+2)*(2*QPAD) + key] = __float2half_rn(vv.z);
            vh[(d4*4+3)*(2*QPAD) + key] = __float2half_rn(vv.w);
        }
        if (tid < 64) mkf[tid] = mrow[key0 + tid] ? 0.0f : -1e30f;
        __syncthreads();

        // S = Q K^T  (fp16, k16 per mma)
        float s[8][4];
        #pragma unroll
        for (int nt = 0; nt < 8; nt++)
            #pragma unroll
            for (int j = 0; j < 4; j++) s[nt][j] = 0.f;
        #pragma unroll
        for (int kw = 0; kw < 4; kw++) {
            #pragma unroll
            for (int nt = 0; nt < 8; nt++) {
                uint32_t b0 = KP[nt*8+gr][kw*8+gc];
                uint32_t b1 = KP[nt*8+gr][kw*8+gc+4];
                mma_fp16(s[nt][0], s[nt][1], s[nt][2], s[nt][3],
                         qa[kw][0], qa[kw][1], qa[kw][2], qa[kw][3], b0, b1);
            }
        }

        bool last = (kt == ntile - 1);
        #pragma unroll
        for (int nt = 0; nt < 8; nt++) {
            float mk0 = mkf[nt*8+gc*2], mk1 = mkf[nt*8+gc*2+1];
            s[nt][0] += mk0; s[nt][1] += mk1;
            s[nt][2] += mk0; s[nt][3] += mk1;
            if (last) {
                int c = key0 + nt*8 + gc*2;
                if (c     > r0) s[nt][0] = -1e30f;
                if (c + 1 > r0) s[nt][1] = -1e30f;
                if (c     > r1) s[nt][2] = -1e30f;
                if (c + 1 > r1) s[nt][3] = -1e30f;
            }
        }

        float rm0 = -1e30f, rm1 = -1e30f;
        #pragma unroll
        for (int nt = 0; nt < 8; nt++) {
            rm0 = fmaxf(rm0, fmaxf(s[nt][0], s[nt][1]));
            rm1 = fmaxf(rm1, fmaxf(s[nt][2], s[nt][3]));
        }
        rm0 = fmaxf(rm0, __shfl_xor_sync(0xffffffffu, rm0, 1));
        rm0 = fmaxf(rm0, __shfl_xor_sync(0xffffffffu, rm0, 2));
        rm1 = fmaxf(rm1, __shfl_xor_sync(0xffffffffu, rm1, 1));
        rm1 = fmaxf(rm1, __shfl_xor_sync(0xffffffffu, rm1, 2));

        float mn0 = fmaxf(m0, rm0), mn1 = fmaxf(m1, rm1);
        float cor0 = __expf(m0 - mn0), cor1 = __expf(m1 - mn1);
        m0 = mn0; m1 = mn1;

        __syncthreads();   // everyone done reading K before P overwrites KP

        float ps0 = 0.f, ps1 = 0.f;
        #pragma unroll
        for (int nt = 0; nt < 8; nt++) {
            float p00 = __expf(s[nt][0] - mn0);
            float p01 = __expf(s[nt][1] - mn0);
            float p10 = __expf(s[nt][2] - mn1);
            float p11 = __expf(s[nt][3] - mn1);
            ps0 += p00 + p01;
            ps1 += p10 + p11;
            KP[wr+gr  ][nt*4+gc] = pack_h2(p00, p01);
            KP[wr+gr+8][nt*4+gc] = pack_h2(p10, p11);
        }
        ps0 += __shfl_xor_sync(0xffffffffu, ps0, 1);
        ps0 += __shfl_xor_sync(0xffffffffu, ps0, 2);
        ps1 += __shfl_xor_sync(0xffffffffu, ps1, 1);
        ps1 += __shfl_xor_sync(0xffffffffu, ps1, 2);
        l0 = l0 * cor0 + ps0;
        l1 = l1 * cor1 + ps1;
        #pragma unroll
        for (int nt = 0; nt < 8; nt++) {
            o[nt][0] *= cor0; o[nt][1] *= cor0;
            o[nt][2] *= cor1; o[nt][3] *= cor1;
        }
        __syncwarp();      // P rows read cross-lane within this warp only

        // O += P V  (fp16)
        #pragma unroll
        for (int kw = 0; kw < 4; kw++) {
            uint32_t pa0 = KP[wr+gr  ][kw*8+gc];
            uint32_t pa1 = KP[wr+gr+8][kw*8+gc];
            uint32_t pa2 = KP[wr+gr  ][kw*8+gc+4];
            uint32_t pa3 = KP[wr+gr+8][kw*8+gc+4];
            #pragma unroll
            for (int nt = 0; nt < 8; nt++) {
                uint32_t vb0 = Vs[nt*8+gr][kw*8+gc];
                uint32_t vb1 = Vs[nt*8+gr][kw*8+gc+4];
                mma_fp16(o[nt][0], o[nt][1], o[nt][2], o[nt][3],
                         pa0, pa1, pa2, pa3, vb0, vb1);
            }
        }
    }

    float inv0 = 1.0f / l0, inv1 = 1.0f / l1;
    #pragma unroll
    for (int nt = 0; nt < 8; nt++) {
        int d = nt*8 + gc*2;
        size_t i0 = ((size_t)(b*Lk + r0))*Dk + h*DHk + d;
        size_t i1 = ((size_t)(b*Lk + r1))*Dk + h*DHk + d;
        float v00 = o[nt][0]*inv0, v01 = o[nt][1]*inv0;
        float v10 = o[nt][2]*inv1, v11 = o[nt][3]*inv1;
        __nv_bfloat16 h00, l00, h01, l01, h10, l10, h11, l11;
        bf16_split(v00, h00, l00); bf16_split(v01, h01, l01);
        bf16_split(v10, h10, l10); bf16_split(v11, h11, l11);
        __nv_bfloat162 ph0; ph0.x = h00; ph0.y = h01;
        __nv_bfloat162 ph1; ph1.x = h10; ph1.y = h11;
        __nv_bfloat162 pl0; pl0.x = l00; pl0.y = l01;
        __nv_bfloat162 pl1; pl1.x = l10; pl1.y = l11;
        *(__nv_bfloat162*)(Oh + i0) = ph0;
        *(__nv_bfloat162*)(Oh + i1) = ph1;
        *(__nv_bfloat162*)(Ol + i0) = pl0;
        *(__nv_bfloat162*)(Ol + i1) = pl1;
    }
}

// ================= bf16 3-pass split GEMM, cp.async 2-stage, K=32 per stage =========
#define BUFW 2560
#define STGW 10240
template<int EPI>
__global__ __launch_bounds__(256, 2) void gemm_bfs(const __nv_bfloat16* __restrict__ Ah_,
                                                   const __nv_bfloat16* __restrict__ Al_,
                                                   const __nv_bfloat16* __restrict__ Bh0,
                                                   const __nv_bfloat16* __restrict__ Bl0,
                                                   const __nv_bfloat16* __restrict__ Bh1,
                                                   const __nv_bfloat16* __restrict__ Bl1,
                                                   const __nv_bfloat16* __restrict__ Bh2,
                                                   const __nv_bfloat16* __restrict__ Bl2,
                                                   const float* __restrict__ R,
                                                   float* __restrict__ C0,
                                                   float* __restrict__ C1,
                                                   float* __restrict__ C2,
                                                   __nv_bfloat16* __restrict__ Cbh,
                                                   __nv_bfloat16* __restrict__ Cbl,
                                                   int N, int K)
{
    const __nv_bfloat16* Bh = (blockIdx.z == 0) ? Bh0 : (blockIdx.z == 1 ? Bh1 : Bh2);
    const __nv_bfloat16* Bl = (blockIdx.z == 0) ? Bl0 : (blockIdx.z == 1 ? Bl1 : Bl2);
    float*               C  = (blockIdx.z == 0) ? C0  : (blockIdx.z == 1 ? C1  : C2);

    extern __shared__ uint32_t dsm[];

    int t    = threadIdx.x;
    int lane = t & 31;
    int wid  = t >> 5;
    int bm0  = blockIdx.y * 128;
    int bn0  = blockIdx.x * 128;
    int wm0  = (wid & 3) * 32;
    int wn0  = (wid >> 2) * 64;
    int gr   = lane >> 2;
    int gc   = lane & 3;

    int lrow = t >> 1;
    int lkw  = (t & 1) * 8;

    const __nv_bfloat16* pAh = Ah_ + (size_t)(bm0 + lrow) * K + lkw * 2;
    const __nv_bfloat16* pAl = Al_ + (size_t)(bm0 + lrow) * K + lkw * 2;
    const __nv_bfloat16* pBh = Bh  + (size_t)(bn0 + lrow) * K + lkw * 2;
    const __nv_bfloat16* pBl = Bl  + (size_t)(bn0 + lrow) * K + lkw * 2;

    uint32_t sbase = (uint32_t)__cvta_generic_to_shared(dsm);
    uint32_t soff  = (lrow * 20 + lkw) * 4;

    float c[2][8][4];
    #pragma unroll
    for (int i = 0; i < 2; i++)
        #pragma unroll
        for (int j = 0; j < 8; j++)
            #pragma unroll
            for (int q = 0; q < 4; q++) c[i][j][q] = 0.f;

    #pragma unroll
    for (int s = 0; s < 2; s++) {
        int ko = s * 32;
        uint32_t sb = sbase + s * STGW * 4 + soff;
        cp16(sb,            pAh + ko); cp16(sb + 16,            pAh + ko + 8);
        cp16(sb + BUFW*4,   pAl + ko); cp16(sb + BUFW*4 + 16,   pAl + ko + 8);
        cp16(sb + 2*BUFW*4, pBh + ko); cp16(sb + 2*BUFW*4 + 16, pBh + ko + 8);
        cp16(sb + 3*BUFW*4, pBl + ko); cp16(sb + 3*BUFW*4 + 16, pBl + ko + 8);
        CP_COMMIT();
    }

    const int niter = K / 32;
    for (int it = 0; it < niter; it++) {
        CP_WAIT1();
        __syncthreads();
        int cur = it & 1;
        const uint32_t* sAh = dsm + cur * STGW;
        const uint32_t* sAl = sAh + BUFW;
        const uint32_t* sBh = sAh + 2 * BUFW;
        const uint32_t* sBl = sAh + 3 * BUFW;

        #pragma unroll
        for (int kk = 0; kk < 16; kk += 8) {
            uint32_t afh[2][4], afl[2][4];
            #pragma unroll
            for (int mt = 0; mt < 2; mt++) {
                int rr = (wm0 + mt * 16 + gr) * 20 + kk + gc;
                afh[mt][0] = sAh[rr];
                afh[mt][1] = sAh[rr + 8 * 20];
                afh[mt][2] = sAh[rr + 4];
                afh[mt][3] = sAh[rr + 8 * 20 + 4];
                afl[mt][0] = sAl[rr];
                afl[mt][1] = sAl[rr + 8 * 20];
                afl[mt][2] = sAl[rr + 4];
                afl[mt][3] = sAl[rr + 8 * 20 + 4];
            }
            #pragma unroll
            for (int nt = 0; nt < 8; nt++) {
                int nn = (wn0 + nt * 8 + gr) * 20 + kk + gc;
                uint32_t bh0 = sBh[nn], bh1 = sBh[nn + 4];
                uint32_t bl0 = sBl[nn], bl1 = sBl[nn + 4];
                #pragma unroll
                for (int mt = 0; mt < 2; mt++) {
                    mma_bf16(c[mt][nt][0], c[mt][nt][1], c[mt][nt][2], c[mt][nt][3],
                             afh[mt][0], afh[mt][1], afh[mt][2], afh[mt][3], bh0, bh1);
                    mma_bf16(c[mt][nt][0], c[mt][nt][1], c[mt][nt][2], c[mt][nt][3],
                             afh[mt][0], afh[mt][1], afh[mt][2], afh[mt][3], bl0, bl1);
                    mma_bf16(c[mt][nt][0], c[mt][nt][1], c[mt][nt][2], c[mt][nt][3],
                             afl[mt][0], afl[mt][1], afl[mt][2], afl[mt][3], bh0, bh1);
                }
            }
        }

        __syncthreads();
        if (it + 2 < niter) {
            int ko = (it + 2) * 32;
            uint32_t sb = sbase + cur * STGW * 4 + soff;
            cp16(sb,            pAh + ko); cp16(sb + 16,            pAh + ko + 8);
            cp16(sb + BUFW*4,   pAl + ko); cp16(sb + BUFW*4 + 16,   pAl + ko + 8);
            cp16(sb + 2*BUFW*4, pBh + ko); cp16(sb + 2*BUFW*4 + 16, pBh + ko + 8);
            cp16(sb + 3*BUFW*4, pBl + ko); cp16(sb + 3*BUFW*4 + 16, pBl + ko + 8);
        }
        CP_COMMIT();
    }

    #pragma unroll
    for (int mt = 0; mt < 2; mt++) {
        #pragma unroll
        for (int nt = 0; nt < 8; nt++) {
            int row = bm0 + wm0 + mt * 16 + gr;
            int col = bn0 + wn0 + nt * 8 + gc * 2;
            #pragma unroll
            for (int half = 0; half < 2; half++) {
                int r = row + half * 8;
                float vx = c[mt][nt][half * 2 + 0];
                float vy = c[mt][nt][half * 2 + 1];
                size_t idx = (size_t)r * N + col;
                if (EPI == 1) {
                    float2 rr = *(const float2*)(R + idx);
                    vx += rr.x; vy += rr.y;
                    float2 ov; ov.x = vx; ov.y = vy;
                    *(float2*)(C + idx) = ov;
                } else if (EPI == 2) {
                    vx = vx / (1.f + __expf(-vx));
                    vy = vy / (1.f + __expf(-vy));
                    __nv_bfloat16 hx, lx, hy, ly;
                    bf16_split(vx, hx, lx);
                    bf16_split(vy, hy, ly);
                    __nv_bfloat162 ph; ph.x = hx; ph.y = hy;
                    __nv_bfloat162 pl; pl.x = lx; pl.y = ly;
                    *(__nv_bfloat162*)(Cbh + idx) = ph;
                    *(__nv_bfloat162*)(Cbl + idx) = pl;
                } else {
                    float2 ov; ov.x = vx; ov.y = vy;
                    *(float2*)(C + idx) = ov;
                }
            }
        }
    }
}

// ================= LM head GEMM: fp16 single-pass, ldmatrix frags, cp.async 2-stage ====
__global__ __launch_bounds__(256, 2) void gemm_lm_h(const __half* __restrict__ A,
                                                    const __half* __restrict__ B,
                                                    float* __restrict__ C,
                                                    int N, int K)
{
    __shared__ uint32_t sA[2][128][20];
    __shared__ uint32_t sB[2][128][20];

    int t    = threadIdx.x;
    int lane = t & 31;
    int wid  = t >> 5;
    int bm0  = blockIdx.y * 128;
    int bn0  = blockIdx.x * 128;
    int wm0  = (wid & 3) * 32;
    int wn0  = (wid >> 2) * 64;
    int gr   = lane >> 2;
    int gc   = lane & 3;
    int lm8  = lane & 7, ldq = (lane >> 3) & 1, ldh = lane >> 4;

    int lrow = t >> 1;
    int lkw  = (t & 1) * 8;

    const __half* Ap = A + (size_t)(bm0 + lrow) * K + lkw * 2;
    const __half* Bp = B + (size_t)(bn0 + lrow) * K + lkw * 2;

    float c[2][8][4];
    #pragma unroll
    for (int i = 0; i < 2; i++)
        #pragma unroll
        for (int j = 0; j < 8; j++)
            #pragma unroll
            for (int q = 0; q < 4; q++) c[i][j][q] = 0.f;

    uint32_t saA0 = (uint32_t)__cvta_generic_to_shared(&sA[0][lrow][lkw]);
    uint32_t saB0 = (uint32_t)__cvta_generic_to_shared(&sB[0][lrow][lkw]);
    uint32_t sAbase = (uint32_t)__cvta_generic_to_shared(&sA[0][0][0]);
    uint32_t sBbase = (uint32_t)__cvta_generic_to_shared(&sB[0][0][0]);
    uint32_t aoff = ((wm0 + lm8 + 8*ldq) * 20 + 4*ldh) * 4;
    uint32_t boff = ((wn0 + lm8 + 8*ldh) * 20 + 4*ldq) * 4;
    const uint32_t stageStride = 128 * 20 * 4;

    #pragma unroll
    for (int s = 0; s < 2; s++) {
        int ko = s * 32;
        cp16(saA0 + s * stageStride,      Ap + ko);
        cp16(saA0 + s * stageStride + 16, Ap + ko + 8);
        cp16(saB0 + s * stageStride,      Bp + ko);
        cp16(saB0 + s * stageStride + 16, Bp + ko + 8);
        CP_COMMIT();
    }

    const int niter = K / 32;    // 8
    for (int it = 0; it < niter; it++) {
        CP_WAIT1();
        __syncthreads();
        int cur = it & 1;
        uint32_t sAc = sAbase + cur * stageStride;
        uint32_t sBc = sBbase + cur * stageStride;

        #pragma unroll
        for (int kk = 0; kk < 16; kk += 8) {
            uint32_t af[2][4];
            #pragma unroll
            for (int mt = 0; mt < 2; mt++)
                ldsm_x4(af[mt][0], af[mt][1], af[mt][2], af[mt][3],
                        sAc + aoff + (uint32_t)((mt * 320 + kk) * 4));
            #pragma unroll
            for (int p = 0; p < 4; p++) {
                uint32_t b00, b01, b10, b11;
                ldsm_x4(b00, b01, b10, b11, sBc + boff + (uint32_t)((p * 320 + kk) * 4));
                int n0 = 2*p, n1 = 2*p + 1;
                #pragma unroll
                for (int mt = 0; mt < 2; mt++) {
                    mma_fp16(c[mt][n0][0], c[mt][n0][1], c[mt][n0][2], c[mt][n0][3],
                             af[mt][0], af[mt][1], af[mt][2], af[mt][3], b00, b01);
                    mma_fp16(c[mt][n1][0], c[mt][n1][1], c[mt][n1][2], c[mt][n1][3],
                             af[mt][0], af[mt][1], af[mt][2], af[mt][3], b10, b11);
                }
            }
        }

        __syncthreads();
        if (it + 2 < niter) {
            int ko = (it + 2) * 32;
            cp16(saA0 + cur * stageStride,      Ap + ko);
            cp16(saA0 + cur * stageStride + 16, Ap + ko + 8);
            cp16(saB0 + cur * stageStride,      Bp + ko);
            cp16(saB0 + cur * stageStride + 16, Bp + ko + 8);
        }
        CP_COMMIT();
    }

    #pragma unroll
    for (int mt = 0; mt < 2; mt++) {
        #pragma unroll
        for (int nt = 0; nt < 8; nt++) {
            int row = bm0 + wm0 + mt * 16 + gr;
            int col = bn0 + wn0 + nt * 8 + gc * 2;
            #pragma unroll
            for (int half = 0; half < 2; half++) {
                int r = row + half * 8;
                float2 ov;
                ov.x = c[mt][nt][half * 2 + 0];
                ov.y = c[mt][nt][half * 2 + 1];
                *(float2*)(C + (size_t)r * N + col) = ov;
            }
        }
    }
}

// ---------------- classifier heads ----------------
__global__ void heads_kernel(const float* __restrict__ X,
                             const float* __restrict__ fnw,
                             const float* __restrict__ rw, const float* __restrict__ rb,
                             const float* __restrict__ mw, const float* __restrict__ mb,
                             float* __restrict__ out)
{
    int w = threadIdx.x >> 5, lane = threadIdx.x & 31;
    if (w >= Bk) return;
    const float* x = X + (size_t)w * Lk * Dk;
    float ss = 0.f;
    for (int d = lane; d < Dk; d += 32) { float v = x[d]; ss += v * v; }
    #pragma unroll
    for (int o = 16; o > 0; o >>= 1) ss += __shfl_xor_sync(0xffffffffu, ss, o);
    float rs = rsqrtf(ss * (1.0f / Dk) + 1.1920929e-07f);
    float sr = 0.f, sm = 0.f;
    for (int d = lane; d < Dk; d += 32) {
        float xn = x[d] * rs * fnw[d];
        sr += xn * rw[d];
        sm += xn * mw[d];
    }
    #pragma unroll
    for (int o = 16; o > 0; o >>= 1) {
        sr += __shfl_down_sync(0xffffffffu, sr, o);
        sm += __shfl_down_sync(0xffffffffu, sm, o);
    }
    if (lane == 0) {
        out[w]      = sr + rb[0];
        out[Bk + w] = sm + mb[0];
    }
}

// ---------------- launch ----------------
extern "C" void kernel_launch(void* const* d_in, const int* in_sizes, int n_in,
                              void* d_out, int out_size)
{
    const int*   ids      = (const int*)d_in[0];
    const int*   tts      = (const int*)d_in[1];
    const int*   mask     = (const int*)d_in[2];
    const float* tok_emb  = (const float*)d_in[3];
    const float* type_emb = (const float*)d_in[4];
    const float* norm1    = (const float*)d_in[5];
    const float* wq       = (const float*)d_in[6];
    const float* wk       = (const float*)d_in[7];
    const float* wv       = (const float*)d_in[8];
    const float* wo       = (const float*)d_in[9];
    const float* norm2    = (const float*)d_in[10];
    const float* fw1      = (const float*)d_in[11];
    const float* fw2      = (const float*)d_in[12];
    const float* fnorm    = (const float*)d_in[13];
    const float* lmw      = (const float*)d_in[14];
    const float* rw       = (const float*)d_in[15];
    const float* rbias    = (const float*)d_in[16];
    const float* mw       = (const float*)d_in[17];
    const float* mbias    = (const float*)d_in[18];
    float* out = (float*)d_out;

    float *X, *Q, *K, *V;
    __nv_bfloat16 *XNh, *XNl, *AOh, *AOl, *F1h, *F1l, *Wh, *Wl;
    __half *XNH16, *LWH;
    cudaGetSymbolAddress((void**)&X,     g_X);
    cudaGetSymbolAddress((void**)&Q,     g_Q);
    cudaGetSymbolAddress((void**)&K,     g_K);
    cudaGetSymbolAddress((void**)&V,     g_V);
    cudaGetSymbolAddress((void**)&XNh,   g_XNh);
    cudaGetSymbolAddress((void**)&XNl,   g_XNl);
    cudaGetSymbolAddress((void**)&AOh,   g_AOh);
    cudaGetSymbolAddress((void**)&AOl,   g_AOl);
    cudaGetSymbolAddress((void**)&F1h,   g_F1h);
    cudaGetSymbolAddress((void**)&F1l,   g_F1l);
    cudaGetSymbolAddress((void**)&Wh,    g_Wh);
    cudaGetSymbolAddress((void**)&Wl,    g_Wl);
    cudaGetSymbolAddress((void**)&XNH16, g_XNH16);
    cudaGetSymbolAddress((void**)&LWH,   g_LWH);

    const int dynSmem = STGW * 2 * 4;   // 81920 bytes
    cudaFuncSetAttribute(gemm_bfs<0>, cudaFuncAttributeMaxDynamicSharedMemorySize, dynSmem);
    cudaFuncSetAttribute(gemm_bfs<1>, cudaFuncAttributeMaxDynamicSharedMemorySize, dynSmem);
    cudaFuncSetAttribute(gemm_bfs<2>, cudaFuncAttributeMaxDynamicSharedMemorySize, dynSmem);

    embed_kernel<<<(MR * Dk) / 256, 256>>>(ids, tts, tok_emb, type_emb, X);
    prep_kernel<<<(WTOT + Vk * Dk) / 256, 256>>>(wq, wk, wv, wo, fw1, fw2, lmw, Wh, Wl, LWH);
    rope_tab_kernel<<<(Lk * 32) / 256, 256>>>();

    dim3 gqkv(Dk  / 128, MR / 128, 3);
    dim3 gs  (Dk  / 128, MR / 128, 1);
    dim3 gf1 (FFD / 128, MR / 128, 1);
    dim3 glm (Vk  / 128, MR / 128);
    dim3 ga  (Lk / 64, Hk, Bk);
    dim3 grp ((MR * Hk * 32) / 256, 2);

    for (int i = 0; i < NLk; i++) {
        size_t od = (size_t)i * Dk * Dk;
        size_t of = (size_t)i * FFD * Dk;
        const __nv_bfloat16 *qh = Wh + OFF_WQ + od, *ql = Wl + OFF_WQ + od;
        const __nv_bfloat16 *kh = Wh + OFF_WK + od, *kl = Wl + OFF_WK + od;
        const __nv_bfloat16 *vh = Wh + OFF_WV + od, *vl = Wl + OFF_WV + od;
        const __nv_bfloat16 *oh = Wh + OFF_WO + od, *ol = Wl + OFF_WO + od;
        const __nv_bfloat16 *f1h = Wh + OFF_F1 + of, *f1l = Wl + OFF_F1 + of;
        const __nv_bfloat16 *f2h = Wh + OFF_F2 + of, *f2l = Wl + OFF_F2 + of;

        rmsnorm_kernel<<<MR / 8, 256>>>(X, norm1 + (size_t)i * Dk, XNh, XNl);
        gemm_bfs<0><<<gqkv, 256, dynSmem>>>(XNh, XNl, qh, ql, kh, kl, vh, vl,
                                            nullptr, Q, K, V, nullptr, nullptr, Dk, Dk);
        rope2_kernel<<<grp, 256>>>(Q, K);
        attn_fa<<<ga, 128>>>(Q, K, V, mask, AOh, AOl);
        gemm_bfs<1><<<gs, 256, dynSmem>>>(AOh, AOl, oh, ol, oh, ol, oh, ol,
                                          X, X, X, X, nullptr, nullptr, Dk, Dk);
        rmsnorm_kernel<<<MR / 8, 256>>>(X, norm2 + (size_t)i * Dk, XNh, XNl);
        gemm_bfs<2><<<gf1, 256, dynSmem>>>(XNh, XNl, f1h, f1l, f1h, f1l, f1h, f1l,
                                           nullptr, nullptr, nullptr, nullptr,
                                           F1h, F1l, FFD, Dk);
        gemm_bfs<1><<<gs, 256, dynSmem>>>(F1h, F1l, f2h, f2l, f2h, f2l, f2h, f2l,
                                          X, X, X, X, nullptr, nullptr, Dk, FFD);
    }

    rmsnorm_f16_kernel<<<MR / 8, 256>>>(X, fnorm, XNH16);
    gemm_lm_h<<<glm, 256>>>(XNH16, LWH, out, Vk, Dk);
    heads_kernel<<<1, 128>>>(X, fnorm, rw, rbias, mw, mbias, out + (size_t)Bk * Lk * Vk);
}

// round 13
// speedup vs baseline: 1.4628x; 1.0240x over previous
#include <cuda_runtime.h>
#include <cuda_bf16.h>
#include <cuda_fp16.h>
#include <math.h>
#include <stdint.h>

// Problem constants
#define Bk   4
#define Lk   2048
#define Dk   256
#define Hk   4
#define NLk  4
#define Vk   32000
#define DHk  64
#define MR   (Bk*Lk)      // 8192 rows
#define FFD  (4*Dk)       // 1024

// weight-split offsets (elements)
#define WDSZ (NLk*Dk*Dk)          // 262144
#define WFSZ (NLk*FFD*Dk)         // 1048576
#define OFF_WQ  0
#define OFF_WK  (WDSZ)
#define OFF_WV  (2*WDSZ)
#define OFF_WO  (3*WDSZ)
#define OFF_F1  (4*WDSZ)
#define OFF_F2  (4*WDSZ + WFSZ)
#define WTOT    (4*WDSZ + 2*WFSZ)

// ---------------- scratch ----------------
__device__ float g_X   [MR*Dk];
__device__ float g_Q   [MR*Dk];
__device__ float g_K   [MR*Dk];
__device__ float g_V   [MR*Dk];
__device__ __nv_bfloat16 g_XNh[MR*Dk];
__device__ __nv_bfloat16 g_XNl[MR*Dk];
__device__ __nv_bfloat16 g_AOh[MR*Dk];
__device__ __nv_bfloat16 g_AOl[MR*Dk];
__device__ __nv_bfloat16 g_F1h[MR*FFD];
__device__ __nv_bfloat16 g_F1l[MR*FFD];
__device__ __nv_bfloat16 g_Wh [WTOT];
__device__ __nv_bfloat16 g_Wl [WTOT];
__device__ __half g_XNH16[MR*Dk];
__device__ __half g_LWH  [Vk*Dk];
__device__ float2 g_ROPE [Lk*32];

// ---------------- helpers ----------------
__device__ __forceinline__ void mma_bf16(float& c0, float& c1, float& c2, float& c3,
                                         uint32_t a0, uint32_t a1, uint32_t a2, uint32_t a3,
                                         uint32_t b0, uint32_t b1)
{
    asm volatile("mma.sync.aligned.m16n8k16.row.col.f32.bf16.bf16.f32 "
                 "{%0,%1,%2,%3},{%4,%5,%6,%7},{%8,%9},{%0,%1,%2,%3};"
                 : "+f"(c0), "+f"(c1), "+f"(c2), "+f"(c3)
                 : "r"(a0), "r"(a1), "r"(a2), "r"(a3), "r"(b0), "r"(b1));
}

__device__ __forceinline__ void mma_fp16(float& c0, float& c1, float& c2, float& c3,
                                         uint32_t a0, uint32_t a1, uint32_t a2, uint32_t a3,
                                         uint32_t b0, uint32_t b1)
{
    asm volatile("mma.sync.aligned.m16n8k16.row.col.f32.f16.f16.f32 "
                 "{%0,%1,%2,%3},{%4,%5,%6,%7},{%8,%9},{%0,%1,%2,%3};"
                 : "+f"(c0), "+f"(c1), "+f"(c2), "+f"(c3)
                 : "r"(a0), "r"(a1), "r"(a2), "r"(a3), "r"(b0), "r"(b1));
}

__device__ __forceinline__ void ldsm_x4(uint32_t& r0, uint32_t& r1, uint32_t& r2, uint32_t& r3,
                                        uint32_t addr)
{
    asm volatile("ldmatrix.sync.aligned.m8n8.x4.shared.b16 {%0,%1,%2,%3}, [%4];"
                 : "=r"(r0), "=r"(r1), "=r"(r2), "=r"(r3) : "r"(addr));
}

__device__ __forceinline__ void cp16(uint32_t smem, const void* gmem) {
    asm volatile("cp.async.ca.shared.global [%0], [%1], 16;\n" :: "r"(smem), "l"(gmem));
}
#define CP_COMMIT() asm volatile("cp.async.commit_group;\n" ::: "memory")
#define CP_WAIT1()  asm volatile("cp.async.wait_group 1;\n" ::: "memory")

__device__ __forceinline__ void bf16_split(float v, __nv_bfloat16& h, __nv_bfloat16& l) {
    h = __float2bfloat16_rn(v);
    l = __float2bfloat16_rn(v - __bfloat162float(h));
}

__device__ __forceinline__ uint32_t pack_h2(float a, float b) {
    __half2 h = __floats2half2_rn(a, b);
    return *reinterpret_cast<uint32_t*>(&h);
}

// ---------------- embedding ----------------
__global__ void embed_kernel(const int* __restrict__ ids, const int* __restrict__ tts,
                             const float* __restrict__ te, const float* __restrict__ ye,
                             float* __restrict__ X)
{
    int i = blockIdx.x * 256 + threadIdx.x;
    int row = i >> 8;
    int d   = i & 255;
    X[i] = te[(size_t)ids[row] * Dk + d] + ye[(size_t)tts[row] * Dk + d];
}

// ---------------- merged prep: weight splits + LM fp16 convert ----------------
__global__ void prep_kernel(const float* __restrict__ wq, const float* __restrict__ wk,
                            const float* __restrict__ wv, const float* __restrict__ wo,
                            const float* __restrict__ fw1, const float* __restrict__ fw2,
                            const float* __restrict__ lmw,
                            __nv_bfloat16* __restrict__ Wh,
                            __nv_bfloat16* __restrict__ Wl,
                            __half* __restrict__ LWH)
{
    int i = blockIdx.x * 256 + threadIdx.x;
    if (i < WTOT) {
        float x;
        if (i < 4*WDSZ) {
            int seg = i / WDSZ;
            int j = i - seg * WDSZ;
            const float* src = (seg == 0) ? wq : (seg == 1) ? wk : (seg == 2) ? wv : wo;
            x = src[j];
        } else if (i < 4*WDSZ + WFSZ) {
            x = fw1[i - 4*WDSZ];
        } else {
            x = fw2[i - 4*WDSZ - WFSZ];
        }
        __nv_bfloat16 h, l;
        bf16_split(x, h, l);
        Wh[i] = h; Wl[i] = l;
    } else {
        int j = i - WTOT;           // < Vk*Dk by grid sizing
        LWH[j] = __float2half_rn(lmw[j]);
    }
}

// ---------------- RoPE table ----------------
__global__ void rope_tab_kernel()
{
    int i = blockIdx.x * 256 + threadIdx.x;    // Lk*32
    int pos = i >> 5, t = i & 31;
    float inv = exp2f(-(float)t * (13.287712379549449f / 32.0f));
    float sn, cs;
    sincosf((float)pos * inv, &sn, &cs);
    float2 v; v.x = cs; v.y = sn;
    g_ROPE[i] = v;
}

// ---------------- RMSNorm: warp-per-row -> bf16 hi/lo ----------------
__global__ __launch_bounds__(256) void rmsnorm_kernel(const float* __restrict__ X,
                                                      const float* __restrict__ w,
                                                      __nv_bfloat16* __restrict__ Yh,
                                                      __nv_bfloat16* __restrict__ Yl)
{
    int warp = threadIdx.x >> 5, lane = threadIdx.x & 31;
    int r = blockIdx.x * 8 + warp;
    const float* xr = X + (size_t)r * Dk;
    float4 v0 = *(const float4*)(xr + lane * 4);
    float4 v1 = *(const float4*)(xr + 128 + lane * 4);
    float s = v0.x*v0.x + v0.y*v0.y + v0.z*v0.z + v0.w*v0.w
            + v1.x*v1.x + v1.y*v1.y + v1.z*v1.z + v1.w*v1.w;
    #pragma unroll
    for (int o = 16; o > 0; o >>= 1) s += __shfl_xor_sync(0xffffffffu, s, o);
    float rs = rsqrtf(s * (1.0f / Dk) + 1.1920929e-07f);
    float4 w0 = *(const float4*)(w + lane * 4);
    float4 w1 = *(const float4*)(w + 128 + lane * 4);
    float y[8] = { v0.x*rs*w0.x, v0.y*rs*w0.y, v0.z*rs*w0.z, v0.w*rs*w0.w,
                   v1.x*rs*w1.x, v1.y*rs*w1.y, v1.z*rs*w1.z, v1.w*rs*w1.w };
    #pragma unroll
    for (int seg = 0; seg < 2; seg++) {
        #pragma unroll
        for (int p = 0; p < 2; p++) {
            __nv_bfloat16 h0, l0, h1, l1;
            bf16_split(y[seg*4 + p*2    ], h0, l0);
            bf16_split(y[seg*4 + p*2 + 1], h1, l1);
            __nv_bfloat162 ph; ph.x = h0; ph.y = h1;
            __nv_bfloat162 pl; pl.x = l0; pl.y = l1;
            size_t idx = (size_t)r * Dk + seg * 128 + lane * 4 + p * 2;
            *(__nv_bfloat162*)(Yh + idx) = ph;
            *(__nv_bfloat162*)(Yl + idx) = pl;
        }
    }
}

// ---------------- final RMSNorm: warp-per-row -> fp16 ----------------
__global__ __launch_bounds__(256) void rmsnorm_f16_kernel(const float* __restrict__ X,
                                                          const float* __restrict__ w,
                                                          __half* __restrict__ Y)
{
    int warp = threadIdx.x >> 5, lane = threadIdx.x & 31;
    int r = blockIdx.x * 8 + warp;
    const float* xr = X + (size_t)r * Dk;
    float4 v0 = *(const float4*)(xr + lane * 4);
    float4 v1 = *(const float4*)(xr + 128 + lane * 4);
    float s = v0.x*v0.x + v0.y*v0.y + v0.z*v0.z + v0.w*v0.w
            + v1.x*v1.x + v1.y*v1.y + v1.z*v1.z + v1.w*v1.w;
    #pragma unroll
    for (int o = 16; o > 0; o >>= 1) s += __shfl_xor_sync(0xffffffffu, s, o);
    float rs = rsqrtf(s * (1.0f / Dk) + 1.1920929e-07f);
    float4 w0 = *(const float4*)(w + lane * 4);
    float4 w1 = *(const float4*)(w + 128 + lane * 4);
    size_t base = (size_t)r * Dk + lane * 4;
    __half2 a0 = __floats2half2_rn(v0.x*rs*w0.x, v0.y*rs*w0.y);
    __half2 a1 = __floats2half2_rn(v0.z*rs*w0.z, v0.w*rs*w0.w);
    __half2 b0 = __floats2half2_rn(v1.x*rs*w1.x, v1.y*rs*w1.y);
    __half2 b1 = __floats2half2_rn(v1.z*rs*w1.z, v1.w*rs*w1.w);
    *(__half2*)(Y + base)           = a0;
    *(__half2*)(Y + base + 2)       = a1;
    *(__half2*)(Y + base + 128)     = b0;
    *(__half2*)(Y + base + 128 + 2) = b1;
}

// ---------------- RoPE (table-driven; Q and K via blockIdx.y) ----------------
__global__ void rope2_kernel(float* __restrict__ Q, float* __restrict__ K)
{
    float* P = blockIdx.y ? K : Q;
    int i   = blockIdx.x * 256 + threadIdx.x;
    int t   = i & 31;
    int h   = (i >> 5) & 3;
    int row = i >> 7;
    int pos = row & (Lk - 1);
    float2 cs = g_ROPE[(pos << 5) | t];
    size_t base = (size_t)row * Dk + h * DHk;
    float a = P[base + t];
    float b = P[base + t + 32];
    P[base + t]      = a * cs.x - b * cs.y;
    P[base + t + 32] = b * cs.x + a * cs.y;
}

// ---------------- fp16 tensor-core flash attention (ldmatrix), bf16 hi/lo output -------
// 64 queries/block (4 warps x 16 rows), 64-key tiles, DH=64. Heavy blocks first.
#define QPAD 36
__global__ __launch_bounds__(128) void attn_fa(const float* __restrict__ Q,
                                               const float* __restrict__ K,
                                               const float* __restrict__ V,
                                               const int*   __restrict__ mask,
                                               __nv_bfloat16* __restrict__ Oh,
                                               __nv_bfloat16* __restrict__ Ol)
{
    __shared__ uint32_t KP[64][QPAD];   // K tile (rows=key, words along d), then P (rows=q, words along key)
    __shared__ uint32_t Vs[64][QPAD];   // V^T: rows=d, words along key
    __shared__ float    mkf[64];

    int b  = blockIdx.z, h = blockIdx.y;
    int qb = gridDim.x - 1 - blockIdx.x;   // heaviest causal blocks launch first
    int q0 = qb * 64;
    int tid = threadIdx.x;
    int lane = tid & 31, wid = tid >> 5;
    int gr = lane >> 2, gc = lane & 3;
    int wr = wid * 16;
    int lm8 = lane & 7, ldq = (lane >> 3) & 1, ldh = lane >> 4;

    uint32_t kpbase = (uint32_t)__cvta_generic_to_shared(&KP[0][0]);
    uint32_t vsbase = (uint32_t)__cvta_generic_to_shared(&Vs[0][0]);
    // B-pattern (16 rows x 8 k-words per ldsm.x4): used for K rows and V rows
    uint32_t boffw = ((lm8 + 8*ldh) * QPAD + 4*ldq) * 4;
    // A-pattern for P rows (this warp's 16 rows)
    uint32_t paoff = ((wr + lm8 + 8*ldq) * QPAD + 4*ldh) * 4;

    const int* mrow = mask + (size_t)b * Lk;

    // stage Q (scaled) as fp16 pairs along d
    #pragma unroll
    for (int it = 0; it < 8; it++) {
        int pos = tid + it * 128;
        int row = pos >> 4, d4 = pos & 15;
        float4 qv = *(const float4*)(Q + ((size_t)(b*Lk + q0 + row))*Dk + h*DHk + d4*4);
        KP[row][d4*2    ] = pack_h2(qv.x*0.125f, qv.y*0.125f);
        KP[row][d4*2 + 1] = pack_h2(qv.z*0.125f, qv.w*0.125f);
    }
    __syncthreads();
    uint32_t qa[4][4];
    #pragma unroll
    for (int kw = 0; kw < 4; kw++) {
        qa[kw][0] = KP[wr+gr  ][kw*8+gc];
        qa[kw][1] = KP[wr+gr+8][kw*8+gc];
        qa[kw][2] = KP[wr+gr  ][kw*8+gc+4];
        qa[kw][3] = KP[wr+gr+8][kw*8+gc+4];
    }

    float o[8][4];
    #pragma unroll
    for (int nt = 0; nt < 8; nt++)
        #pragma unroll
        for (int j = 0; j < 4; j++) o[nt][j] = 0.f;
    float m0 = -1e30f, m1 = -1e30f, l0 = 0.f, l1 = 0.f;
    int r0 = q0 + wr + gr, r1 = r0 + 8;

    int ntile = qb + 1;
    for (int kt = 0; kt < ntile; kt++) {
        int key0 = kt * 64;
        __syncthreads();
        #pragma unroll
        for (int it = 0; it < 8; it++) {
            int pos = tid + it * 128;
            int key = pos >> 4, d4 = pos & 15;
            size_t gbase = ((size_t)(b*Lk + key0 + key))*Dk + h*DHk + d4*4;
            float4 kv = *(const float4*)(K + gbase);
            KP[key][d4*2    ] = pack_h2(kv.x, kv.y);
            KP[key][d4*2 + 1] = pack_h2(kv.z, kv.w);
            float4 vv = *(const float4*)(V + gbase);
            __half* vh = (__half*)&Vs[0][0];
            vh[(d4*4+0)*(2*QPAD) + key] = __float2half_rn(vv.x);
            vh[(d4*4+1)*(2*QPAD) + key] = __float2half_rn(vv.y);
            vh[(d4*4+2)*(2*QPAD) + key] = __float2half_rn(vv.z);
            vh[(d4*4+3)*(2*QPAD) + key] = __float2half_rn(vv.w);
        }
        if (tid < 64) mkf[tid] = mrow[key0 + tid] ? 0.0f : -1e30f;
        __syncthreads();

        // S = Q K^T  (fp16, ldmatrix B-frags: 2 nt per ldsm_x4)
        float s[8][4];
        #pragma unroll
        for (int nt = 0; nt < 8; nt++)
            #pragma unroll
            for (int j = 0; j < 4; j++) s[nt][j] = 0.f;
        #pragma unroll
        for (int kw = 0; kw < 4; kw++) {
            #pragma unroll
            for (int p = 0; p < 4; p++) {
                uint32_t b00, b01, b10, b11;
                ldsm_x4(b00, b01, b10, b11, kpbase + boffw + (uint32_t)((p*16*QPAD + kw*8) * 4));
                mma_fp16(s[2*p  ][0], s[2*p  ][1], s[2*p  ][2], s[2*p  ][3],
                         qa[kw][0], qa[kw][1], qa[kw][2], qa[kw][3], b00, b01);
                mma_fp16(s[2*p+1][0], s[2*p+1][1], s[2*p+1][2], s[2*p+1][3],
                         qa[kw][0], qa[kw][1], qa[kw][2], qa[kw][3], b10, b11);
            }
        }

        bool last = (kt == ntile - 1);
        #pragma unroll
        for (int nt = 0; nt < 8; nt++) {
            float mk0 = mkf[nt*8+gc*2], mk1 = mkf[nt*8+gc*2+1];
            s[nt][0] += mk0; s[nt][1] += mk1;
            s[nt][2] += mk0; s[nt][3] += mk1;
            if (last) {
                int c = key0 + nt*8 + gc*2;
                if (c     > r0) s[nt][0] = -1e30f;
                if (c + 1 > r0) s[nt][1] = -1e30f;
                if (c     > r1) s[nt][2] = -1e30f;
                if (c + 1 > r1) s[nt][3] = -1e30f;
            }
        }

        float rm0 = -1e30f, rm1 = -1e30f;
        #pragma unroll
        for (int nt = 0; nt < 8; nt++) {
            rm0 = fmaxf(rm0, fmaxf(s[nt][0], s[nt][1]));
            rm1 = fmaxf(rm1, fmaxf(s[nt][2], s[nt][3]));
        }
        rm0 = fmaxf(rm0, __shfl_xor_sync(0xffffffffu, rm0, 1));
        rm0 = fmaxf(rm0, __shfl_xor_sync(0xffffffffu, rm0, 2));
        rm1 = fmaxf(rm1, __shfl_xor_sync(0xffffffffu, rm1, 1));
        rm1 = fmaxf(rm1, __shfl_xor_sync(0xffffffffu, rm1, 2));

        float mn0 = fmaxf(m0, rm0), mn1 = fmaxf(m1, rm1);
        float cor0 = __expf(m0 - mn0), cor1 = __expf(m1 - mn1);
        m0 = mn0; m1 = mn1;

        __syncthreads();   // everyone done reading K before P overwrites KP

        float ps0 = 0.f, ps1 = 0.f;
        #pragma unroll
        for (int nt = 0; nt < 8; nt++) {
            float p00 = __expf(s[nt][0] - mn0);
            float p01 = __expf(s[nt][1] - mn0);
            float p10 = __expf(s[nt][2] - mn1);
            float p11 = __expf(s[nt][3] - mn1);
            ps0 += p00 + p01;
            ps1 += p10 + p11;
            KP[wr+gr  ][nt*4+gc] = pack_h2(p00, p01);
            KP[wr+gr+8][nt*4+gc] = pack_h2(p10, p11);
        }
        ps0 += __shfl_xor_sync(0xffffffffu, ps0, 1);
        ps0 += __shfl_xor_sync(0xffffffffu, ps0, 2);
        ps1 += __shfl_xor_sync(0xffffffffu, ps1, 1);
        ps1 += __shfl_xor_sync(0xffffffffu, ps1, 2);
        l0 = l0 * cor0 + ps0;
        l1 = l1 * cor1 + ps1;
        #pragma unroll
        for (int nt = 0; nt < 8; nt++) {
            o[nt][0] *= cor0; o[nt][1] *= cor0;
            o[nt][2] *= cor1; o[nt][3] *= cor1;
        }
        __syncwarp();      // P rows read cross-lane within this warp only

        // O += P V  (fp16, ldmatrix A- and B-frags)
        #pragma unroll
        for (int kw = 0; kw < 4; kw++) {
            uint32_t pa0, pa1, pa2, pa3;
            ldsm_x4(pa0, pa1, pa2, pa3, kpbase + paoff + (uint32_t)(kw * 32));
            #pragma unroll
            for (int p = 0; p < 4; p++) {
                uint32_t v00, v01, v10, v11;
                ldsm_x4(v00, v01, v10, v11, vsbase + boffw + (uint32_t)((p*16*QPAD + kw*8) * 4));
                mma_fp16(o[2*p  ][0], o[2*p  ][1], o[2*p  ][2], o[2*p  ][3],
                         pa0, pa1, pa2, pa3, v00, v01);
                mma_fp16(o[2*p+1][0], o[2*p+1][1], o[2*p+1][2], o[2*p+1][3],
                         pa0, pa1, pa2, pa3, v10, v11);
            }
        }
    }

    float inv0 = 1.0f / l0, inv1 = 1.0f / l1;
    #pragma unroll
    for (int nt = 0; nt < 8; nt++) {
        int d = nt*8 + gc*2;
        size_t i0 = ((size_t)(b*Lk + r0))*Dk + h*DHk + d;
        size_t i1 = ((size_t)(b*Lk + r1))*Dk + h*DHk + d;
        float v00 = o[nt][0]*inv0, v01 = o[nt][1]*inv0;
        float v10 = o[nt][2]*inv1, v11 = o[nt][3]*inv1;
        __nv_bfloat16 h00, l00, h01, l01, h10, l10, h11, l11;
        bf16_split(v00, h00, l00); bf16_split(v01, h01, l01);
        bf16_split(v10, h10, l10); bf16_split(v11, h11, l11);
        __nv_bfloat162 ph0; ph0.x = h00; ph0.y = h01;
        __nv_bfloat162 ph1; ph1.x = h10; ph1.y = h11;
        __nv_bfloat162 pl0; pl0.x = l00; pl0.y = l01;
        __nv_bfloat162 pl1; pl1.x = l10; pl1.y = l11;
        *(__nv_bfloat162*)(Oh + i0) = ph0;
        *(__nv_bfloat162*)(Oh + i1) = ph1;
        *(__nv_bfloat162*)(Ol + i0) = pl0;
        *(__nv_bfloat162*)(Ol + i1) = pl1;
    }
}

// ================= bf16 3-pass split GEMM, cp.async 2-stage, K=32 per stage =========
#define BUFW 2560
#define STGW 10240
template<int EPI>
__global__ __launch_bounds__(256, 2) void gemm_bfs(const __nv_bfloat16* __restrict__ Ah_,
                                                   const __nv_bfloat16* __restrict__ Al_,
                                                   const __nv_bfloat16* __restrict__ Bh0,
                                                   const __nv_bfloat16* __restrict__ Bl0,
                                                   const __nv_bfloat16* __restrict__ Bh1,
                                                   const __nv_bfloat16* __restrict__ Bl1,
                                                   const __nv_bfloat16* __restrict__ Bh2,
                                                   const __nv_bfloat16* __restrict__ Bl2,
                                                   const float* __restrict__ R,
                                                   float* __restrict__ C0,
                                                   float* __restrict__ C1,
                                                   float* __restrict__ C2,
                                                   __nv_bfloat16* __restrict__ Cbh,
                                                   __nv_bfloat16* __restrict__ Cbl,
                                                   int N, int K)
{
    const __nv_bfloat16* Bh = (blockIdx.z == 0) ? Bh0 : (blockIdx.z == 1 ? Bh1 : Bh2);
    const __nv_bfloat16* Bl = (blockIdx.z == 0) ? Bl0 : (blockIdx.z == 1 ? Bl1 : Bl2);
    float*               C  = (blockIdx.z == 0) ? C0  : (blockIdx.z == 1 ? C1  : C2);

    extern __shared__ uint32_t dsm[];

    int t    = threadIdx.x;
    int lane = t & 31;
    int wid  = t >> 5;
    int bm0  = blockIdx.y * 128;
    int bn0  = blockIdx.x * 128;
    int wm0  = (wid & 3) * 32;
    int wn0  = (wid >> 2) * 64;
    int gr   = lane >> 2;
    int gc   = lane & 3;

    int lrow = t >> 1;
    int lkw  = (t & 1) * 8;

    const __nv_bfloat16* pAh = Ah_ + (size_t)(bm0 + lrow) * K + lkw * 2;
    const __nv_bfloat16* pAl = Al_ + (size_t)(bm0 + lrow) * K + lkw * 2;
    const __nv_bfloat16* pBh = Bh  + (size_t)(bn0 + lrow) * K + lkw * 2;
    const __nv_bfloat16* pBl = Bl  + (size_t)(bn0 + lrow) * K + lkw * 2;

    uint32_t sbase = (uint32_t)__cvta_generic_to_shared(dsm);
    uint32_t soff  = (lrow * 20 + lkw) * 4;

    float c[2][8][4];
    #pragma unroll
    for (int i = 0; i < 2; i++)
        #pragma unroll
        for (int j = 0; j < 8; j++)
            #pragma unroll
            for (int q = 0; q < 4; q++) c[i][j][q] = 0.f;

    #pragma unroll
    for (int s = 0; s < 2; s++) {
        int ko = s * 32;
        uint32_t sb = sbase + s * STGW * 4 + soff;
        cp16(sb,            pAh + ko); cp16(sb + 16,            pAh + ko + 8);
        cp16(sb + BUFW*4,   pAl + ko); cp16(sb + BUFW*4 + 16,   pAl + ko + 8);
        cp16(sb + 2*BUFW*4, pBh + ko); cp16(sb + 2*BUFW*4 + 16, pBh + ko + 8);
        cp16(sb + 3*BUFW*4, pBl + ko); cp16(sb + 3*BUFW*4 + 16, pBl + ko + 8);
        CP_COMMIT();
    }

    const int niter = K / 32;
    for (int it = 0; it < niter; it++) {
        CP_WAIT1();
        __syncthreads();
        int cur = it & 1;
        const uint32_t* sAh = dsm + cur * STGW;
        const uint32_t* sAl = sAh + BUFW;
        const uint32_t* sBh = sAh + 2 * BUFW;
        const uint32_t* sBl = sAh + 3 * BUFW;

        #pragma unroll
        for (int kk = 0; kk < 16; kk += 8) {
            uint32_t afh[2][4], afl[2][4];
            #pragma unroll
            for (int mt = 0; mt < 2; mt++) {
                int rr = (wm0 + mt * 16 + gr) * 20 + kk + gc;
                afh[mt][0] = sAh[rr];
                afh[mt][1] = sAh[rr + 8 * 20];
                afh[mt][2] = sAh[rr + 4];
                afh[mt][3] = sAh[rr + 8 * 20 + 4];
                afl[mt][0] = sAl[rr];
                afl[mt][1] = sAl[rr + 8 * 20];
                afl[mt][2] = sAl[rr + 4];
                afl[mt][3] = sAl[rr + 8 * 20 + 4];
            }
            #pragma unroll
            for (int nt = 0; nt < 8; nt++) {
                int nn = (wn0 + nt * 8 + gr) * 20 + kk + gc;
                uint32_t bh0 = sBh[nn], bh1 = sBh[nn + 4];
                uint32_t bl0 = sBl[nn], bl1 = sBl[nn + 4];
                #pragma unroll
                for (int mt = 0; mt < 2; mt++) {
                    mma_bf16(c[mt][nt][0], c[mt][nt][1], c[mt][nt][2], c[mt][nt][3],
                             afh[mt][0], afh[mt][1], afh[mt][2], afh[mt][3], bh0, bh1);
                    mma_bf16(c[mt][nt][0], c[mt][nt][1], c[mt][nt][2], c[mt][nt][3],
                             afh[mt][0], afh[mt][1], afh[mt][2], afh[mt][3], bl0, bl1);
                    mma_bf16(c[mt][nt][0], c[mt][nt][1], c[mt][nt][2], c[mt][nt][3],
                             afl[mt][0], afl[mt][1], afl[mt][2], afl[mt][3], bh0, bh1);
                }
            }
        }

        __syncthreads();
        if (it + 2 < niter) {
            int ko = (it + 2) * 32;
            uint32_t sb = sbase + cur * STGW * 4 + soff;
            cp16(sb,            pAh + ko); cp16(sb + 16,            pAh + ko + 8);
            cp16(sb + BUFW*4,   pAl + ko); cp16(sb + BUFW*4 + 16,   pAl + ko + 8);
            cp16(sb + 2*BUFW*4, pBh + ko); cp16(sb + 2*BUFW*4 + 16, pBh + ko + 8);
            cp16(sb + 3*BUFW*4, pBl + ko); cp16(sb + 3*BUFW*4 + 16, pBl + ko + 8);
        }
        CP_COMMIT();
    }

    #pragma unroll
    for (int mt = 0; mt < 2; mt++) {
        #pragma unroll
        for (int nt = 0; nt < 8; nt++) {
            int row = bm0 + wm0 + mt * 16 + gr;
            int col = bn0 + wn0 + nt * 8 + gc * 2;
            #pragma unroll
            for (int half = 0; half < 2; half++) {
                int r = row + half * 8;
                float vx = c[mt][nt][half * 2 + 0];
                float vy = c[mt][nt][half * 2 + 1];
                size_t idx = (size_t)r * N + col;
                if (EPI == 1) {
                    float2 rr = *(const float2*)(R + idx);
                    vx += rr.x; vy += rr.y;
                    float2 ov; ov.x = vx; ov.y = vy;
                    *(float2*)(C + idx) = ov;
                } else if (EPI == 2) {
                    vx = vx / (1.f + __expf(-vx));
                    vy = vy / (1.f + __expf(-vy));
                    __nv_bfloat16 hx, lx, hy, ly;
                    bf16_split(vx, hx, lx);
                    bf16_split(vy, hy, ly);
                    __nv_bfloat162 ph; ph.x = hx; ph.y = hy;
                    __nv_bfloat162 pl; pl.x = lx; pl.y = ly;
                    *(__nv_bfloat162*)(Cbh + idx) = ph;
                    *(__nv_bfloat162*)(Cbl + idx) = pl;
                } else {
                    float2 ov; ov.x = vx; ov.y = vy;
                    *(float2*)(C + idx) = ov;
                }
            }
        }
    }
}

// ================= LM head GEMM: fp16 single-pass, ldmatrix frags, cp.async 2-stage ====
__global__ __launch_bounds__(256, 2) void gemm_lm_h(const __half* __restrict__ A,
                                                    const __half* __restrict__ B,
                                                    float* __restrict__ C,
                                                    int N, int K)
{
    __shared__ uint32_t sA[2][128][20];
    __shared__ uint32_t sB[2][128][20];

    int t    = threadIdx.x;
    int lane = t & 31;
    int wid  = t >> 5;
    int bm0  = blockIdx.y * 128;
    int bn0  = blockIdx.x * 128;
    int wm0  = (wid & 3) * 32;
    int wn0  = (wid >> 2) * 64;
    int gr   = lane >> 2;
    int gc   = lane & 3;
    int lm8  = lane & 7, ldq = (lane >> 3) & 1, ldh = lane >> 4;

    int lrow = t >> 1;
    int lkw  = (t & 1) * 8;

    const __half* Ap = A + (size_t)(bm0 + lrow) * K + lkw * 2;
    const __half* Bp = B + (size_t)(bn0 + lrow) * K + lkw * 2;

    float c[2][8][4];
    #pragma unroll
    for (int i = 0; i < 2; i++)
        #pragma unroll
        for (int j = 0; j < 8; j++)
            #pragma unroll
            for (int q = 0; q < 4; q++) c[i][j][q] = 0.f;

    uint32_t saA0 = (uint32_t)__cvta_generic_to_shared(&sA[0][lrow][lkw]);
    uint32_t saB0 = (uint32_t)__cvta_generic_to_shared(&sB[0][lrow][lkw]);
    uint32_t sAbase = (uint32_t)__cvta_generic_to_shared(&sA[0][0][0]);
    uint32_t sBbase = (uint32_t)__cvta_generic_to_shared(&sB[0][0][0]);
    uint32_t aoff = ((wm0 + lm8 + 8*ldq) * 20 + 4*ldh) * 4;
    uint32_t boff = ((wn0 + lm8 + 8*ldh) * 20 + 4*ldq) * 4;
    const uint32_t stageStride = 128 * 20 * 4;

    #pragma unroll
    for (int s = 0; s < 2; s++) {
        int ko = s * 32;
        cp16(saA0 + s * stageStride,      Ap + ko);
        cp16(saA0 + s * stageStride + 16, Ap + ko + 8);
        cp16(saB0 + s * stageStride,      Bp + ko);
        cp16(saB0 + s * stageStride + 16, Bp + ko + 8);
        CP_COMMIT();
    }

    const int niter = K / 32;    // 8
    for (int it = 0; it < niter; it++) {
        CP_WAIT1();
        __syncthreads();
        int cur = it & 1;
        uint32_t sAc = sAbase + cur * stageStride;
        uint32_t sBc = sBbase + cur * stageStride;

        #pragma unroll
        for (int kk = 0; kk < 16; kk += 8) {
            uint32_t af[2][4];
            #pragma unroll
            for (int mt = 0; mt < 2; mt++)
                ldsm_x4(af[mt][0], af[mt][1], af[mt][2], af[mt][3],
                        sAc + aoff + (uint32_t)((mt * 320 + kk) * 4));
            #pragma unroll
            for (int p = 0; p < 4; p++) {
                uint32_t b00, b01, b10, b11;
                ldsm_x4(b00, b01, b10, b11, sBc + boff + (uint32_t)((p * 320 + kk) * 4));
                int n0 = 2*p, n1 = 2*p + 1;
                #pragma unroll
                for (int mt = 0; mt < 2; mt++) {
                    mma_fp16(c[mt][n0][0], c[mt][n0][1], c[mt][n0][2], c[mt][n0][3],
                             af[mt][0], af[mt][1], af[mt][2], af[mt][3], b00, b01);
                    mma_fp16(c[mt][n1][0], c[mt][n1][1], c[mt][n1][2], c[mt][n1][3],
                             af[mt][0], af[mt][1], af[mt][2], af[mt][3], b10, b11);
                }
            }
        }

        __syncthreads();
        if (it + 2 < niter) {
            int ko = (it + 2) * 32;
            cp16(saA0 + cur * stageStride,      Ap + ko);
            cp16(saA0 + cur * stageStride + 16, Ap + ko + 8);
            cp16(saB0 + cur * stageStride,      Bp + ko);
            cp16(saB0 + cur * stageStride + 16, Bp + ko + 8);
        }
        CP_COMMIT();
    }

    #pragma unroll
    for (int mt = 0; mt < 2; mt++) {
        #pragma unroll
        for (int nt = 0; nt < 8; nt++) {
            int row = bm0 + wm0 + mt * 16 + gr;
            int col = bn0 + wn0 + nt * 8 + gc * 2;
            #pragma unroll
            for (int half = 0; half < 2; half++) {
                int r = row + half * 8;
                float2 ov;
                ov.x = c[mt][nt][half * 2 + 0];
                ov.y = c[mt][nt][half * 2 + 1];
                *(float2*)(C + (size_t)r * N + col) = ov;
            }
        }
    }
}

// ---------------- classifier heads ----------------
__global__ void heads_kernel(const float* __restrict__ X,
                             const float* __restrict__ fnw,
                             const float* __restrict__ rw, const float* __restrict__ rb,
                             const float* __restrict__ mw, const float* __restrict__ mb,
                             float* __restrict__ out)
{
    int w = threadIdx.x >> 5, lane = threadIdx.x & 31;
    if (w >= Bk) return;
    const float* x = X + (size_t)w * Lk * Dk;
    float ss = 0.f;
    for (int d = lane; d < Dk; d += 32) { float v = x[d]; ss += v * v; }
    #pragma unroll
    for (int o = 16; o > 0; o >>= 1) ss += __shfl_xor_sync(0xffffffffu, ss, o);
    float rs = rsqrtf(ss * (1.0f / Dk) + 1.1920929e-07f);
    float sr = 0.f, sm = 0.f;
    for (int d = lane; d < Dk; d += 32) {
        float xn = x[d] * rs * fnw[d];
        sr += xn * rw[d];
        sm += xn * mw[d];
    }
    #pragma unroll
    for (int o = 16; o > 0; o >>= 1) {
        sr += __shfl_down_sync(0xffffffffu, sr, o);
        sm += __shfl_down_sync(0xffffffffu, sm, o);
    }
    if (lane == 0) {
        out[w]      = sr + rb[0];
        out[Bk + w] = sm + mb[0];
    }
}

// ---------------- launch ----------------
extern "C" void kernel_launch(void* const* d_in, const int* in_sizes, int n_in,
                              void* d_out, int out_size)
{
    const int*   ids      = (const int*)d_in[0];
    const int*   tts      = (const int*)d_in[1];
    const int*   mask     = (const int*)d_in[2];
    const float* tok_emb  = (const float*)d_in[3];
    const float* type_emb = (const float*)d_in[4];
    const float* norm1    = (const float*)d_in[5];
    const float* wq       = (const float*)d_in[6];
    const float* wk       = (const float*)d_in[7];
    const float* wv       = (const float*)d_in[8];
    const float* wo       = (const float*)d_in[9];
    const float* norm2    = (const float*)d_in[10];
    const float* fw1      = (const float*)d_in[11];
    const float* fw2      = (const float*)d_in[12];
    const float* fnorm    = (const float*)d_in[13];
    const float* lmw      = (const float*)d_in[14];
    const float* rw       = (const float*)d_in[15];
    const float* rbias    = (const float*)d_in[16];
    const float* mw       = (const float*)d_in[17];
    const float* mbias    = (const float*)d_in[18];
    float* out = (float*)d_out;

    float *X, *Q, *K, *V;
    __nv_bfloat16 *XNh, *XNl, *AOh, *AOl, *F1h, *F1l, *Wh, *Wl;
    __half *XNH16, *LWH;
    cudaGetSymbolAddress((void**)&X,     g_X);
    cudaGetSymbolAddress((void**)&Q,     g_Q);
    cudaGetSymbolAddress((void**)&K,     g_K);
    cudaGetSymbolAddress((void**)&V,     g_V);
    cudaGetSymbolAddress((void**)&XNh,   g_XNh);
    cudaGetSymbolAddress((void**)&XNl,   g_XNl);
    cudaGetSymbolAddress((void**)&AOh,   g_AOh);
    cudaGetSymbolAddress((void**)&AOl,   g_AOl);
    cudaGetSymbolAddress((void**)&F1h,   g_F1h);
    cudaGetSymbolAddress((void**)&F1l,   g_F1l);
    cudaGetSymbolAddress((void**)&Wh,    g_Wh);
    cudaGetSymbolAddress((void**)&Wl,    g_Wl);
    cudaGetSymbolAddress((void**)&XNH16, g_XNH16);
    cudaGetSymbolAddress((void**)&LWH,   g_LWH);

    const int dynSmem = STGW * 2 * 4;   // 81920 bytes
    cudaFuncSetAttribute(gemm_bfs<0>, cudaFuncAttributeMaxDynamicSharedMemorySize, dynSmem);
    cudaFuncSetAttribute(gemm_bfs<1>, cudaFuncAttributeMaxDynamicSharedMemorySize, dynSmem);
    cudaFuncSetAttribute(gemm_bfs<2>, cudaFuncAttributeMaxDynamicSharedMemorySize, dynSmem);

    embed_kernel<<<(MR * Dk) / 256, 256>>>(ids, tts, tok_emb, type_emb, X);
    prep_kernel<<<(WTOT + Vk * Dk) / 256, 256>>>(wq, wk, wv, wo, fw1, fw2, lmw, Wh, Wl, LWH);
    rope_tab_kernel<<<(Lk * 32) / 256, 256>>>();

    dim3 gqkv(Dk  / 128, MR / 128, 3);
    dim3 gs  (Dk  / 128, MR / 128, 1);
    dim3 gf1 (FFD / 128, MR / 128, 1);
    dim3 glm (Vk  / 128, MR / 128);
    dim3 ga  (Lk / 64, Hk, Bk);
    dim3 grp ((MR * Hk * 32) / 256, 2);

    for (int i = 0; i < NLk; i++) {
        size_t od = (size_t)i * Dk * Dk;
        size_t of = (size_t)i * FFD * Dk;
        const __nv_bfloat16 *qh = Wh + OFF_WQ + od, *ql = Wl + OFF_WQ + od;
        const __nv_bfloat16 *kh = Wh + OFF_WK + od, *kl = Wl + OFF_WK + od;
        const __nv_bfloat16 *vh = Wh + OFF_WV + od, *vl = Wl + OFF_WV + od;
        const __nv_bfloat16 *oh = Wh + OFF_WO + od, *ol = Wl + OFF_WO + od;
        const __nv_bfloat16 *f1h = Wh + OFF_F1 + of, *f1l = Wl + OFF_F1 + of;
        const __nv_bfloat16 *f2h = Wh + OFF_F2 + of, *f2l = Wl + OFF_F2 + of;

        rmsnorm_kernel<<<MR / 8, 256>>>(X, norm1 + (size_t)i * Dk, XNh, XNl);
        gemm_bfs<0><<<gqkv, 256, dynSmem>>>(XNh, XNl, qh, ql, kh, kl, vh, vl,
                                            nullptr, Q, K, V, nullptr, nullptr, Dk, Dk);
        rope2_kernel<<<grp, 256>>>(Q, K);
        attn_fa<<<ga, 128>>>(Q, K, V, mask, AOh, AOl);
        gemm_bfs<1><<<gs, 256, dynSmem>>>(AOh, AOl, oh, ol, oh, ol, oh, ol,
                                          X, X, X, X, nullptr, nullptr, Dk, Dk);
        rmsnorm_kernel<<<MR / 8, 256>>>(X, norm2 + (size_t)i * Dk, XNh, XNl);
        gemm_bfs<2><<<gf1, 256, dynSmem>>>(XNh, XNl, f1h, f1l, f1h, f1l, f1h, f1l,
                                           nullptr, nullptr, nullptr, nullptr,
                                           F1h, F1l, FFD, Dk);
        gemm_bfs<1><<<gs, 256, dynSmem>>>(F1h, F1l, f2h, f2l, f2h, f2l, f2h, f2l,
                                          X, X, X, X, nullptr, nullptr, Dk, FFD);
    }

    rmsnorm_f16_kernel<<<MR / 8, 256>>>(X, fnorm, XNH16);
    gemm_lm_h<<<glm, 256>>>(XNH16, LWH, out, Vk, Dk);
    heads_kernel<<<1, 128>>>(X, fnorm, rw, rbias, mw, mbias, out + (size_t)Bk * Lk * Vk);
}

// round 14
// speedup vs baseline: 1.4719x; 1.0062x over previous
#include <cuda_runtime.h>
#include <cuda_bf16.h>
#include <cuda_fp16.h>
#include <math.h>
#include <stdint.h>

// Problem constants
#define Bk   4
#define Lk   2048
#define Dk   256
#define Hk   4
#define NLk  4
#define Vk   32000
#define DHk  64
#define MR   (Bk*Lk)      // 8192 rows
#define FFD  (4*Dk)       // 1024

// weight-split offsets (elements)
#define WDSZ (NLk*Dk*Dk)          // 262144
#define WFSZ (NLk*FFD*Dk)         // 1048576
#define OFF_WQ  0
#define OFF_WK  (WDSZ)
#define OFF_WV  (2*WDSZ)
#define OFF_WO  (3*WDSZ)
#define OFF_F1  (4*WDSZ)
#define OFF_F2  (4*WDSZ + WFSZ)
#define WTOT    (4*WDSZ + 2*WFSZ)

// ---------------- scratch ----------------
__device__ float g_X   [MR*Dk];
__device__ __half g_QKV16[3*MR*Dk];          // Q | K | V, fp16, RoPE applied (Q pre-scaled)
__device__ __nv_bfloat16 g_XNh[MR*Dk];
__device__ __nv_bfloat16 g_XNl[MR*Dk];
__device__ __nv_bfloat16 g_AOh[MR*Dk];
__device__ __nv_bfloat16 g_AOl[MR*Dk];
__device__ __nv_bfloat16 g_F1h[MR*FFD];
__device__ __nv_bfloat16 g_F1l[MR*FFD];
__device__ __nv_bfloat16 g_Wh [WTOT];
__device__ __nv_bfloat16 g_Wl [WTOT];
__device__ __half g_XNH16[MR*Dk];
__device__ __half g_LWH  [Vk*Dk];
__device__ float2 g_ROPE [Lk*32];

// ---------------- helpers ----------------
__device__ __forceinline__ void mma_bf16(float& c0, float& c1, float& c2, float& c3,
                                         uint32_t a0, uint32_t a1, uint32_t a2, uint32_t a3,
                                         uint32_t b0, uint32_t b1)
{
    asm volatile("mma.sync.aligned.m16n8k16.row.col.f32.bf16.bf16.f32 "
                 "{%0,%1,%2,%3},{%4,%5,%6,%7},{%8,%9},{%0,%1,%2,%3};"
                 : "+f"(c0), "+f"(c1), "+f"(c2), "+f"(c3)
                 : "r"(a0), "r"(a1), "r"(a2), "r"(a3), "r"(b0), "r"(b1));
}

__device__ __forceinline__ void mma_fp16(float& c0, float& c1, float& c2, float& c3,
                                         uint32_t a0, uint32_t a1, uint32_t a2, uint32_t a3,
                                         uint32_t b0, uint32_t b1)
{
    asm volatile("mma.sync.aligned.m16n8k16.row.col.f32.f16.f16.f32 "
                 "{%0,%1,%2,%3},{%4,%5,%6,%7},{%8,%9},{%0,%1,%2,%3};"
                 : "+f"(c0), "+f"(c1), "+f"(c2), "+f"(c3)
                 : "r"(a0), "r"(a1), "r"(a2), "r"(a3), "r"(b0), "r"(b1));
}

__device__ __forceinline__ void ldsm_x4(uint32_t& r0, uint32_t& r1, uint32_t& r2, uint32_t& r3,
                                        uint32_t addr)
{
    asm volatile("ldmatrix.sync.aligned.m8n8.x4.shared.b16 {%0,%1,%2,%3}, [%4];"
                 : "=r"(r0), "=r"(r1), "=r"(r2), "=r"(r3) : "r"(addr));
}

__device__ __forceinline__ void cp16(uint32_t smem, const void* gmem) {
    asm volatile("cp.async.ca.shared.global [%0], [%1], 16;\n" :: "r"(smem), "l"(gmem));
}
#define CP_COMMIT() asm volatile("cp.async.commit_group;\n" ::: "memory")
#define CP_WAIT1()  asm volatile("cp.async.wait_group 1;\n" ::: "memory")

__device__ __forceinline__ void bf16_split(float v, __nv_bfloat16& h, __nv_bfloat16& l) {
    h = __float2bfloat16_rn(v);
    l = __float2bfloat16_rn(v - __bfloat162float(h));
}

// ---------------- embedding ----------------
__global__ void embed_kernel(const int* __restrict__ ids, const int* __restrict__ tts,
                             const float* __restrict__ te, const float* __restrict__ ye,
                             float* __restrict__ X)
{
    int i = blockIdx.x * 256 + threadIdx.x;
    int row = i >> 8;
    int d   = i & 255;
    X[i] = te[(size_t)ids[row] * Dk + d] + ye[(size_t)tts[row] * Dk + d];
}

// ---------------- merged prep: weight splits + LM fp16 convert ----------------
__global__ void prep_kernel(const float* __restrict__ wq, const float* __restrict__ wk,
                            const float* __restrict__ wv, const float* __restrict__ wo,
                            const float* __restrict__ fw1, const float* __restrict__ fw2,
                            const float* __restrict__ lmw,
                            __nv_bfloat16* __restrict__ Wh,
                            __nv_bfloat16* __restrict__ Wl,
                            __half* __restrict__ LWH)
{
    int i = blockIdx.x * 256 + threadIdx.x;
    if (i < WTOT) {
        float x;
        if (i < 4*WDSZ) {
            int seg = i / WDSZ;
            int j = i - seg * WDSZ;
            const float* src = (seg == 0) ? wq : (seg == 1) ? wk : (seg == 2) ? wv : wo;
            x = src[j];
        } else if (i < 4*WDSZ + WFSZ) {
            x = fw1[i - 4*WDSZ];
        } else {
            x = fw2[i - 4*WDSZ - WFSZ];
        }
        __nv_bfloat16 h, l;
        bf16_split(x, h, l);
        Wh[i] = h; Wl[i] = l;
    } else {
        int j = i - WTOT;           // < Vk*Dk by grid sizing
        LWH[j] = __float2half_rn(lmw[j]);
    }
}

// ---------------- RoPE table ----------------
__global__ void rope_tab_kernel()
{
    int i = blockIdx.x * 256 + threadIdx.x;    // Lk*32
    int pos = i >> 5, t = i & 31;
    float inv = exp2f(-(float)t * (13.287712379549449f / 32.0f));
    float sn, cs;
    sincosf((float)pos * inv, &sn, &cs);
    float2 v; v.x = cs; v.y = sn;
    g_ROPE[i] = v;
}

// ---------------- RMSNorm: warp-per-row -> bf16 hi/lo ----------------
__global__ __launch_bounds__(256) void rmsnorm_kernel(const float* __restrict__ X,
                                                      const float* __restrict__ w,
                                                      __nv_bfloat16* __restrict__ Yh,
                                                      __nv_bfloat16* __restrict__ Yl)
{
    int warp = threadIdx.x >> 5, lane = threadIdx.x & 31;
    int r = blockIdx.x * 8 + warp;
    const float* xr = X + (size_t)r * Dk;
    float4 v0 = *(const float4*)(xr + lane * 4);
    float4 v1 = *(const float4*)(xr + 128 + lane * 4);
    float s = v0.x*v0.x + v0.y*v0.y + v0.z*v0.z + v0.w*v0.w
            + v1.x*v1.x + v1.y*v1.y + v1.z*v1.z + v1.w*v1.w;
    #pragma unroll
    for (int o = 16; o > 0; o >>= 1) s += __shfl_xor_sync(0xffffffffu, s, o);
    float rs = rsqrtf(s * (1.0f / Dk) + 1.1920929e-07f);
    float4 w0 = *(const float4*)(w + lane * 4);
    float4 w1 = *(const float4*)(w + 128 + lane * 4);
    float y[8] = { v0.x*rs*w0.x, v0.y*rs*w0.y, v0.z*rs*w0.z, v0.w*rs*w0.w,
                   v1.x*rs*w1.x, v1.y*rs*w1.y, v1.z*rs*w1.z, v1.w*rs*w1.w };
    #pragma unroll
    for (int seg = 0; seg < 2; seg++) {
        #pragma unroll
        for (int p = 0; p < 2; p++) {
            __nv_bfloat16 h0, l0, h1, l1;
            bf16_split(y[seg*4 + p*2    ], h0, l0);
            bf16_split(y[seg*4 + p*2 + 1], h1, l1);
            __nv_bfloat162 ph; ph.x = h0; ph.y = h1;
            __nv_bfloat162 pl; pl.x = l0; pl.y = l1;
            size_t idx = (size_t)r * Dk + seg * 128 + lane * 4 + p * 2;
            *(__nv_bfloat162*)(Yh + idx) = ph;
            *(__nv_bfloat162*)(Yl + idx) = pl;
        }
    }
}

// ---------------- final RMSNorm: warp-per-row -> fp16 ----------------
__global__ __launch_bounds__(256) void rmsnorm_f16_kernel(const float* __restrict__ X,
                                                          const float* __restrict__ w,
                                                          __half* __restrict__ Y)
{
    int warp = threadIdx.x >> 5, lane = threadIdx.x & 31;
    int r = blockIdx.x * 8 + warp;
    const float* xr = X + (size_t)r * Dk;
    float4 v0 = *(const float4*)(xr + lane * 4);
    float4 v1 = *(const float4*)(xr + 128 + lane * 4);
    float s = v0.x*v0.x + v0.y*v0.y + v0.z*v0.z + v0.w*v0.w
            + v1.x*v1.x + v1.y*v1.y + v1.z*v1.z + v1.w*v1.w;
    #pragma unroll
    for (int o = 16; o > 0; o >>= 1) s += __shfl_xor_sync(0xffffffffu, s, o);
    float rs = rsqrtf(s * (1.0f / Dk) + 1.1920929e-07f);
    float4 w0 = *(const float4*)(w + lane * 4);
    float4 w1 = *(const float4*)(w + 128 + lane * 4);
    size_t base = (size_t)r * Dk + lane * 4;
    __half2 a0 = __floats2half2_rn(v0.x*rs*w0.x, v0.y*rs*w0.y);
    __half2 a1 = __floats2half2_rn(v0.z*rs*w0.z, v0.w*rs*w0.w);
    __half2 b0 = __floats2half2_rn(v1.x*rs*w1.x, v1.y*rs*w1.y);
    __half2 b1 = __floats2half2_rn(v1.z*rs*w1.z, v1.w*rs*w1.w);
    *(__half2*)(Y + base)           = a0;
    *(__half2*)(Y + base + 2)       = a1;
    *(__half2*)(Y + base + 128)     = b0;
    *(__half2*)(Y + base + 128 + 2) = b1;
}

// ---------------- fp16 tensor-core flash attention (ldmatrix, fp16 in), bf16 hi/lo out --
// 64 queries/block (4 warps x 16 rows), 64-key tiles, DH=64. Heavy blocks first.
#define QPAD 36
__global__ __launch_bounds__(128) void attn_fa(const __half* __restrict__ Q,
                                               const __half* __restrict__ K,
                                               const __half* __restrict__ V,
                                               const int*   __restrict__ mask,
                                               __nv_bfloat16* __restrict__ Oh,
                                               __nv_bfloat16* __restrict__ Ol)
{
    __shared__ uint32_t KP[64][QPAD];   // K tile (rows=key, words along d), then P (rows=q, words along key)
    __shared__ uint32_t Vs[64][QPAD];   // V^T: rows=d, words along key
    __shared__ float    mkf[64];

    int b  = blockIdx.z, h = blockIdx.y;
    int qb = gridDim.x - 1 - blockIdx.x;   // heaviest causal blocks launch first
    int q0 = qb * 64;
    int tid = threadIdx.x;
    int lane = tid & 31, wid = tid >> 5;
    int gr = lane >> 2, gc = lane & 3;
    int wr = wid * 16;
    int lm8 = lane & 7, ldq = (lane >> 3) & 1, ldh = lane >> 4;

    uint32_t kpbase = (uint32_t)__cvta_generic_to_shared(&KP[0][0]);
    uint32_t vsbase = (uint32_t)__cvta_generic_to_shared(&Vs[0][0]);
    uint32_t boffw = ((lm8 + 8*ldh) * QPAD + 4*ldq) * 4;
    uint32_t paoff = ((wr + lm8 + 8*ldq) * QPAD + 4*ldh) * 4;

    const int* mrow = mask + (size_t)b * Lk;

    // stage Q tile (already fp16, RoPE'd, pre-scaled): pure 16B copies
    #pragma unroll
    for (int it = 0; it < 4; it++) {
        int pos = tid + it * 128;
        int row = pos >> 3, c8 = pos & 7;
        uint4 qv = *(const uint4*)(Q + ((size_t)(b*Lk + q0 + row))*Dk + h*DHk + c8*8);
        *(uint4*)&KP[row][c8*4] = qv;
    }
    __syncthreads();
    uint32_t qa[4][4];
    #pragma unroll
    for (int kw = 0; kw < 4; kw++) {
        qa[kw][0] = KP[wr+gr  ][kw*8+gc];
        qa[kw][1] = KP[wr+gr+8][kw*8+gc];
        qa[kw][2] = KP[wr+gr  ][kw*8+gc+4];
        qa[kw][3] = KP[wr+gr+8][kw*8+gc+4];
    }

    float o[8][4];
    #pragma unroll
    for (int nt = 0; nt < 8; nt++)
        #pragma unroll
        for (int j = 0; j < 4; j++) o[nt][j] = 0.f;
    float m0 = -1e30f, m1 = -1e30f, l0 = 0.f, l1 = 0.f;
    int r0 = q0 + wr + gr, r1 = r0 + 8;

    int ntile = qb + 1;
    for (int kt = 0; kt < ntile; kt++) {
        int key0 = kt * 64;
        __syncthreads();
        #pragma unroll
        for (int it = 0; it < 4; it++) {
            int pos = tid + it * 128;
            int key = pos >> 3, c8 = pos & 7;
            size_t gbase = ((size_t)(b*Lk + key0 + key))*Dk + h*DHk + c8*8;
            uint4 kv = *(const uint4*)(K + gbase);
            *(uint4*)&KP[key][c8*4] = kv;
            uint4 vv = *(const uint4*)(V + gbase);
            const __half* vsrc = (const __half*)&vv;
            __half* vh = (__half*)&Vs[0][0];
            #pragma unroll
            for (int j = 0; j < 8; j++)
                vh[(c8*8 + j)*(2*QPAD) + key] = vsrc[j];
        }
        if (tid < 64) mkf[tid] = mrow[key0 + tid] ? 0.0f : -1e30f;
        __syncthreads();

        // S = Q K^T  (fp16, ldmatrix B-frags)
        float s[8][4];
        #pragma unroll
        for (int nt = 0; nt < 8; nt++)
            #pragma unroll
            for (int j = 0; j < 4; j++) s[nt][j] = 0.f;
        #pragma unroll
        for (int kw = 0; kw < 4; kw++) {
            #pragma unroll
            for (int p = 0; p < 4; p++) {
                uint32_t b00, b01, b10, b11;
                ldsm_x4(b00, b01, b10, b11, kpbase + boffw + (uint32_t)((p*16*QPAD + kw*8) * 4));
                mma_fp16(s[2*p  ][0], s[2*p  ][1], s[2*p  ][2], s[2*p  ][3],
                         qa[kw][0], qa[kw][1], qa[kw][2], qa[kw][3], b00, b01);
                mma_fp16(s[2*p+1][0], s[2*p+1][1], s[2*p+1][2], s[2*p+1][3],
                         qa[kw][0], qa[kw][1], qa[kw][2], qa[kw][3], b10, b11);
            }
        }

        bool last = (kt == ntile - 1);
        #pragma unroll
        for (int nt = 0; nt < 8; nt++) {
            float mk0 = mkf[nt*8+gc*2], mk1 = mkf[nt*8+gc*2+1];
            s[nt][0] += mk0; s[nt][1] += mk1;
            s[nt][2] += mk0; s[nt][3] += mk1;
            if (last) {
                int c = key0 + nt*8 + gc*2;
                if (c     > r0) s[nt][0] = -1e30f;
                if (c + 1 > r0) s[nt][1] = -1e30f;
                if (c     > r1) s[nt][2] = -1e30f;
                if (c + 1 > r1) s[nt][3] = -1e30f;
            }
        }

        float rm0 = -1e30f, rm1 = -1e30f;
        #pragma unroll
        for (int nt = 0; nt < 8; nt++) {
            rm0 = fmaxf(rm0, fmaxf(s[nt][0], s[nt][1]));
            rm1 = fmaxf(rm1, fmaxf(s[nt][2], s[nt][3]));
        }
        rm0 = fmaxf(rm0, __shfl_xor_sync(0xffffffffu, rm0, 1));
        rm0 = fmaxf(rm0, __shfl_xor_sync(0xffffffffu, rm0, 2));
        rm1 = fmaxf(rm1, __shfl_xor_sync(0xffffffffu, rm1, 1));
        rm1 = fmaxf(rm1, __shfl_xor_sync(0xffffffffu, rm1, 2));

        float mn0 = fmaxf(m0, rm0), mn1 = fmaxf(m1, rm1);
        float cor0 = __expf(m0 - mn0), cor1 = __expf(m1 - mn1);
        m0 = mn0; m1 = mn1;

        __syncthreads();   // everyone done reading K before P overwrites KP

        float ps0 = 0.f, ps1 = 0.f;
        #pragma unroll
        for (int nt = 0; nt < 8; nt++) {
            float p00 = __expf(s[nt][0] - mn0);
            float p01 = __expf(s[nt][1] - mn0);
            float p10 = __expf(s[nt][2] - mn1);
            float p11 = __expf(s[nt][3] - mn1);
            ps0 += p00 + p01;
            ps1 += p10 + p11;
            __half2 hp0 = __floats2half2_rn(p00, p01);
            __half2 hp1 = __floats2half2_rn(p10, p11);
            KP[wr+gr  ][nt*4+gc] = *(uint32_t*)&hp0;
            KP[wr+gr+8][nt*4+gc] = *(uint32_t*)&hp1;
        }
        ps0 += __shfl_xor_sync(0xffffffffu, ps0, 1);
        ps0 += __shfl_xor_sync(0xffffffffu, ps0, 2);
        ps1 += __shfl_xor_sync(0xffffffffu, ps1, 1);
        ps1 += __shfl_xor_sync(0xffffffffu, ps1, 2);
        l0 = l0 * cor0 + ps0;
        l1 = l1 * cor1 + ps1;
        #pragma unroll
        for (int nt = 0; nt < 8; nt++) {
            o[nt][0] *= cor0; o[nt][1] *= cor0;
            o[nt][2] *= cor1; o[nt][3] *= cor1;
        }
        __syncwarp();      // P rows read cross-lane within this warp only

        // O += P V  (fp16, ldmatrix A- and B-frags)
        #pragma unroll
        for (int kw = 0; kw < 4; kw++) {
            uint32_t pa0, pa1, pa2, pa3;
            ldsm_x4(pa0, pa1, pa2, pa3, kpbase + paoff + (uint32_t)(kw * 32));
            #pragma unroll
            for (int p = 0; p < 4; p++) {
                uint32_t v00, v01, v10, v11;
                ldsm_x4(v00, v01, v10, v11, vsbase + boffw + (uint32_t)((p*16*QPAD + kw*8) * 4));
                mma_fp16(o[2*p  ][0], o[2*p  ][1], o[2*p  ][2], o[2*p  ][3],
                         pa0, pa1, pa2, pa3, v00, v01);
                mma_fp16(o[2*p+1][0], o[2*p+1][1], o[2*p+1][2], o[2*p+1][3],
                         pa0, pa1, pa2, pa3, v10, v11);
            }
        }
    }

    float inv0 = 1.0f / l0, inv1 = 1.0f / l1;
    #pragma unroll
    for (int nt = 0; nt < 8; nt++) {
        int d = nt*8 + gc*2;
        size_t i0 = ((size_t)(b*Lk + r0))*Dk + h*DHk + d;
        size_t i1 = ((size_t)(b*Lk + r1))*Dk + h*DHk + d;
        float v00 = o[nt][0]*inv0, v01 = o[nt][1]*inv0;
        float v10 = o[nt][2]*inv1, v11 = o[nt][3]*inv1;
        __nv_bfloat16 h00, l00, h01, l01, h10, l10, h11, l11;
        bf16_split(v00, h00, l00); bf16_split(v01, h01, l01);
        bf16_split(v10, h10, l10); bf16_split(v11, h11, l11);
        __nv_bfloat162 ph0; ph0.x = h00; ph0.y = h01;
        __nv_bfloat162 ph1; ph1.x = h10; ph1.y = h11;
        __nv_bfloat162 pl0; pl0.x = l00; pl0.y = l01;
        __nv_bfloat162 pl1; pl1.x = l10; pl1.y = l11;
        *(__nv_bfloat162*)(Oh + i0) = ph0;
        *(__nv_bfloat162*)(Oh + i1) = ph1;
        *(__nv_bfloat162*)(Ol + i0) = pl0;
        *(__nv_bfloat162*)(Ol + i1) = pl1;
    }
}

// ================= bf16 3-pass split GEMM, cp.async 2-stage, K=32 per stage =========
// EPI: 1 fp32 +R, 2 silu -> bf16 hi/lo, 3 fp16 QKV with table-RoPE (z<2) + Q scale
#define BUFW 2560
#define STGW 10240
template<int EPI>
__global__ __launch_bounds__(256, 2) void gemm_bfs(const __nv_bfloat16* __restrict__ Ah_,
                                                   const __nv_bfloat16* __restrict__ Al_,
                                                   const __nv_bfloat16* __restrict__ Bh0,
                                                   const __nv_bfloat16* __restrict__ Bl0,
                                                   const __nv_bfloat16* __restrict__ Bh1,
                                                   const __nv_bfloat16* __restrict__ Bl1,
                                                   const __nv_bfloat16* __restrict__ Bh2,
                                                   const __nv_bfloat16* __restrict__ Bl2,
                                                   const float* __restrict__ R,
                                                   float* __restrict__ C0,
                                                   __half* __restrict__ C16,
                                                   __nv_bfloat16* __restrict__ Cbh,
                                                   __nv_bfloat16* __restrict__ Cbl,
                                                   int N, int K)
{
    const __nv_bfloat16* Bh = (blockIdx.z == 0) ? Bh0 : (blockIdx.z == 1 ? Bh1 : Bh2);
    const __nv_bfloat16* Bl = (blockIdx.z == 0) ? Bl0 : (blockIdx.z == 1 ? Bl1 : Bl2);

    extern __shared__ uint32_t dsm[];

    int t    = threadIdx.x;
    int lane = t & 31;
    int wid  = t >> 5;
    int bm0  = blockIdx.y * 128;
    int bn0  = blockIdx.x * 128;
    int wm0  = (wid & 3) * 32;
    int wn0  = (wid >> 2) * 64;
    int gr   = lane >> 2;
    int gc   = lane & 3;

    int lrow = t >> 1;
    int lkw  = (t & 1) * 8;

    const __nv_bfloat16* pAh = Ah_ + (size_t)(bm0 + lrow) * K + lkw * 2;
    const __nv_bfloat16* pAl = Al_ + (size_t)(bm0 + lrow) * K + lkw * 2;
    const __nv_bfloat16* pBh = Bh  + (size_t)(bn0 + lrow) * K + lkw * 2;
    const __nv_bfloat16* pBl = Bl  + (size_t)(bn0 + lrow) * K + lkw * 2;

    uint32_t sbase = (uint32_t)__cvta_generic_to_shared(dsm);
    uint32_t soff  = (lrow * 20 + lkw) * 4;

    float c[2][8][4];
    #pragma unroll
    for (int i = 0; i < 2; i++)
        #pragma unroll
        for (int j = 0; j < 8; j++)
            #pragma unroll
            for (int q = 0; q < 4; q++) c[i][j][q] = 0.f;

    #pragma unroll
    for (int s = 0; s < 2; s++) {
        int ko = s * 32;
        uint32_t sb = sbase + s * STGW * 4 + soff;
        cp16(sb,            pAh + ko); cp16(sb + 16,            pAh + ko + 8);
        cp16(sb + BUFW*4,   pAl + ko); cp16(sb + BUFW*4 + 16,   pAl + ko + 8);
        cp16(sb + 2*BUFW*4, pBh + ko); cp16(sb + 2*BUFW*4 + 16, pBh + ko + 8);
        cp16(sb + 3*BUFW*4, pBl + ko); cp16(sb + 3*BUFW*4 + 16, pBl + ko + 8);
        CP_COMMIT();
    }

    const int niter = K / 32;
    for (int it = 0; it < niter; it++) {
        CP_WAIT1();
        __syncthreads();
        int cur = it & 1;
        const uint32_t* sAh = dsm + cur * STGW;
        const uint32_t* sAl = sAh + BUFW;
        const uint32_t* sBh = sAh + 2 * BUFW;
        const uint32_t* sBl = sAh + 3 * BUFW;

        #pragma unroll
        for (int kk = 0; kk < 16; kk += 8) {
            uint32_t afh[2][4], afl[2][4];
            #pragma unroll
            for (int mt = 0; mt < 2; mt++) {
                int rr = (wm0 + mt * 16 + gr) * 20 + kk + gc;
                afh[mt][0] = sAh[rr];
                afh[mt][1] = sAh[rr + 8 * 20];
                afh[mt][2] = sAh[rr + 4];
                afh[mt][3] = sAh[rr + 8 * 20 + 4];
                afl[mt][0] = sAl[rr];
                afl[mt][1] = sAl[rr + 8 * 20];
                afl[mt][2] = sAl[rr + 4];
                afl[mt][3] = sAl[rr + 8 * 20 + 4];
            }
            #pragma unroll
            for (int nt = 0; nt < 8; nt++) {
                int nn = (wn0 + nt * 8 + gr) * 20 + kk + gc;
                uint32_t bh0 = sBh[nn], bh1 = sBh[nn + 4];
                uint32_t bl0 = sBl[nn], bl1 = sBl[nn + 4];
                #pragma unroll
                for (int mt = 0; mt < 2; mt++) {
                    mma_bf16(c[mt][nt][0], c[mt][nt][1], c[mt][nt][2], c[mt][nt][3],
                             afh[mt][0], afh[mt][1], afh[mt][2], afh[mt][3], bh0, bh1);
                    mma_bf16(c[mt][nt][0], c[mt][nt][1], c[mt][nt][2], c[mt][nt][3],
                             afh[mt][0], afh[mt][1], afh[mt][2], afh[mt][3], bl0, bl1);
                    mma_bf16(c[mt][nt][0], c[mt][nt][1], c[mt][nt][2], c[mt][nt][3],
                             afl[mt][0], afl[mt][1], afl[mt][2], afl[mt][3], bh0, bh1);
                }
            }
        }

        __syncthreads();
        if (it + 2 < niter) {
            int ko = (it + 2) * 32;
            uint32_t sb = sbase + cur * STGW * 4 + soff;
            cp16(sb,            pAh + ko); cp16(sb + 16,            pAh + ko + 8);
            cp16(sb + BUFW*4,   pAl + ko); cp16(sb + BUFW*4 + 16,   pAl + ko + 8);
            cp16(sb + 2*BUFW*4, pBh + ko); cp16(sb + 2*BUFW*4 + 16, pBh + ko + 8);
            cp16(sb + 3*BUFW*4, pBl + ko); cp16(sb + 3*BUFW*4 + 16, pBl + ko + 8);
        }
        CP_COMMIT();
    }

    if (EPI == 3) {
        // QKV epilogue: fp16 store; RoPE via table for Q (z=0, with 0.125 scale) and K (z=1).
        __half* C = C16 + (size_t)blockIdx.z * (MR * Dk);
        bool dorope = (blockIdx.z < 2);
        float qs = (blockIdx.z == 0) ? 0.125f : 1.0f;
        #pragma unroll
        for (int mt = 0; mt < 2; mt++) {
            #pragma unroll
            for (int half = 0; half < 2; half++) {
                int r = bm0 + wm0 + mt * 16 + gr + half * 8;
                int pos = r & (Lk - 1);
                #pragma unroll
                for (int nt = 0; nt < 4; nt++) {
                    int tc = nt * 8 + gc * 2;       // 0..30 within this warp's head window
                    float a0 = c[mt][nt  ][half*2+0], a1 = c[mt][nt  ][half*2+1];
                    float b0 = c[mt][nt+4][half*2+0], b1 = c[mt][nt+4][half*2+1];
                    size_t idx = (size_t)r * N + bn0 + wn0 + tc;
                    if (dorope) {
                        float2 cs0 = g_ROPE[(pos << 5) | tc];
                        float2 cs1 = g_ROPE[(pos << 5) | (tc + 1)];
                        float lo0 = (a0 * cs0.x - b0 * cs0.y) * qs;
                        float lo1 = (a1 * cs1.x - b1 * cs1.y) * qs;
                        float hi0 = (b0 * cs0.x + a0 * cs0.y) * qs;
                        float hi1 = (b1 * cs1.x + a1 * cs1.y) * qs;
                        *(__half2*)(C + idx)      = __floats2half2_rn(lo0, lo1);
                        *(__half2*)(C + idx + 32) = __floats2half2_rn(hi0, hi1);
                    } else {
                        *(__half2*)(C + idx)      = __floats2half2_rn(a0, a1);
                        *(__half2*)(C + idx + 32) = __floats2half2_rn(b0, b1);
                    }
                }
            }
        }
        return;
    }

    #pragma unroll
    for (int mt = 0; mt < 2; mt++) {
        #pragma unroll
        for (int nt = 0; nt < 8; nt++) {
            int row = bm0 + wm0 + mt * 16 + gr;
            int col = bn0 + wn0 + nt * 8 + gc * 2;
            #pragma unroll
            for (int half = 0; half < 2; half++) {
                int r = row + half * 8;
                float vx = c[mt][nt][half * 2 + 0];
                float vy = c[mt][nt][half * 2 + 1];
                size_t idx = (size_t)r * N + col;
                if (EPI == 1) {
                    float2 rr = *(const float2*)(R + idx);
                    vx += rr.x; vy += rr.y;
                    float2 ov; ov.x = vx; ov.y = vy;
                    *(float2*)(C0 + idx) = ov;
                } else if (EPI == 2) {
                    vx = vx / (1.f + __expf(-vx));
                    vy = vy / (1.f + __expf(-vy));
                    __nv_bfloat16 hx, lx, hy, ly;
                    bf16_split(vx, hx, lx);
                    bf16_split(vy, hy, ly);
                    __nv_bfloat162 ph; ph.x = hx; ph.y = hy;
                    __nv_bfloat162 pl; pl.x = lx; pl.y = ly;
                    *(__nv_bfloat162*)(Cbh + idx) = ph;
                    *(__nv_bfloat162*)(Cbl + idx) = pl;
                }
            }
        }
    }
}

// ================= LM head GEMM: fp16 single-pass, ldmatrix frags, cp.async 2-stage ====
__global__ __launch_bounds__(256, 2) void gemm_lm_h(const __half* __restrict__ A,
                                                    const __half* __restrict__ B,
                                                    float* __restrict__ C,
                                                    int N, int K)
{
    __shared__ uint32_t sA[2][128][20];
    __shared__ uint32_t sB[2][128][20];

    int t    = threadIdx.x;
    int lane = t & 31;
    int wid  = t >> 5;
    int bm0  = blockIdx.y * 128;
    int bn0  = blockIdx.x * 128;
    int wm0  = (wid & 3) * 32;
    int wn0  = (wid >> 2) * 64;
    int gr   = lane >> 2;
    int gc   = lane & 3;
    int lm8  = lane & 7, ldq = (lane >> 3) & 1, ldh = lane >> 4;

    int lrow = t >> 1;
    int lkw  = (t & 1) * 8;

    const __half* Ap = A + (size_t)(bm0 + lrow) * K + lkw * 2;
    const __half* Bp = B + (size_t)(bn0 + lrow) * K + lkw * 2;

    float c[2][8][4];
    #pragma unroll
    for (int i = 0; i < 2; i++)
        #pragma unroll
        for (int j = 0; j < 8; j++)
            #pragma unroll
            for (int q = 0; q < 4; q++) c[i][j][q] = 0.f;

    uint32_t saA0 = (uint32_t)__cvta_generic_to_shared(&sA[0][lrow][lkw]);
    uint32_t saB0 = (uint32_t)__cvta_generic_to_shared(&sB[0][lrow][lkw]);
    uint32_t sAbase = (uint32_t)__cvta_generic_to_shared(&sA[0][0][0]);
    uint32_t sBbase = (uint32_t)__cvta_generic_to_shared(&sB[0][0][0]);
    uint32_t aoff = ((wm0 + lm8 + 8*ldq) * 20 + 4*ldh) * 4;
    uint32_t boff = ((wn0 + lm8 + 8*ldh) * 20 + 4*ldq) * 4;
    const uint32_t stageStride = 128 * 20 * 4;

    #pragma unroll
    for (int s = 0; s < 2; s++) {
        int ko = s * 32;
        cp16(saA0 + s * stageStride,      Ap + ko);
        cp16(saA0 + s * stageStride + 16, Ap + ko + 8);
        cp16(saB0 + s * stageStride,      Bp + ko);
        cp16(saB0 + s * stageStride + 16, Bp + ko + 8);
        CP_COMMIT();
    }

    const int niter = K / 32;    // 8
    for (int it = 0; it < niter; it++) {
        CP_WAIT1();
        __syncthreads();
        int cur = it & 1;
        uint32_t sAc = sAbase + cur * stageStride;
        uint32_t sBc = sBbase + cur * stageStride;

        #pragma unroll
        for (int kk = 0; kk < 16; kk += 8) {
            uint32_t af[2][4];
            #pragma unroll
            for (int mt = 0; mt < 2; mt++)
                ldsm_x4(af[mt][0], af[mt][1], af[mt][2], af[mt][3],
                        sAc + aoff + (uint32_t)((mt * 320 + kk) * 4));
            #pragma unroll
            for (int p = 0; p < 4; p++) {
                uint32_t b00, b01, b10, b11;
                ldsm_x4(b00, b01, b10, b11, sBc + boff + (uint32_t)((p * 320 + kk) * 4));
                int n0 = 2*p, n1 = 2*p + 1;
                #pragma unroll
                for (int mt = 0; mt < 2; mt++) {
                    mma_fp16(c[mt][n0][0], c[mt][n0][1], c[mt][n0][2], c[mt][n0][3],
                             af[mt][0], af[mt][1], af[mt][2], af[mt][3], b00, b01);
                    mma_fp16(c[mt][n1][0], c[mt][n1][1], c[mt][n1][2], c[mt][n1][3],
                             af[mt][0], af[mt][1], af[mt][2], af[mt][3], b10, b11);
                }
            }
        }

        __syncthreads();
        if (it + 2 < niter) {
            int ko = (it + 2) * 32;
            cp16(saA0 + cur * stageStride,      Ap + ko);
            cp16(saA0 + cur * stageStride + 16, Ap + ko + 8);
            cp16(saB0 + cur * stageStride,      Bp + ko);
            cp16(saB0 + cur * stageStride + 16, Bp + ko + 8);
        }
        CP_COMMIT();
    }

    #pragma unroll
    for (int mt = 0; mt < 2; mt++) {
        #pragma unroll
        for (int nt = 0; nt < 8; nt++) {
            int row = bm0 + wm0 + mt * 16 + gr;
            int col = bn0 + wn0 + nt * 8 + gc * 2;
            #pragma unroll
            for (int half = 0; half < 2; half++) {
                int r = row + half * 8;
                float2 ov;
                ov.x = c[mt][nt][half * 2 + 0];
                ov.y = c[mt][nt][half * 2 + 1];
                *(float2*)(C + (size_t)r * N + col) = ov;
            }
        }
    }
}

// ---------------- classifier heads ----------------
__global__ void heads_kernel(const float* __restrict__ X,
                             const float* __restrict__ fnw,
                             const float* __restrict__ rw, const float* __restrict__ rb,
                             const float* __restrict__ mw, const float* __restrict__ mb,
                             float* __restrict__ out)
{
    int w = threadIdx.x >> 5, lane = threadIdx.x & 31;
    if (w >= Bk) return;
    const float* x = X + (size_t)w * Lk * Dk;
    float ss = 0.f;
    for (int d = lane; d < Dk; d += 32) { float v = x[d]; ss += v * v; }
    #pragma unroll
    for (int o = 16; o > 0; o >>= 1) ss += __shfl_xor_sync(0xffffffffu, ss, o);
    float rs = rsqrtf(ss * (1.0f / Dk) + 1.1920929e-07f);
    float sr = 0.f, sm = 0.f;
    for (int d = lane; d < Dk; d += 32) {
        float xn = x[d] * rs * fnw[d];
        sr += xn * rw[d];
        sm += xn * mw[d];
    }
    #pragma unroll
    for (int o = 16; o > 0; o >>= 1) {
        sr += __shfl_down_sync(0xffffffffu, sr, o);
        sm += __shfl_down_sync(0xffffffffu, sm, o);
    }
    if (lane == 0) {
        out[w]      = sr + rb[0];
        out[Bk + w] = sm + mb[0];
    }
}

// ---------------- launch ----------------
extern "C" void kernel_launch(void* const* d_in, const int* in_sizes, int n_in,
                              void* d_out, int out_size)
{
    const int*   ids      = (const int*)d_in[0];
    const int*   tts      = (const int*)d_in[1];
    const int*   mask     = (const int*)d_in[2];
    const float* tok_emb  = (const float*)d_in[3];
    const float* type_emb = (const float*)d_in[4];
    const float* norm1    = (const float*)d_in[5];
    const float* wq       = (const float*)d_in[6];
    const float* wk       = (const float*)d_in[7];
    const float* wv       = (const float*)d_in[8];
    const float* wo       = (const float*)d_in[9];
    const float* norm2    = (const float*)d_in[10];
    const float* fw1      = (const float*)d_in[11];
    const float* fw2      = (const float*)d_in[12];
    const float* fnorm    = (const float*)d_in[13];
    const float* lmw      = (const float*)d_in[14];
    const float* rw       = (const float*)d_in[15];
    const float* rbias    = (const float*)d_in[16];
    const float* mw       = (const float*)d_in[17];
    const float* mbias    = (const float*)d_in[18];
    float* out = (float*)d_out;

    float *X;
    __half *QKV16;
    __nv_bfloat16 *XNh, *XNl, *AOh, *AOl, *F1h, *F1l, *Wh, *Wl;
    __half *XNH16, *LWH;
    cudaGetSymbolAddress((void**)&X,     g_X);
    cudaGetSymbolAddress((void**)&QKV16, g_QKV16);
    cudaGetSymbolAddress((void**)&XNh,   g_XNh);
    cudaGetSymbolAddress((void**)&XNl,   g_XNl);
    cudaGetSymbolAddress((void**)&AOh,   g_AOh);
    cudaGetSymbolAddress((void**)&AOl,   g_AOl);
    cudaGetSymbolAddress((void**)&F1h,   g_F1h);
    cudaGetSymbolAddress((void**)&F1l,   g_F1l);
    cudaGetSymbolAddress((void**)&Wh,    g_Wh);
    cudaGetSymbolAddress((void**)&Wl,    g_Wl);
    cudaGetSymbolAddress((void**)&XNH16, g_XNH16);
    cudaGetSymbolAddress((void**)&LWH,   g_LWH);

    __half* Q16 = QKV16;
    __half* K16 = QKV16 + (size_t)MR * Dk;
    __half* V16 = QKV16 + 2 * (size_t)MR * Dk;

    const int dynSmem = STGW * 2 * 4;   // 81920 bytes
    cudaFuncSetAttribute(gemm_bfs<1>, cudaFuncAttributeMaxDynamicSharedMemorySize, dynSmem);
    cudaFuncSetAttribute(gemm_bfs<2>, cudaFuncAttributeMaxDynamicSharedMemorySize, dynSmem);
    cudaFuncSetAttribute(gemm_bfs<3>, cudaFuncAttributeMaxDynamicSharedMemorySize, dynSmem);

    embed_kernel<<<(MR * Dk) / 256, 256>>>(ids, tts, tok_emb, type_emb, X);
    prep_kernel<<<(WTOT + Vk * Dk) / 256, 256>>>(wq, wk, wv, wo, fw1, fw2, lmw, Wh, Wl, LWH);
    rope_tab_kernel<<<(Lk * 32) / 256, 256>>>();

    dim3 gqkv(Dk  / 128, MR / 128, 3);
    dim3 gs  (Dk  / 128, MR / 128, 1);
    dim3 gf1 (FFD / 128, MR / 128, 1);
    dim3 glm (Vk  / 128, MR / 128);
    dim3 ga  (Lk / 64, Hk, Bk);

    for (int i = 0; i < NLk; i++) {
        size_t od = (size_t)i * Dk * Dk;
        size_t of = (size_t)i * FFD * Dk;
        const __nv_bfloat16 *qh = Wh + OFF_WQ + od, *ql = Wl + OFF_WQ + od;
        const __nv_bfloat16 *kh = Wh + OFF_WK + od, *kl = Wl + OFF_WK + od;
        const __nv_bfloat16 *vh = Wh + OFF_WV + od, *vl = Wl + OFF_WV + od;
        const __nv_bfloat16 *oh = Wh + OFF_WO + od, *ol = Wl + OFF_WO + od;
        const __nv_bfloat16 *f1h = Wh + OFF_F1 + of, *f1l = Wl + OFF_F1 + of;
        const __nv_bfloat16 *f2h = Wh + OFF_F2 + of, *f2l = Wl + OFF_F2 + of;

        rmsnorm_kernel<<<MR / 8, 256>>>(X, norm1 + (size_t)i * Dk, XNh, XNl);
        gemm_bfs<3><<<gqkv, 256, dynSmem>>>(XNh, XNl, qh, ql, kh, kl, vh, vl,
                                            nullptr, nullptr, QKV16, nullptr, nullptr, Dk, Dk);
        attn_fa<<<ga, 128>>>(Q16, K16, V16, mask, AOh, AOl);
        gemm_bfs<1><<<gs, 256, dynSmem>>>(AOh, AOl, oh, ol, oh, ol, oh, ol,
                                          X, X, nullptr, nullptr, nullptr, Dk, Dk);
        rmsnorm_kernel<<<MR / 8, 256>>>(X, norm2 + (size_t)i * Dk, XNh, XNl);
        gemm_bfs<2><<<gf1, 256, dynSmem>>>(XNh, XNl, f1h, f1l, f1h, f1l, f1h, f1l,
                                           nullptr, nullptr, nullptr, F1h, F1l, FFD, Dk);
        gemm_bfs<1><<<gs, 256, dynSmem>>>(F1h, F1l, f2h, f2l, f2h, f2l, f2h, f2l,
                                          X, X, nullptr, nullptr, nullptr, Dk, FFD);
    }

    rmsnorm_f16_kernel<<<MR / 8, 256>>>(X, fnorm, XNH16);
    gemm_lm_h<<<glm, 256>>>(XNH16, LWH, out, Vk, Dk);
    heads_kernel<<<1, 128>>>(X, fnorm, rw, rbias, mw, mbias, out + (size_t)Bk * Lk * Vk);
}

// round 16
// speedup vs baseline: 1.6346x; 1.1106x over previous
#include <cuda_runtime.h>
#include <cuda_bf16.h>
#include <cuda_fp16.h>
#include <math.h>
#include <stdint.h>

// Problem constants
#define Bk   4
#define Lk   2048
#define Dk   256
#define Hk   4
#define NLk  4
#define Vk   32000
#define DHk  64
#define MR   (Bk*Lk)      // 8192 rows
#define FFD  (4*Dk)       // 1024

// weight-split offsets (elements)
#define WDSZ (NLk*Dk*Dk)          // 262144
#define WFSZ (NLk*FFD*Dk)         // 1048576
#define OFF_WQ  0
#define OFF_WK  (WDSZ)
#define OFF_WV  (2*WDSZ)
#define OFF_WO  (3*WDSZ)
#define OFF_F1  (4*WDSZ)
#define OFF_F2  (4*WDSZ + WFSZ)
#define WTOT    (4*WDSZ + 2*WFSZ)

// ---------------- scratch ----------------
__device__ float g_X   [MR*Dk];
__device__ __half g_QKV16[3*MR*Dk];          // Q | K | V, fp16, RoPE applied (Q pre-scaled)
__device__ __nv_bfloat16 g_XNh[MR*Dk];
__device__ __nv_bfloat16 g_XNl[MR*Dk];
__device__ __nv_bfloat16 g_AOh[MR*Dk];
__device__ __nv_bfloat16 g_AOl[MR*Dk];
__device__ __nv_bfloat16 g_F1h[MR*FFD];
__device__ __nv_bfloat16 g_F1l[MR*FFD];
__device__ __nv_bfloat16 g_Wh [WTOT];
__device__ __nv_bfloat16 g_Wl [WTOT];
__device__ __half g_XNH16[MR*Dk];
__device__ __half g_LWH  [Vk*Dk];
__device__ float2 g_ROPE [Lk*32];

// ---------------- helpers ----------------
__device__ __forceinline__ void mma_bf16(float& c0, float& c1, float& c2, float& c3,
                                         uint32_t a0, uint32_t a1, uint32_t a2, uint32_t a3,
                                         uint32_t b0, uint32_t b1)
{
    asm volatile("mma.sync.aligned.m16n8k16.row.col.f32.bf16.bf16.f32 "
                 "{%0,%1,%2,%3},{%4,%5,%6,%7},{%8,%9},{%0,%1,%2,%3};"
                 : "+f"(c0), "+f"(c1), "+f"(c2), "+f"(c3)
                 : "r"(a0), "r"(a1), "r"(a2), "r"(a3), "r"(b0), "r"(b1));
}

__device__ __forceinline__ void mma_fp16(float& c0, float& c1, float& c2, float& c3,
                                         uint32_t a0, uint32_t a1, uint32_t a2, uint32_t a3,
                                         uint32_t b0, uint32_t b1)
{
    asm volatile("mma.sync.aligned.m16n8k16.row.col.f32.f16.f16.f32 "
                 "{%0,%1,%2,%3},{%4,%5,%6,%7},{%8,%9},{%0,%1,%2,%3};"
                 : "+f"(c0), "+f"(c1), "+f"(c2), "+f"(c3)
                 : "r"(a0), "r"(a1), "r"(a2), "r"(a3), "r"(b0), "r"(b1));
}

__device__ __forceinline__ void ldsm_x4(uint32_t& r0, uint32_t& r1, uint32_t& r2, uint32_t& r3,
                                        uint32_t addr)
{
    asm volatile("ldmatrix.sync.aligned.m8n8.x4.shared.b16 {%0,%1,%2,%3}, [%4];"
                 : "=r"(r0), "=r"(r1), "=r"(r2), "=r"(r3) : "r"(addr));
}

__device__ __forceinline__ void ldsm_x4_t(uint32_t& r0, uint32_t& r1, uint32_t& r2, uint32_t& r3,
                                          uint32_t addr)
{
    asm volatile("ldmatrix.sync.aligned.m8n8.x4.trans.shared.b16 {%0,%1,%2,%3}, [%4];"
                 : "=r"(r0), "=r"(r1), "=r"(r2), "=r"(r3) : "r"(addr));
}

__device__ __forceinline__ void cp16(uint32_t smem, const void* gmem) {
    asm volatile("cp.async.ca.shared.global [%0], [%1], 16;\n" :: "r"(smem), "l"(gmem));
}
#define CP_COMMIT() asm volatile("cp.async.commit_group;\n" ::: "memory")
#define CP_WAIT1()  asm volatile("cp.async.wait_group 1;\n" ::: "memory")

__device__ __forceinline__ void bf16_split(float v, __nv_bfloat16& h, __nv_bfloat16& l) {
    h = __float2bfloat16_rn(v);
    l = __float2bfloat16_rn(v - __bfloat162float(h));
}

// ---------------- embedding ----------------
__global__ void embed_kernel(const int* __restrict__ ids, const int* __restrict__ tts,
                             const float* __restrict__ te, const float* __restrict__ ye,
                             float* __restrict__ X)
{
    int i = blockIdx.x * 256 + threadIdx.x;
    int row = i >> 8;
    int d   = i & 255;
    X[i] = te[(size_t)ids[row] * Dk + d] + ye[(size_t)tts[row] * Dk + d];
}

// ---------------- merged prep: weight splits + LM fp16 convert ----------------
__global__ void prep_kernel(const float* __restrict__ wq, const float* __restrict__ wk,
                            const float* __restrict__ wv, const float* __restrict__ wo,
                            const float* __restrict__ fw1, const float* __restrict__ fw2,
                            const float* __restrict__ lmw,
                            __nv_bfloat16* __restrict__ Wh,
                            __nv_bfloat16* __restrict__ Wl,
                            __half* __restrict__ LWH)
{
    int i = blockIdx.x * 256 + threadIdx.x;
    if (i < WTOT) {
        float x;
        if (i < 4*WDSZ) {
            int seg = i / WDSZ;
            int j = i - seg * WDSZ;
            const float* src = (seg == 0) ? wq : (seg == 1) ? wk : (seg == 2) ? wv : wo;
            x = src[j];
        } else if (i < 4*WDSZ + WFSZ) {
            x = fw1[i - 4*WDSZ];
        } else {
            x = fw2[i - 4*WDSZ - WFSZ];
        }
        __nv_bfloat16 h, l;
        bf16_split(x, h, l);
        Wh[i] = h; Wl[i] = l;
    } else {
        int j = i - WTOT;           // < Vk*Dk by grid sizing
        LWH[j] = __float2half_rn(lmw[j]);
    }
}

// ---------------- RoPE table ----------------
__global__ void rope_tab_kernel()
{
    int i = blockIdx.x * 256 + threadIdx.x;    // Lk*32
    int pos = i >> 5, t = i & 31;
    float inv = exp2f(-(float)t * (13.287712379549449f / 32.0f));
    float sn, cs;
    sincosf((float)pos * inv, &sn, &cs);
    float2 v; v.x = cs; v.y = sn;
    g_ROPE[i] = v;
}

// ---------------- RMSNorm: warp-per-row -> bf16 hi/lo ----------------
__global__ __launch_bounds__(256) void rmsnorm_kernel(const float* __restrict__ X,
                                                      const float* __restrict__ w,
                                                      __nv_bfloat16* __restrict__ Yh,
                                                      __nv_bfloat16* __restrict__ Yl)
{
    int warp = threadIdx.x >> 5, lane = threadIdx.x & 31;
    int r = blockIdx.x * 8 + warp;
    const float* xr = X + (size_t)r * Dk;
    float4 v0 = *(const float4*)(xr + lane * 4);
    float4 v1 = *(const float4*)(xr + 128 + lane * 4);
    float s = v0.x*v0.x + v0.y*v0.y + v0.z*v0.z + v0.w*v0.w
            + v1.x*v1.x + v1.y*v1.y + v1.z*v1.z + v1.w*v1.w;
    #pragma unroll
    for (int o = 16; o > 0; o >>= 1) s += __shfl_xor_sync(0xffffffffu, s, o);
    float rs = rsqrtf(s * (1.0f / Dk) + 1.1920929e-07f);
    float4 w0 = *(const float4*)(w + lane * 4);
    float4 w1 = *(const float4*)(w + 128 + lane * 4);
    float y[8] = { v0.x*rs*w0.x, v0.y*rs*w0.y, v0.z*rs*w0.z, v0.w*rs*w0.w,
                   v1.x*rs*w1.x, v1.y*rs*w1.y, v1.z*rs*w1.z, v1.w*rs*w1.w };
    #pragma unroll
    for (int seg = 0; seg < 2; seg++) {
        #pragma unroll
        for (int p = 0; p < 2; p++) {
            __nv_bfloat16 h0, l0, h1, l1;
            bf16_split(y[seg*4 + p*2    ], h0, l0);
            bf16_split(y[seg*4 + p*2 + 1], h1, l1);
            __nv_bfloat162 ph; ph.x = h0; ph.y = h1;
            __nv_bfloat162 pl; pl.x = l0; pl.y = l1;
            size_t idx = (size_t)r * Dk + seg * 128 + lane * 4 + p * 2;
            *(__nv_bfloat162*)(Yh + idx) = ph;
            *(__nv_bfloat162*)(Yl + idx) = pl;
        }
    }
}

// ---------------- final RMSNorm: warp-per-row -> fp16 ----------------
__global__ __launch_bounds__(256) void rmsnorm_f16_kernel(const float* __restrict__ X,
                                                          const float* __restrict__ w,
                                                          __half* __restrict__ Y)
{
    int warp = threadIdx.x >> 5, lane = threadIdx.x & 31;
    int r = blockIdx.x * 8 + warp;
    const float* xr = X + (size_t)r * Dk;
    float4 v0 = *(const float4*)(xr + lane * 4);
    float4 v1 = *(const float4*)(xr + 128 + lane * 4);
    float s = v0.x*v0.x + v0.y*v0.y + v0.z*v0.z + v0.w*v0.w
            + v1.x*v1.x + v1.y*v1.y + v1.z*v1.z + v1.w*v1.w;
    #pragma unroll
    for (int o = 16; o > 0; o >>= 1) s += __shfl_xor_sync(0xffffffffu, s, o);
    float rs = rsqrtf(s * (1.0f / Dk) + 1.1920929e-07f);
    float4 w0 = *(const float4*)(w + lane * 4);
    float4 w1 = *(const float4*)(w + 128 + lane * 4);
    size_t base = (size_t)r * Dk + lane * 4;
    __half2 a0 = __floats2half2_rn(v0.x*rs*w0.x, v0.y*rs*w0.y);
    __half2 a1 = __floats2half2_rn(v0.z*rs*w0.z, v0.w*rs*w0.w);
    __half2 b0 = __floats2half2_rn(v1.x*rs*w1.x, v1.y*rs*w1.y);
    __half2 b1 = __floats2half2_rn(v1.z*rs*w1.z, v1.w*rs*w1.w);
    *(__half2*)(Y + base)           = a0;
    *(__half2*)(Y + base + 2)       = a1;
    *(__half2*)(Y + base + 128)     = b0;
    *(__half2*)(Y + base + 128 + 2) = b1;
}

// ---------------- fp16 tensor-core flash attention (ldmatrix + trans-V), bf16 out ------
// 64 queries/block (4 warps x 16 rows), 64-key tiles, DH=64. Heavy blocks first.
#define QPAD 36
__global__ __launch_bounds__(128) void attn_fa(const __half* __restrict__ Q,
                                               const __half* __restrict__ K,
                                               const __half* __restrict__ V,
                                               const int*   __restrict__ mask,
                                               __nv_bfloat16* __restrict__ Oh,
                                               __nv_bfloat16* __restrict__ Ol)
{
    __shared__ uint32_t KP[64][QPAD];   // K tile (rows=key, words along d), then P (rows=q, words along key)
    __shared__ uint32_t Vs[64][QPAD];   // V tile, rows=key, words along d (same as K)
    __shared__ float    mkf[64];

    int b  = blockIdx.z, h = blockIdx.y;
    int qb = gridDim.x - 1 - blockIdx.x;   // heaviest causal blocks launch first
    int q0 = qb * 64;
    int tid = threadIdx.x;
    int lane = tid & 31, wid = tid >> 5;
    int gr = lane >> 2, gc = lane & 3;
    int wr = wid * 16;
    int lm8 = lane & 7, ldq = (lane >> 3) & 1, ldh = lane >> 4;

    uint32_t kpbase = (uint32_t)__cvta_generic_to_shared(&KP[0][0]);
    uint32_t vsbase = (uint32_t)__cvta_generic_to_shared(&Vs[0][0]);
    uint32_t boffw  = ((lm8 + 8*ldh) * QPAD + 4*ldq) * 4;          // K rows (S-phase B)
    uint32_t paoff  = ((wr + lm8 + 8*ldq) * QPAD + 4*ldh) * 4;     // P rows (PV-phase A)
    uint32_t vtoff  = ((lm8 + 8*ldq) * QPAD) * 4 + ldh * 16;       // V rows (PV-phase B, trans)

    const int* mrow = mask + (size_t)b * Lk;

    // stage Q tile (already fp16, RoPE'd, pre-scaled): pure 16B copies
    #pragma unroll
    for (int it = 0; it < 4; it++) {
        int pos = tid + it * 128;
        int row = pos >> 3, c8 = pos & 7;
        uint4 qv = *(const uint4*)(Q + ((size_t)(b*Lk + q0 + row))*Dk + h*DHk + c8*8);
        *(uint4*)&KP[row][c8*4] = qv;
    }
    __syncthreads();
    uint32_t qa[4][4];
    #pragma unroll
    for (int kw = 0; kw < 4; kw++) {
        qa[kw][0] = KP[wr+gr  ][kw*8+gc];
        qa[kw][1] = KP[wr+gr+8][kw*8+gc];
        qa[kw][2] = KP[wr+gr  ][kw*8+gc+4];
        qa[kw][3] = KP[wr+gr+8][kw*8+gc+4];
    }

    float o[8][4];
    #pragma unroll
    for (int nt = 0; nt < 8; nt++)
        #pragma unroll
        for (int j = 0; j < 4; j++) o[nt][j] = 0.f;
    float m0 = -1e30f, m1 = -1e30f, l0 = 0.f, l1 = 0.f;
    int r0 = q0 + wr + gr, r1 = r0 + 8;

    int ntile = qb + 1;
    for (int kt = 0; kt < ntile; kt++) {
        int key0 = kt * 64;
        __syncthreads();
        #pragma unroll
        for (int it = 0; it < 4; it++) {
            int pos = tid + it * 128;
            int key = pos >> 3, c8 = pos & 7;
            size_t gbase = ((size_t)(b*Lk + key0 + key))*Dk + h*DHk + c8*8;
            uint4 kv = *(const uint4*)(K + gbase);
            *(uint4*)&KP[key][c8*4] = kv;
            uint4 vv = *(const uint4*)(V + gbase);
            *(uint4*)&Vs[key][c8*4] = vv;
        }
        if (tid < 64) mkf[tid] = mrow[key0 + tid] ? 0.0f : -1e30f;
        __syncthreads();

        // S = Q K^T  (fp16, ldmatrix B-frags)
        float s[8][4];
        #pragma unroll
        for (int nt = 0; nt < 8; nt++)
            #pragma unroll
            for (int j = 0; j < 4; j++) s[nt][j] = 0.f;
        #pragma unroll
        for (int kw = 0; kw < 4; kw++) {
            #pragma unroll
            for (int p = 0; p < 4; p++) {
                uint32_t b00, b01, b10, b11;
                ldsm_x4(b00, b01, b10, b11, kpbase + boffw + (uint32_t)((p*16*QPAD + kw*8) * 4));
                mma_fp16(s[2*p  ][0], s[2*p  ][1], s[2*p  ][2], s[2*p  ][3],
                         qa[kw][0], qa[kw][1], qa[kw][2], qa[kw][3], b00, b01);
                mma_fp16(s[2*p+1][0], s[2*p+1][1], s[2*p+1][2], s[2*p+1][3],
                         qa[kw][0], qa[kw][1], qa[kw][2], qa[kw][3], b10, b11);
            }
        }

        bool last = (kt == ntile - 1);
        #pragma unroll
        for (int nt = 0; nt < 8; nt++) {
            float mk0 = mkf[nt*8+gc*2], mk1 = mkf[nt*8+gc*2+1];
            s[nt][0] += mk0; s[nt][1] += mk1;
            s[nt][2] += mk0; s[nt][3] += mk1;
            if (last) {
                int c = key0 + nt*8 + gc*2;
                if (c     > r0) s[nt][0] = -1e30f;
                if (c + 1 > r0) s[nt][1] = -1e30f;
                if (c     > r1) s[nt][2] = -1e30f;
                if (c + 1 > r1) s[nt][3] = -1e30f;
            }
        }

        float rm0 = -1e30f, rm1 = -1e30f;
        #pragma unroll
        for (int nt = 0; nt < 8; nt++) {
            rm0 = fmaxf(rm0, fmaxf(s[nt][0], s[nt][1]));
            rm1 = fmaxf(rm1, fmaxf(s[nt][2], s[nt][3]));
        }
        rm0 = fmaxf(rm0, __shfl_xor_sync(0xffffffffu, rm0, 1));
        rm0 = fmaxf(rm0, __shfl_xor_sync(0xffffffffu, rm0, 2));
        rm1 = fmaxf(rm1, __shfl_xor_sync(0xffffffffu, rm1, 1));
        rm1 = fmaxf(rm1, __shfl_xor_sync(0xffffffffu, rm1, 2));

        float mn0 = fmaxf(m0, rm0), mn1 = fmaxf(m1, rm1);
        float cor0 = __expf(m0 - mn0), cor1 = __expf(m1 - mn1);
        m0 = mn0; m1 = mn1;

        __syncthreads();   // everyone done reading K before P overwrites KP

        float ps0 = 0.f, ps1 = 0.f;
        #pragma unroll
        for (int nt = 0; nt < 8; nt++) {
            float p00 = __expf(s[nt][0] - mn0);
            float p01 = __expf(s[nt][1] - mn0);
            float p10 = __expf(s[nt][2] - mn1);
            float p11 = __expf(s[nt][3] - mn1);
            ps0 += p00 + p01;
            ps1 += p10 + p11;
            __half2 hp0 = __floats2half2_rn(p00, p01);
            __half2 hp1 = __floats2half2_rn(p10, p11);
            KP[wr+gr  ][nt*4+gc] = *(uint32_t*)&hp0;
            KP[wr+gr+8][nt*4+gc] = *(uint32_t*)&hp1;
        }
        ps0 += __shfl_xor_sync(0xffffffffu, ps0, 1);
        ps0 += __shfl_xor_sync(0xffffffffu, ps0, 2);
        ps1 += __shfl_xor_sync(0xffffffffu, ps1, 1);
        ps1 += __shfl_xor_sync(0xffffffffu, ps1, 2);
        l0 = l0 * cor0 + ps0;
        l1 = l1 * cor1 + ps1;
        #pragma unroll
        for (int nt = 0; nt < 8; nt++) {
            o[nt][0] *= cor0; o[nt][1] *= cor0;
            o[nt][2] *= cor1; o[nt][3] *= cor1;
        }
        __syncwarp();      // P rows read cross-lane within this warp only

        // O += P V  (fp16; P via ldmatrix, V via ldmatrix.trans on row-major tile)
        #pragma unroll
        for (int kw = 0; kw < 4; kw++) {
            uint32_t pa0, pa1, pa2, pa3;
            ldsm_x4(pa0, pa1, pa2, pa3, kpbase + paoff + (uint32_t)(kw * 32));
            #pragma unroll
            for (int p = 0; p < 4; p++) {
                uint32_t v00, v01, v10, v11;
                ldsm_x4_t(v00, v01, v10, v11,
                          vsbase + vtoff + (uint32_t)(kw * (16*QPAD*4) + p * 32));
                mma_fp16(o[2*p  ][0], o[2*p  ][1], o[2*p  ][2], o[2*p  ][3],
                         pa0, pa1, pa2, pa3, v00, v01);
                mma_fp16(o[2*p+1][0], o[2*p+1][1], o[2*p+1][2], o[2*p+1][3],
                         pa0, pa1, pa2, pa3, v10, v11);
            }
        }
    }

    float inv0 = 1.0f / l0, inv1 = 1.0f / l1;
    #pragma unroll
    for (int nt = 0; nt < 8; nt++) {
        int d = nt*8 + gc*2;
        size_t i0 = ((size_t)(b*Lk + r0))*Dk + h*DHk + d;
        size_t i1 = ((size_t)(b*Lk + r1))*Dk + h*DHk + d;
        float v00 = o[nt][0]*inv0, v01 = o[nt][1]*inv0;
        float v10 = o[nt][2]*inv1, v11 = o[nt][3]*inv1;
        __nv_bfloat16 h00, l00, h01, l01, h10, l10, h11, l11;
        bf16_split(v00, h00, l00); bf16_split(v01, h01, l01);
        bf16_split(v10, h10, l10); bf16_split(v11, h11, l11);
        __nv_bfloat162 ph0; ph0.x = h00; ph0.y = h01;
        __nv_bfloat162 ph1; ph1.x = h10; ph1.y = h11;
        __nv_bfloat162 pl0; pl0.x = l00; pl0.y = l01;
        __nv_bfloat162 pl1; pl1.x = l10; pl1.y = l11;
        *(__nv_bfloat162*)(Oh + i0) = ph0;
        *(__nv_bfloat162*)(Oh + i1) = ph1;
        *(__nv_bfloat162*)(Ol + i0) = pl0;
        *(__nv_bfloat162*)(Ol + i1) = pl1;
    }
}

// ================= bf16 3-pass split GEMM, cp.async 2-stage, K=32 per stage =========
// EPI: 1 fp32 +R, 2 silu -> bf16 hi/lo, 3 fp16 QKV with table-RoPE (z<2) + Q scale
#define BUFW 2560
#define STGW 10240
template<int EPI>
__global__ __launch_bounds__(256, 2) void gemm_bfs(const __nv_bfloat16* __restrict__ Ah_,
                                                   const __nv_bfloat16* __restrict__ Al_,
                                                   const __nv_bfloat16* __restrict__ Bh0,
                                                   const __nv_bfloat16* __restrict__ Bl0,
                                                   const __nv_bfloat16* __restrict__ Bh1,
                                                   const __nv_bfloat16* __restrict__ Bl1,
                                                   const __nv_bfloat16* __restrict__ Bh2,
                                                   const __nv_bfloat16* __restrict__ Bl2,
                                                   const float* __restrict__ R,
                                                   float* __restrict__ C0,
                                                   __half* __restrict__ C16,
                                                   __nv_bfloat16* __restrict__ Cbh,
                                                   __nv_bfloat16* __restrict__ Cbl,
                                                   int N, int K)
{
    const __nv_bfloat16* Bh = (blockIdx.z == 0) ? Bh0 : (blockIdx.z == 1 ? Bh1 : Bh2);
    const __nv_bfloat16* Bl = (blockIdx.z == 0) ? Bl0 : (blockIdx.z == 1 ? Bl1 : Bl2);

    extern __shared__ uint32_t dsm[];

    int t    = threadIdx.x;
    int lane = t & 31;
    int wid  = t >> 5;
    int bm0  = blockIdx.y * 128;
    int bn0  = blockIdx.x * 128;
    int wm0  = (wid & 3) * 32;
    int wn0  = (wid >> 2) * 64;
    int gr   = lane >> 2;
    int gc   = lane & 3;

    int lrow = t >> 1;
    int lkw  = (t & 1) * 8;

    const __nv_bfloat16* pAh = Ah_ + (size_t)(bm0 + lrow) * K + lkw * 2;
    const __nv_bfloat16* pAl = Al_ + (size_t)(bm0 + lrow) * K + lkw * 2;
    const __nv_bfloat16* pBh = Bh  + (size_t)(bn0 + lrow) * K + lkw * 2;
    const __nv_bfloat16* pBl = Bl  + (size_t)(bn0 + lrow) * K + lkw * 2;

    uint32_t sbase = (uint32_t)__cvta_generic_to_shared(dsm);
    uint32_t soff  = (lrow * 20 + lkw) * 4;

    float c[2][8][4];
    #pragma unroll
    for (int i = 0; i < 2; i++)
        #pragma unroll
        for (int j = 0; j < 8; j++)
            #pragma unroll
            for (int q = 0; q < 4; q++) c[i][j][q] = 0.f;

    #pragma unroll
    for (int s = 0; s < 2; s++) {
        int ko = s * 32;
        uint32_t sb = sbase + s * STGW * 4 + soff;
        cp16(sb,            pAh + ko); cp16(sb + 16,            pAh + ko + 8);
        cp16(sb + BUFW*4,   pAl + ko); cp16(sb + BUFW*4 + 16,   pAl + ko + 8);
        cp16(sb + 2*BUFW*4, pBh + ko); cp16(sb + 2*BUFW*4 + 16, pBh + ko + 8);
        cp16(sb + 3*BUFW*4, pBl + ko); cp16(sb + 3*BUFW*4 + 16, pBl + ko + 8);
        CP_COMMIT();
    }

    const int niter = K / 32;
    for (int it = 0; it < niter; it++) {
        CP_WAIT1();
        __syncthreads();
        int cur = it & 1;
        const uint32_t* sAh = dsm + cur * STGW;
        const uint32_t* sAl = sAh + BUFW;
        const uint32_t* sBh = sAh + 2 * BUFW;
        const uint32_t* sBl = sAh + 3 * BUFW;

        #pragma unroll
        for (int kk = 0; kk < 16; kk += 8) {
            uint32_t afh[2][4], afl[2][4];
            #pragma unroll
            for (int mt = 0; mt < 2; mt++) {
                int rr = (wm0 + mt * 16 + gr) * 20 + kk + gc;
                afh[mt][0] = sAh[rr];
                afh[mt][1] = sAh[rr + 8 * 20];
                afh[mt][2] = sAh[rr + 4];
                afh[mt][3] = sAh[rr + 8 * 20 + 4];
                afl[mt][0] = sAl[rr];
                afl[mt][1] = sAl[rr + 8 * 20];
                afl[mt][2] = sAl[rr + 4];
                afl[mt][3] = sAl[rr + 8 * 20 + 4];
            }
            #pragma unroll
            for (int nt = 0; nt < 8; nt++) {
                int nn = (wn0 + nt * 8 + gr) * 20 + kk + gc;
                uint32_t bh0 = sBh[nn], bh1 = sBh[nn + 4];
                uint32_t bl0 = sBl[nn], bl1 = sBl[nn + 4];
                #pragma unroll
                for (int mt = 0; mt < 2; mt++) {
                    mma_bf16(c[mt][nt][0], c[mt][nt][1], c[mt][nt][2], c[mt][nt][3],
                             afh[mt][0], afh[mt][1], afh[mt][2], afh[mt][3], bh0, bh1);
                    mma_bf16(c[mt][nt][0], c[mt][nt][1], c[mt][nt][2], c[mt][nt][3],
                             afh[mt][0], afh[mt][1], afh[mt][2], afh[mt][3], bl0, bl1);
                    mma_bf16(c[mt][nt][0], c[mt][nt][1], c[mt][nt][2], c[mt][nt][3],
                             afl[mt][0], afl[mt][1], afl[mt][2], afl[mt][3], bh0, bh1);
                }
            }
        }

        __syncthreads();
        if (it + 2 < niter) {
            int ko = (it + 2) * 32;
            uint32_t sb = sbase + cur * STGW * 4 + soff;
            cp16(sb,            pAh + ko); cp16(sb + 16,            pAh + ko + 8);
            cp16(sb + BUFW*4,   pAl + ko); cp16(sb + BUFW*4 + 16,   pAl + ko + 8);
            cp16(sb + 2*BUFW*4, pBh + ko); cp16(sb + 2*BUFW*4 + 16, pBh + ko + 8);
            cp16(sb + 3*BUFW*4, pBl + ko); cp16(sb + 3*BUFW*4 + 16, pBl + ko + 8);
        }
        CP_COMMIT();
    }

    if (EPI == 3) {
        // QKV epilogue: fp16 store; RoPE via table for Q (z=0, with 0.125 scale) and K (z=1).
        __half* C = C16 + (size_t)blockIdx.z * (MR * Dk);
        bool dorope = (blockIdx.z < 2);
        float qs = (blockIdx.z == 0) ? 0.125f : 1.0f;
        #pragma unroll
        for (int mt = 0; mt < 2; mt++) {
            #pragma unroll
            for (int half = 0; half < 2; half++) {
                int r = bm0 + wm0 + mt * 16 + gr + half * 8;
                int pos = r & (Lk - 1);
                #pragma unroll
                for (int nt = 0; nt < 4; nt++) {
                    int tc = nt * 8 + gc * 2;
                    float a0 = c[mt][nt  ][half*2+0], a1 = c[mt][nt  ][half*2+1];
                    float b0 = c[mt][nt+4][half*2+0], b1 = c[mt][nt+4][half*2+1];
                    size_t idx = (size_t)r * N + bn0 + wn0 + tc;
                    if (dorope) {
                        float2 cs0 = g_ROPE[(pos << 5) | tc];
                        float2 cs1 = g_ROPE[(pos << 5) | (tc + 1)];
                        float lo0 = (a0 * cs0.x - b0 * cs0.y) * qs;
                        float lo1 = (a1 * cs1.x - b1 * cs1.y) * qs;
                        float hi0 = (b0 * cs0.x + a0 * cs0.y) * qs;
                        float hi1 = (b1 * cs1.x + a1 * cs1.y) * qs;
                        *(__half2*)(C + idx)      = __floats2half2_rn(lo0, lo1);
                        *(__half2*)(C + idx + 32) = __floats2half2_rn(hi0, hi1);
                    } else {
                        *(__half2*)(C + idx)      = __floats2half2_rn(a0, a1);
                        *(__half2*)(C + idx + 32) = __floats2half2_rn(b0, b1);
                    }
                }
            }
        }
        return;
    }

    #pragma unroll
    for (int mt = 0; mt < 2; mt++) {
        #pragma unroll
        for (int nt = 0; nt < 8; nt++) {
            int row = bm0 + wm0 + mt * 16 + gr;
            int col = bn0 + wn0 + nt * 8 + gc * 2;
            #pragma unroll
            for (int half = 0; half < 2; half++) {
                int r = row + half * 8;
                float vx = c[mt][nt][half * 2 + 0];
                float vy = c[mt][nt][half * 2 + 1];
                size_t idx = (size_t)r * N + col;
                if (EPI == 1) {
                    float2 rr = *(const float2*)(R + idx);
                    vx += rr.x; vy += rr.y;
                    float2 ov; ov.x = vx; ov.y = vy;
                    *(float2*)(C0 + idx) = ov;
                } else if (EPI == 2) {
                    vx = vx / (1.f + __expf(-vx));
                    vy = vy / (1.f + __expf(-vy));
                    __nv_bfloat16 hx, lx, hy, ly;
                    bf16_split(vx, hx, lx);
                    bf16_split(vy, hy, ly);
                    __nv_bfloat162 ph; ph.x = hx; ph.y = hy;
                    __nv_bfloat162 pl; pl.x = lx; pl.y = ly;
                    *(__nv_bfloat162*)(Cbh + idx) = ph;
                    *(__nv_bfloat162*)(Cbl + idx) = pl;
                }
            }
        }
    }
}

// ================= LM head GEMM: fp16 single-pass, ldmatrix frags, cp.async 2-stage ====
__global__ __launch_bounds__(256, 2) void gemm_lm_h(const __half* __restrict__ A,
                                                    const __half* __restrict__ B,
                                                    float* __restrict__ C,
                                                    int N, int K)
{
    __shared__ uint32_t sA[2][128][20];
    __shared__ uint32_t sB[2][128][20];

    int t    = threadIdx.x;
    int lane = t & 31;
    int wid  = t >> 5;
    int bm0  = blockIdx.y * 128;
    int bn0  = blockIdx.x * 128;
    int wm0  = (wid & 3) * 32;
    int wn0  = (wid >> 2) * 64;
    int gr   = lane >> 2;
    int gc   = lane & 3;
    int lm8  = lane & 7, ldq = (lane >> 3) & 1, ldh = lane >> 4;

    int lrow = t >> 1;
    int lkw  = (t & 1) * 8;

    const __half* Ap = A + (size_t)(bm0 + lrow) * K + lkw * 2;
    const __half* Bp = B + (size_t)(bn0 + lrow) * K + lkw * 2;

    float c[2][8][4];
    #pragma unroll
    for (int i = 0; i < 2; i++)
        #pragma unroll
        for (int j = 0; j < 8; j++)
            #pragma unroll
            for (int q = 0; q < 4; q++) c[i][j][q] = 0.f;

    uint32_t saA0 = (uint32_t)__cvta_generic_to_shared(&sA[0][lrow][lkw]);
    uint32_t saB0 = (uint32_t)__cvta_generic_to_shared(&sB[0][lrow][lkw]);
    uint32_t sAbase = (uint32_t)__cvta_generic_to_shared(&sA[0][0][0]);
    uint32_t sBbase = (uint32_t)__cvta_generic_to_shared(&sB[0][0][0]);
    uint32_t aoff = ((wm0 + lm8 + 8*ldq) * 20 + 4*ldh) * 4;
    uint32_t boff = ((wn0 + lm8 + 8*ldh) * 20 + 4*ldq) * 4;
    const uint32_t stageStride = 128 * 20 * 4;

    #pragma unroll
    for (int s = 0; s < 2; s++) {
        int ko = s * 32;
        cp16(saA0 + s * stageStride,      Ap + ko);
        cp16(saA0 + s * stageStride + 16, Ap + ko + 8);
        cp16(saB0 + s * stageStride,      Bp + ko);
        cp16(saB0 + s * stageStride + 16, Bp + ko + 8);
        CP_COMMIT();
    }

    const int niter = K / 32;    // 8
    for (int it = 0; it < niter; it++) {
        CP_WAIT1();
        __syncthreads();
        int cur = it & 1;
        uint32_t sAc = sAbase + cur * stageStride;
        uint32_t sBc = sBbase + cur * stageStride;

        #pragma unroll
        for (int kk = 0; kk < 16; kk += 8) {
            uint32_t af[2][4];
            #pragma unroll
            for (int mt = 0; mt < 2; mt++)
                ldsm_x4(af[mt][0], af[mt][1], af[mt][2], af[mt][3],
                        sAc + aoff + (uint32_t)((mt * 320 + kk) * 4));
            #pragma unroll
            for (int p = 0; p < 4; p++) {
                uint32_t b00, b01, b10, b11;
                ldsm_x4(b00, b01, b10, b11, sBc + boff + (uint32_t)((p * 320 + kk) * 4));
                int n0 = 2*p, n1 = 2*p + 1;
                #pragma unroll
                for (int mt = 0; mt < 2; mt++) {
                    mma_fp16(c[mt][n0][0], c[mt][n0][1], c[mt][n0][2], c[mt][n0][3],
                             af[mt][0], af[mt][1], af[mt][2], af[mt][3], b00, b01);
                    mma_fp16(c[mt][n1][0], c[mt][n1][1], c[mt][n1][2], c[mt][n1][3],
                             af[mt][0], af[mt][1], af[mt][2], af[mt][3], b10, b11);
                }
            }
        }

        __syncthreads();
        if (it + 2 < niter) {
            int ko = (it + 2) * 32;
            cp16(saA0 + cur * stageStride,      Ap + ko);
            cp16(saA0 + cur * stageStride + 16, Ap + ko + 8);
            cp16(saB0 + cur * stageStride,      Bp + ko);
            cp16(saB0 + cur * stageStride + 16, Bp + ko + 8);
        }
        CP_COMMIT();
    }

    #pragma unroll
    for (int mt = 0; mt < 2; mt++) {
        #pragma unroll
        for (int nt = 0; nt < 8; nt++) {
            int row = bm0 + wm0 + mt * 16 + gr;
            int col = bn0 + wn0 + nt * 8 + gc * 2;
            #pragma unroll
            for (int half = 0; half < 2; half++) {
                int r = row + half * 8;
                float2 ov;
                ov.x = c[mt][nt][half * 2 + 0];
                ov.y = c[mt][nt][half * 2 + 1];
                *(float2*)(C + (size_t)r * N + col) = ov;
            }
        }
    }
}

// ---------------- classifier heads ----------------
__global__ void heads_kernel(const float* __restrict__ X,
                             const float* __restrict__ fnw,
                             const float* __restrict__ rw, const float* __restrict__ rb,
                             const float* __restrict__ mw, const float* __restrict__ mb,
                             float* __restrict__ out)
{
    int w = threadIdx.x >> 5, lane = threadIdx.x & 31;
    if (w >= Bk) return;
    const float* x = X + (size_t)w * Lk * Dk;
    float ss = 0.f;
    for (int d = lane; d < Dk; d += 32) { float v = x[d]; ss += v * v; }
    #pragma unroll
    for (int o = 16; o > 0; o >>= 1) ss += __shfl_xor_sync(0xffffffffu, ss, o);
    float rs = rsqrtf(ss * (1.0f / Dk) + 1.1920929e-07f);
    float sr = 0.f, sm = 0.f;
    for (int d = lane; d < Dk; d += 32) {
        float xn = x[d] * rs * fnw[d];
        sr += xn * rw[d];
        sm += xn * mw[d];
    }
    #pragma unroll
    for (int o = 16; o > 0; o >>= 1) {
        sr += __shfl_down_sync(0xffffffffu, sr, o);
        sm += __shfl_down_sync(0xffffffffu, sm, o);
    }
    if (lane == 0) {
        out[w]      = sr + rb[0];
        out[Bk + w] = sm + mb[0];
    }
}

// ---------------- launch ----------------
extern "C" void kernel_launch(void* const* d_in, const int* in_sizes, int n_in,
                              void* d_out, int out_size)
{
    const int*   ids      = (const int*)d_in[0];
    const int*   tts      = (const int*)d_in[1];
    const int*   mask     = (const int*)d_in[2];
    const float* tok_emb  = (const float*)d_in[3];
    const float* type_emb = (const float*)d_in[4];
    const float* norm1    = (const float*)d_in[5];
    const float* wq       = (const float*)d_in[6];
    const float* wk       = (const float*)d_in[7];
    const float* wv       = (const float*)d_in[8];
    const float* wo       = (const float*)d_in[9];
    const float* norm2    = (const float*)d_in[10];
    const float* fw1      = (const float*)d_in[11];
    const float* fw2      = (const float*)d_in[12];
    const float* fnorm    = (const float*)d_in[13];
    const float* lmw      = (const float*)d_in[14];
    const float* rw       = (const float*)d_in[15];
    const float* rbias    = (const float*)d_in[16];
    const float* mw       = (const float*)d_in[17];
    const float* mbias    = (const float*)d_in[18];
    float* out = (float*)d_out;

    float *X;
    __half *QKV16;
    __nv_bfloat16 *XNh, *XNl, *AOh, *AOl, *F1h, *F1l, *Wh, *Wl;
    __half *XNH16, *LWH;
    cudaGetSymbolAddress((void**)&X,     g_X);
    cudaGetSymbolAddress((void**)&QKV16, g_QKV16);
    cudaGetSymbolAddress((void**)&XNh,   g_XNh);
    cudaGetSymbolAddress((void**)&XNl,   g_XNl);
    cudaGetSymbolAddress((void**)&AOh,   g_AOh);
    cudaGetSymbolAddress((void**)&AOl,   g_AOl);
    cudaGetSymbolAddress((void**)&F1h,   g_F1h);
    cudaGetSymbolAddress((void**)&F1l,   g_F1l);
    cudaGetSymbolAddress((void**)&Wh,    g_Wh);
    cudaGetSymbolAddress((void**)&Wl,    g_Wl);
    cudaGetSymbolAddress((void**)&XNH16, g_XNH16);
    cudaGetSymbolAddress((void**)&LWH,   g_LWH);

    __half* Q16 = QKV16;
    __half* K16 = QKV16 + (size_t)MR * Dk;
    __half* V16 = QKV16 + 2 * (size_t)MR * Dk;

    const int dynSmem = STGW * 2 * 4;   // 81920 bytes
    cudaFuncSetAttribute(gemm_bfs<1>, cudaFuncAttributeMaxDynamicSharedMemorySize, dynSmem);
    cudaFuncSetAttribute(gemm_bfs<2>, cudaFuncAttributeMaxDynamicSharedMemorySize, dynSmem);
    cudaFuncSetAttribute(gemm_bfs<3>, cudaFuncAttributeMaxDynamicSharedMemorySize, dynSmem);

    embed_kernel<<<(MR * Dk) / 256, 256>>>(ids, tts, tok_emb, type_emb, X);
    prep_kernel<<<(WTOT + Vk * Dk) / 256, 256>>>(wq, wk, wv, wo, fw1, fw2, lmw, Wh, Wl, LWH);
    rope_tab_kernel<<<(Lk * 32) / 256, 256>>>();

    dim3 gqkv(Dk  / 128, MR / 128, 3);
    dim3 gs  (Dk  / 128, MR / 128, 1);
    dim3 gf1 (FFD / 128, MR / 128, 1);
    dim3 glm (Vk  / 128, MR / 128);
    dim3 ga  (Lk / 64, Hk, Bk);

    for (int i = 0; i < NLk; i++) {
        size_t od = (size_t)i * Dk * Dk;
        size_t of = (size_t)i * FFD * Dk;
        const __nv_bfloat16 *qh = Wh + OFF_WQ + od, *ql = Wl + OFF_WQ + od;
        const __nv_bfloat16 *kh = Wh + OFF_WK + od, *kl = Wl + OFF_WK + od;
        const __nv_bfloat16 *vh = Wh + OFF_WV + od, *vl = Wl + OFF_WV + od;
        const __nv_bfloat16 *oh = Wh + OFF_WO + od, *ol = Wl + OFF_WO + od;
        const __nv_bfloat16 *f1h = Wh + OFF_F1 + of, *f1l = Wl + OFF_F1 + of;
        const __nv_bfloat16 *f2h = Wh + OFF_F2 + of, *f2l = Wl + OFF_F2 + of;

        rmsnorm_kernel<<<MR / 8, 256>>>(X, norm1 + (size_t)i * Dk, XNh, XNl);
        gemm_bfs<3><<<gqkv, 256, dynSmem>>>(XNh, XNl, qh, ql, kh, kl, vh, vl,
                                            nullptr, nullptr, QKV16, nullptr, nullptr, Dk, Dk);
        attn_fa<<<ga, 128>>>(Q16, K16, V16, mask, AOh, AOl);
        gemm_bfs<1><<<gs, 256, dynSmem>>>(AOh, AOl, oh, ol, oh, ol, oh, ol,
                                          X, X, nullptr, nullptr, nullptr, Dk, Dk);
        rmsnorm_kernel<<<MR / 8, 256>>>(X, norm2 + (size_t)i * Dk, XNh, XNl);
        gemm_bfs<2><<<gf1, 256, dynSmem>>>(XNh, XNl, f1h, f1l, f1h, f1l, f1h, f1l,
                                           nullptr, nullptr, nullptr, F1h, F1l, FFD, Dk);
        gemm_bfs<1><<<gs, 256, dynSmem>>>(F1h, F1l, f2h, f2l, f2h, f2l, f2h, f2l,
                                          X, X, nullptr, nullptr, nullptr, Dk, FFD);
    }

    rmsnorm_f16_kernel<<<MR / 8, 256>>>(X, fnorm, XNH16);
    gemm_lm_h<<<glm, 256>>>(XNH16, LWH, out, Vk, Dk);
    heads_kernel<<<1, 128>>>(X, fnorm, rw, rbias, mw, mbias, out + (size_t)Bk * Lk * Vk);
}